// round 2
// baseline (speedup 1.0000x reference)
#include <cuda_runtime.h>
#include <math.h>

// ---------------- problem constants (fixed shapes) ----------------
#define BATCH 2
#define NQ    8192
#define RQ    (BATCH*NQ)     // 16384 query rows
#define CDIM  256
#define HEADS 8
#define DH    32
#define LEV   3
#define PTS   4
#define NV    6300           // 4800+1200+300
#define RV    (BATCH*NV)     // 12600 value rows
#define HID   1024           // MLP*C
#define NOFF  (HEADS*LEV*PTS*2)  // 192
#define NAW   (HEADS*LEV*PTS)    // 96

// ---------------- scratch (static device memory; no allocs allowed) ----------------
__device__ float g_qn   [RQ*CDIM];
__device__ float g_qa   [RQ*CDIM];
__device__ float g_offs [RQ*NOFF];
__device__ float g_logit[RQ*NAW];
__device__ float g_aw   [RQ*NAW];
__device__ float g_v    [RV*CDIM];
__device__ float g_attn [RQ*CDIM];
__device__ float g_q    [RQ*CDIM];
__device__ float g_q2   [RQ*CDIM];
__device__ float g_h    [RQ*HID];

// ---------------- LayerNorm over C=256 (one block per row, 256 threads) ----------------
__global__ void ln_kernel(const float* __restrict__ x,
                          const float* __restrict__ g, const float* __restrict__ b,
                          const float* __restrict__ pos,
                          float* __restrict__ outn, float* __restrict__ outa)
{
    int row = blockIdx.x;
    int t = threadIdx.x;
    float v = x[row*CDIM + t];

    __shared__ float sred[8];
    __shared__ float s_mean, s_var;

    float s = v;
    #pragma unroll
    for (int o = 16; o > 0; o >>= 1) s += __shfl_xor_sync(0xffffffffu, s, o);
    if ((t & 31) == 0) sred[t >> 5] = s;
    __syncthreads();
    if (t == 0) {
        float tot = 0.f;
        #pragma unroll
        for (int i = 0; i < 8; i++) tot += sred[i];
        s_mean = tot * (1.0f / CDIM);
    }
    __syncthreads();
    float mean = s_mean;

    float d = v - mean;
    float s2 = d * d;
    #pragma unroll
    for (int o = 16; o > 0; o >>= 1) s2 += __shfl_xor_sync(0xffffffffu, s2, o);
    __syncthreads();   // protect sred reuse
    if ((t & 31) == 0) sred[t >> 5] = s2;
    __syncthreads();
    if (t == 0) {
        float tot = 0.f;
        #pragma unroll
        for (int i = 0; i < 8; i++) tot += sred[i];
        s_var = tot * (1.0f / CDIM);
    }
    __syncthreads();

    float y = d * rsqrtf(s_var + 1e-5f) * g[t] + b[t];
    outn[row*CDIM + t] = y;
    if (outa) outa[row*CDIM + t] = y + pos[row*CDIM + t];
}

// ---------------- Tiled fp32 GEMM: C = act(A[MxK] * W[KxN] + bias) (+res1 +res2) ----------------
// BM=64, BN=64, BK=16, 256 threads (16x16), 4x4 microtile per thread.
#define ACT_NONE 0
#define ACT_GELU 1

__global__ void gemm_kernel(const float* __restrict__ A, const float* __restrict__ W,
                            const float* __restrict__ bias,
                            const float* __restrict__ res1, const float* __restrict__ res2,
                            float* __restrict__ Cout,
                            int M, int N, int K, int act)
{
    const int BM = 64, BN = 64, BK = 16;
    __shared__ __align__(16) float As[BK][BM];
    __shared__ __align__(16) float Ws[BK][BN];

    int t  = threadIdx.x;
    int tx = t & 15;
    int ty = t >> 4;
    int m0 = blockIdx.y * BM;
    int n0 = blockIdx.x * BN;

    float acc[4][4] = {};

    // A-tile load mapping: thread loads one float4: row lm = t>>2, k offset lk = (t&3)*4
    int lm = t >> 2;
    int lk = (t & 3) * 4;
    // W-tile load mapping: wk = t>>4 (0..15), wn = (t&15)*4
    int wk = t >> 4;
    int wn = (t & 15) * 4;

    for (int k0 = 0; k0 < K; k0 += BK) {
        // load A tile (K is always a multiple of 16 here; guard rows only)
        int grow = m0 + lm;
        float4 av;
        if (grow < M) {
            av = *reinterpret_cast<const float4*>(A + grow * K + k0 + lk);
        } else {
            av = make_float4(0.f, 0.f, 0.f, 0.f);
        }
        As[lk + 0][lm] = av.x;
        As[lk + 1][lm] = av.y;
        As[lk + 2][lm] = av.z;
        As[lk + 3][lm] = av.w;

        // load W tile (guard columns; rows k0+wk < K always)
        int kr = k0 + wk;
        const float* wrow = W + kr * N;
        #pragma unroll
        for (int u = 0; u < 4; u++) {
            int col = n0 + wn + u;
            Ws[wk][wn + u] = (col < N) ? wrow[col] : 0.f;
        }
        __syncthreads();

        #pragma unroll
        for (int kk = 0; kk < BK; kk++) {
            float4 a4 = *reinterpret_cast<const float4*>(&As[kk][ty * 4]);
            float4 b4 = *reinterpret_cast<const float4*>(&Ws[kk][tx * 4]);
            float a[4] = {a4.x, a4.y, a4.z, a4.w};
            float b[4] = {b4.x, b4.y, b4.z, b4.w};
            #pragma unroll
            for (int i = 0; i < 4; i++)
                #pragma unroll
                for (int j = 0; j < 4; j++)
                    acc[i][j] = fmaf(a[i], b[j], acc[i][j]);
        }
        __syncthreads();
    }

    #pragma unroll
    for (int i = 0; i < 4; i++) {
        int r = m0 + ty * 4 + i;
        if (r >= M) continue;
        #pragma unroll
        for (int j = 0; j < 4; j++) {
            int c = n0 + tx * 4 + j;
            if (c >= N) continue;
            float val = acc[i][j] + bias[c];
            if (act == ACT_GELU)
                val = 0.5f * val * (1.0f + erff(val * 0.70710678118654752f));
            int oi = r * N + c;
            if (res1) val += res1[oi];
            if (res2) val += res2[oi];
            Cout[oi] = val;
        }
    }
}

// ---------------- softmax over 12 (L*P) per (row, head) ----------------
__global__ void softmax_kernel()
{
    int idx = blockIdx.x * blockDim.x + threadIdx.x;   // (row*HEADS + h)
    if (idx >= RQ * HEADS) return;
    const float* in = g_logit + idx * (LEV * PTS);
    float* out = g_aw + idx * (LEV * PTS);
    float mx = -1e30f;
    float v[LEV * PTS];
    #pragma unroll
    for (int i = 0; i < LEV * PTS; i++) { v[i] = in[i]; mx = fmaxf(mx, v[i]); }
    float sum = 0.f;
    #pragma unroll
    for (int i = 0; i < LEV * PTS; i++) { v[i] = __expf(v[i] - mx); sum += v[i]; }
    float inv = 1.0f / sum;
    #pragma unroll
    for (int i = 0; i < LEV * PTS; i++) out[i] = v[i] * inv;
}

// ---------------- deformable sampling: one block per query row ----------------
__global__ void sample_kernel(const float* __restrict__ refp)
{
    int row = blockIdx.x;            // 0..RQ-1
    int b   = row / NQ;
    int t   = threadIdx.x;           // 256
    int h   = t >> 5;
    int d   = t & 31;

    __shared__ float s_off[NOFF];
    __shared__ float s_aw[NAW];
    __shared__ float s_ref[LEV * 2];
    if (t < NOFF) s_off[t] = g_offs[row * NOFF + t];
    if (t < NAW)  s_aw[t]  = g_aw[row * NAW + t];
    if (t < LEV * 2) s_ref[t] = refp[row * LEV * 2 + t];
    __syncthreads();

    const int Hl_[LEV] = {60, 30, 15};
    const int Wl_[LEV] = {80, 40, 20};
    const int St_[LEV] = {0, 4800, 6000};

    float acc = 0.f;
    #pragma unroll
    for (int l = 0; l < LEV; l++) {
        int Hl = Hl_[l], Wl = Wl_[l];
        const float* vbase = g_v + (b * NV + St_[l]) * CDIM + h * DH + d;
        float rx = s_ref[l * 2 + 0];
        float ry = s_ref[l * 2 + 1];
        #pragma unroll
        for (int p = 0; p < PTS; p++) {
            int oi = ((h * LEV + l) * PTS + p) * 2;
            float gx = rx * (float)Wl + s_off[oi + 0] - 0.5f;
            float gy = ry * (float)Hl + s_off[oi + 1] - 0.5f;
            float w  = s_aw[(h * LEV + l) * PTS + p];

            float x0f = floorf(gx), y0f = floorf(gy);
            int x0 = (int)x0f, y0 = (int)y0f;
            float wx = gx - x0f, wy = gy - y0f;

            float sv = 0.f;
            #pragma unroll
            for (int dy = 0; dy < 2; dy++) {
                int yi = y0 + dy;
                if (yi < 0 || yi >= Hl) continue;
                float wyv = dy ? wy : (1.f - wy);
                #pragma unroll
                for (int dx = 0; dx < 2; dx++) {
                    int xi = x0 + dx;
                    if (xi < 0 || xi >= Wl) continue;
                    float wxv = dx ? wx : (1.f - wx);
                    sv = fmaf(wyv * wxv, vbase[(yi * Wl + xi) * CDIM], sv);
                }
            }
            acc = fmaf(w, sv, acc);
        }
    }
    g_attn[row * CDIM + h * DH + d] = acc;
}

// ---------------- launch ----------------
extern "C" void kernel_launch(void* const* d_in, const int* in_sizes, int n_in,
                              void* d_out, int out_size)
{
    const float* query = (const float*)d_in[0];
    const float* value = (const float*)d_in[1];
    const float* qpos  = (const float*)d_in[2];
    const float* refp  = (const float*)d_in[3];
    // d_in[4] spatial_shapes, d_in[5] level_start_index: compile-time constants here
    const float* g1  = (const float*)d_in[6];
    const float* b1  = (const float*)d_in[7];
    const float* Wo  = (const float*)d_in[8];
    const float* bo  = (const float*)d_in[9];
    const float* Wa  = (const float*)d_in[10];
    const float* ba  = (const float*)d_in[11];
    const float* Wv  = (const float*)d_in[12];
    const float* bv  = (const float*)d_in[13];
    const float* Wp  = (const float*)d_in[14];
    const float* bp  = (const float*)d_in[15];
    const float* g2  = (const float*)d_in[16];
    const float* b2  = (const float*)d_in[17];
    const float* Wf1 = (const float*)d_in[18];
    const float* bf1 = (const float*)d_in[19];
    const float* Wf2 = (const float*)d_in[20];
    const float* bf2 = (const float*)d_in[21];
    float* out = (float*)d_out;

    float *qn, *qa, *offs, *logit, *vproj, *attn, *q, *q2, *hbuf;
    cudaGetSymbolAddress((void**)&qn,    g_qn);
    cudaGetSymbolAddress((void**)&qa,    g_qa);
    cudaGetSymbolAddress((void**)&offs,  g_offs);
    cudaGetSymbolAddress((void**)&logit, g_logit);
    cudaGetSymbolAddress((void**)&vproj, g_v);
    cudaGetSymbolAddress((void**)&attn,  g_attn);
    cudaGetSymbolAddress((void**)&q,     g_q);
    cudaGetSymbolAddress((void**)&q2,    g_q2);
    cudaGetSymbolAddress((void**)&hbuf,  g_h);

    // 1) LN1 (+pos) -> qn, qa
    ln_kernel<<<RQ, 256>>>(query, g1, b1, qpos, qn, qa);

    // 2) offsets: qa @ Wo + bo   [RQ x 192]
    gemm_kernel<<<dim3(3, RQ/64), 256>>>(qa, Wo, bo, nullptr, nullptr, offs,
                                         RQ, NOFF, CDIM, ACT_NONE);

    // 3) attention logits: qa @ Wa + ba   [RQ x 96]
    gemm_kernel<<<dim3(2, RQ/64), 256>>>(qa, Wa, ba, nullptr, nullptr, logit,
                                         RQ, NAW, CDIM, ACT_NONE);

    // 4) softmax over L*P
    softmax_kernel<<<(RQ*HEADS + 255)/256, 256>>>();

    // 5) value projection: value @ Wv + bv   [RV x 256]
    gemm_kernel<<<dim3(4, (RV + 63)/64), 256>>>(value, Wv, bv, nullptr, nullptr, vproj,
                                                RV, CDIM, CDIM, ACT_NONE);

    // 6) deformable bilinear sampling -> attn [RQ x 256]
    sample_kernel<<<RQ, 256>>>(refp);

    // 7) output proj + both residuals: q = attn @ Wp + bp + qn + query
    gemm_kernel<<<dim3(4, RQ/64), 256>>>(attn, Wp, bp, qn, query, q,
                                         RQ, CDIM, CDIM, ACT_NONE);

    // 8) LN2 -> q2
    ln_kernel<<<RQ, 256>>>(q, g2, b2, nullptr, q2, nullptr);

    // 9) FFN up + GELU: h = gelu(q2 @ Wf1 + bf1)   [RQ x 1024]
    gemm_kernel<<<dim3(16, RQ/64), 256>>>(q2, Wf1, bf1, nullptr, nullptr, hbuf,
                                          RQ, HID, CDIM, ACT_GELU);

    // 10) FFN down + residual: out = h @ Wf2 + bf2 + q
    gemm_kernel<<<dim3(4, RQ/64), 256>>>(hbuf, Wf2, bf2, q, nullptr, out,
                                         RQ, CDIM, HID, ACT_NONE);
}

// round 3
// speedup vs baseline: 1.7062x; 1.7062x over previous
#include <cuda_runtime.h>
#include <cstdint>
#include <math.h>

// ---------------- problem constants (fixed shapes) ----------------
#define BATCH 2
#define NQ    8192
#define RQ    (BATCH*NQ)     // 16384 query rows
#define CDIM  256
#define HEADS 8
#define DH    32
#define LEV   3
#define PTS   4
#define NV    6300           // 4800+1200+300
#define RV    (BATCH*NV)     // 12600 value rows
#define HID   1024           // MLP*C
#define NOFF  (HEADS*LEV*PTS*2)  // 192
#define NAW   (HEADS*LEV*PTS)    // 96

// ---------------- scratch (static device memory; no allocs allowed) ----------------
__device__ float g_qn   [RQ*CDIM];
__device__ float g_qa   [RQ*CDIM];
__device__ float g_offs [RQ*NOFF];
__device__ float g_logit[RQ*NAW];
__device__ float g_aw   [RQ*NAW];
__device__ float g_v    [RV*CDIM];
__device__ float g_attn [RQ*CDIM];
__device__ float g_q    [RQ*CDIM];
__device__ float g_q2   [RQ*CDIM];
__device__ float g_h    [RQ*HID];

// ---------------- LayerNorm over C=256 (one block per row, 256 threads) ----------------
__global__ void ln_kernel(const float* __restrict__ x,
                          const float* __restrict__ g, const float* __restrict__ b,
                          const float* __restrict__ pos,
                          float* __restrict__ outn, float* __restrict__ outa)
{
    int row = blockIdx.x;
    int t = threadIdx.x;
    float v = x[row*CDIM + t];

    __shared__ float sred[8];
    __shared__ float s_mean, s_var;

    float s = v;
    #pragma unroll
    for (int o = 16; o > 0; o >>= 1) s += __shfl_xor_sync(0xffffffffu, s, o);
    if ((t & 31) == 0) sred[t >> 5] = s;
    __syncthreads();
    if (t == 0) {
        float tot = 0.f;
        #pragma unroll
        for (int i = 0; i < 8; i++) tot += sred[i];
        s_mean = tot * (1.0f / CDIM);
    }
    __syncthreads();
    float mean = s_mean;

    float d = v - mean;
    float s2 = d * d;
    #pragma unroll
    for (int o = 16; o > 0; o >>= 1) s2 += __shfl_xor_sync(0xffffffffu, s2, o);
    __syncthreads();
    if ((t & 31) == 0) sred[t >> 5] = s2;
    __syncthreads();
    if (t == 0) {
        float tot = 0.f;
        #pragma unroll
        for (int i = 0; i < 8; i++) tot += sred[i];
        s_var = tot * (1.0f / CDIM);
    }
    __syncthreads();

    float y = d * rsqrtf(s_var + 1e-5f) * g[t] + b[t];
    outn[row*CDIM + t] = y;
    if (outa) outa[row*CDIM + t] = y + pos[row*CDIM + t];
}

// ---------------- tf32 tensor-core GEMM ----------------
// C = act(A[MxK] @ W[KxN] + bias) (+res1 +res2)
// BM=128, BN=64, BK=32; 256 threads = 8 warps (4 m x 2 n); warp tile 32x32 (2x4 mma m16n8k8).
#define ACT_NONE 0
#define ACT_GELU 1
#define SA 36   // As row pitch (floats): fragment bank = 4g+t, conflict-free
#define SB 72   // Bs row pitch (floats): fragment bank = 8t+g, conflict-free

__device__ __forceinline__ uint32_t f2tf32(float x) {
    uint32_t u;
    asm("cvt.rna.tf32.f32 %0, %1;" : "=r"(u) : "f"(x));
    return u;
}

__device__ __forceinline__ void mma_tf32(float4& d,
                                         uint32_t a0, uint32_t a1, uint32_t a2, uint32_t a3,
                                         uint32_t b0, uint32_t b1) {
    asm volatile(
        "mma.sync.aligned.m16n8k8.row.col.f32.tf32.tf32.f32 "
        "{%0,%1,%2,%3}, {%4,%5,%6,%7}, {%8,%9}, {%0,%1,%2,%3};\n"
        : "+f"(d.x), "+f"(d.y), "+f"(d.z), "+f"(d.w)
        : "r"(a0), "r"(a1), "r"(a2), "r"(a3), "r"(b0), "r"(b1));
}

__global__ __launch_bounds__(256)
void gemm_tf32_kernel(const float* __restrict__ A, const float* __restrict__ W,
                      const float* __restrict__ bias,
                      const float* __restrict__ res1, const float* __restrict__ res2,
                      float* __restrict__ Cout,
                      int M, int N, int K, int act)
{
    __shared__ uint32_t As[128 * SA];
    __shared__ uint32_t Bs[32 * SB];

    int tid  = threadIdx.x;
    int lane = tid & 31;
    int warp = tid >> 5;
    int g = lane >> 2;      // 0..7
    int t = lane & 3;       // 0..3
    int wm = warp >> 1;     // 0..3
    int wn = warp & 1;      // 0..1
    int m0w = wm * 32;
    int n0w = wn * 32;
    int bm0 = blockIdx.y * 128;
    int bn0 = blockIdx.x * 64;

    float4 acc[2][4];
    #pragma unroll
    for (int i = 0; i < 2; i++)
        #pragma unroll
        for (int j = 0; j < 4; j++)
            acc[i][j] = make_float4(0.f, 0.f, 0.f, 0.f);

    for (int k0 = 0; k0 < K; k0 += 32) {
        // ---- load A tile: 128x32 floats ----
        #pragma unroll
        for (int p = 0; p < 4; p++) {
            int idx = p * 256 + tid;
            int row = idx >> 3;
            int c4  = (idx & 7) * 4;
            float4 v;
            if (bm0 + row < M) {
                v = *reinterpret_cast<const float4*>(A + (bm0 + row) * K + k0 + c4);
            } else {
                v = make_float4(0.f, 0.f, 0.f, 0.f);
            }
            uint4 u = make_uint4(f2tf32(v.x), f2tf32(v.y), f2tf32(v.z), f2tf32(v.w));
            *reinterpret_cast<uint4*>(&As[row * SA + c4]) = u;
        }
        // ---- load B tile: 32x64 (guard columns) ----
        #pragma unroll
        for (int p = 0; p < 2; p++) {
            int idx = p * 256 + tid;
            int row = idx >> 4;
            int c   = (idx & 15) * 4;
            int gc  = bn0 + c;
            const float* wrow = W + (k0 + row) * N;
            float4 v;
            if (gc + 3 < N) {
                v = *reinterpret_cast<const float4*>(wrow + gc);
            } else {
                v.x = (gc + 0 < N) ? wrow[gc + 0] : 0.f;
                v.y = (gc + 1 < N) ? wrow[gc + 1] : 0.f;
                v.z = (gc + 2 < N) ? wrow[gc + 2] : 0.f;
                v.w = (gc + 3 < N) ? wrow[gc + 3] : 0.f;
            }
            uint4 u = make_uint4(f2tf32(v.x), f2tf32(v.y), f2tf32(v.z), f2tf32(v.w));
            *reinterpret_cast<uint4*>(&Bs[row * SB + c]) = u;
        }
        __syncthreads();

        #pragma unroll
        for (int ks = 0; ks < 4; ks++) {
            int kk = ks * 8;
            uint32_t a[2][4];
            #pragma unroll
            for (int im = 0; im < 2; im++) {
                int r = m0w + im * 16;
                a[im][0] = As[(r + g    ) * SA + kk + t    ];
                a[im][1] = As[(r + 8 + g) * SA + kk + t    ];
                a[im][2] = As[(r + g    ) * SA + kk + t + 4];
                a[im][3] = As[(r + 8 + g) * SA + kk + t + 4];
            }
            #pragma unroll
            for (int in = 0; in < 4; in++) {
                uint32_t b0 = Bs[(kk + t    ) * SB + n0w + in * 8 + g];
                uint32_t b1 = Bs[(kk + t + 4) * SB + n0w + in * 8 + g];
                mma_tf32(acc[0][in], a[0][0], a[0][1], a[0][2], a[0][3], b0, b1);
                mma_tf32(acc[1][in], a[1][0], a[1][1], a[1][2], a[1][3], b0, b1);
            }
        }
        __syncthreads();
    }

    // ---- epilogue ----
    #pragma unroll
    for (int im = 0; im < 2; im++) {
        int r0 = bm0 + m0w + im * 16 + g;
        int r1 = r0 + 8;
        #pragma unroll
        for (int in = 0; in < 4; in++) {
            int c = bn0 + n0w + in * 8 + 2 * t;
            if (c >= N) continue;   // N even -> c+1 < N too
            float bx = bias[c], by = bias[c + 1];

            float v0 = acc[im][in].x + bx;
            float v1 = acc[im][in].y + by;
            float v2 = acc[im][in].z + bx;
            float v3 = acc[im][in].w + by;
            if (act == ACT_GELU) {
                v0 = 0.5f * v0 * (1.0f + erff(v0 * 0.70710678118654752f));
                v1 = 0.5f * v1 * (1.0f + erff(v1 * 0.70710678118654752f));
                v2 = 0.5f * v2 * (1.0f + erff(v2 * 0.70710678118654752f));
                v3 = 0.5f * v3 * (1.0f + erff(v3 * 0.70710678118654752f));
            }
            if (r0 < M) {
                int oi = r0 * N + c;
                if (res1) { v0 += res1[oi]; v1 += res1[oi + 1]; }
                if (res2) { v0 += res2[oi]; v1 += res2[oi + 1]; }
                *reinterpret_cast<float2*>(Cout + oi) = make_float2(v0, v1);
            }
            if (r1 < M) {
                int oi = r1 * N + c;
                if (res1) { v2 += res1[oi]; v3 += res1[oi + 1]; }
                if (res2) { v2 += res2[oi]; v3 += res2[oi + 1]; }
                *reinterpret_cast<float2*>(Cout + oi) = make_float2(v2, v3);
            }
        }
    }
}

// ---------------- softmax over 12 (L*P) per (row, head) ----------------
__global__ void softmax_kernel()
{
    int idx = blockIdx.x * blockDim.x + threadIdx.x;   // (row*HEADS + h)
    if (idx >= RQ * HEADS) return;
    const float* in = g_logit + idx * (LEV * PTS);
    float* out = g_aw + idx * (LEV * PTS);
    float mx = -1e30f;
    float v[LEV * PTS];
    #pragma unroll
    for (int i = 0; i < LEV * PTS; i++) { v[i] = in[i]; mx = fmaxf(mx, v[i]); }
    float sum = 0.f;
    #pragma unroll
    for (int i = 0; i < LEV * PTS; i++) { v[i] = __expf(v[i] - mx); sum += v[i]; }
    float inv = 1.0f / sum;
    #pragma unroll
    for (int i = 0; i < LEV * PTS; i++) out[i] = v[i] * inv;
}

// ---------------- deformable sampling: one block per query row ----------------
__global__ void sample_kernel(const float* __restrict__ refp)
{
    int row = blockIdx.x;            // 0..RQ-1
    int b   = row / NQ;
    int t   = threadIdx.x;           // 256
    int h   = t >> 5;
    int d   = t & 31;

    __shared__ float s_off[NOFF];
    __shared__ float s_aw[NAW];
    __shared__ float s_ref[LEV * 2];
    if (t < NOFF) s_off[t] = g_offs[row * NOFF + t];
    if (t < NAW)  s_aw[t]  = g_aw[row * NAW + t];
    if (t < LEV * 2) s_ref[t] = refp[row * LEV * 2 + t];
    __syncthreads();

    const int Hl_[LEV] = {60, 30, 15};
    const int Wl_[LEV] = {80, 40, 20};
    const int St_[LEV] = {0, 4800, 6000};

    float acc = 0.f;
    #pragma unroll
    for (int l = 0; l < LEV; l++) {
        int Hl = Hl_[l], Wl = Wl_[l];
        const float* vbase = g_v + (b * NV + St_[l]) * CDIM + h * DH + d;
        float rx = s_ref[l * 2 + 0];
        float ry = s_ref[l * 2 + 1];
        #pragma unroll
        for (int p = 0; p < PTS; p++) {
            int oi = ((h * LEV + l) * PTS + p) * 2;
            float gx = rx * (float)Wl + s_off[oi + 0] - 0.5f;
            float gy = ry * (float)Hl + s_off[oi + 1] - 0.5f;
            float w  = s_aw[(h * LEV + l) * PTS + p];

            float x0f = floorf(gx), y0f = floorf(gy);
            int x0 = (int)x0f, y0 = (int)y0f;
            float wx = gx - x0f, wy = gy - y0f;

            float sv = 0.f;
            #pragma unroll
            for (int dy = 0; dy < 2; dy++) {
                int yi = y0 + dy;
                if (yi < 0 || yi >= Hl) continue;
                float wyv = dy ? wy : (1.f - wy);
                #pragma unroll
                for (int dx = 0; dx < 2; dx++) {
                    int xi = x0 + dx;
                    if (xi < 0 || xi >= Wl) continue;
                    float wxv = dx ? wx : (1.f - wx);
                    sv = fmaf(wyv * wxv, vbase[(yi * Wl + xi) * CDIM], sv);
                }
            }
            acc = fmaf(w, sv, acc);
        }
    }
    g_attn[row * CDIM + h * DH + d] = acc;
}

// ---------------- launch ----------------
extern "C" void kernel_launch(void* const* d_in, const int* in_sizes, int n_in,
                              void* d_out, int out_size)
{
    const float* query = (const float*)d_in[0];
    const float* value = (const float*)d_in[1];
    const float* qpos  = (const float*)d_in[2];
    const float* refp  = (const float*)d_in[3];
    const float* g1  = (const float*)d_in[6];
    const float* b1  = (const float*)d_in[7];
    const float* Wo  = (const float*)d_in[8];
    const float* bo  = (const float*)d_in[9];
    const float* Wa  = (const float*)d_in[10];
    const float* ba  = (const float*)d_in[11];
    const float* Wv  = (const float*)d_in[12];
    const float* bv  = (const float*)d_in[13];
    const float* Wp  = (const float*)d_in[14];
    const float* bp  = (const float*)d_in[15];
    const float* g2  = (const float*)d_in[16];
    const float* b2  = (const float*)d_in[17];
    const float* Wf1 = (const float*)d_in[18];
    const float* bf1 = (const float*)d_in[19];
    const float* Wf2 = (const float*)d_in[20];
    const float* bf2 = (const float*)d_in[21];
    float* out = (float*)d_out;

    float *qn, *qa, *offs, *logit, *vproj, *attn, *q, *q2, *hbuf;
    cudaGetSymbolAddress((void**)&qn,    g_qn);
    cudaGetSymbolAddress((void**)&qa,    g_qa);
    cudaGetSymbolAddress((void**)&offs,  g_offs);
    cudaGetSymbolAddress((void**)&logit, g_logit);
    cudaGetSymbolAddress((void**)&vproj, g_v);
    cudaGetSymbolAddress((void**)&attn,  g_attn);
    cudaGetSymbolAddress((void**)&q,     g_q);
    cudaGetSymbolAddress((void**)&q2,    g_q2);
    cudaGetSymbolAddress((void**)&hbuf,  g_h);

    // 1) LN1 (+pos) -> qn, qa
    ln_kernel<<<RQ, 256>>>(query, g1, b1, qpos, qn, qa);

    // 2) offsets: qa @ Wo + bo   [RQ x 192]
    gemm_tf32_kernel<<<dim3(3, RQ/128), 256>>>(qa, Wo, bo, nullptr, nullptr, offs,
                                               RQ, NOFF, CDIM, ACT_NONE);

    // 3) attention logits: qa @ Wa + ba   [RQ x 96]
    gemm_tf32_kernel<<<dim3(2, RQ/128), 256>>>(qa, Wa, ba, nullptr, nullptr, logit,
                                               RQ, NAW, CDIM, ACT_NONE);

    // 4) softmax over L*P
    softmax_kernel<<<(RQ*HEADS + 255)/256, 256>>>();

    // 5) value projection: value @ Wv + bv   [RV x 256]
    gemm_tf32_kernel<<<dim3(4, (RV + 127)/128), 256>>>(value, Wv, bv, nullptr, nullptr, vproj,
                                                       RV, CDIM, CDIM, ACT_NONE);

    // 6) deformable bilinear sampling -> attn [RQ x 256]
    sample_kernel<<<RQ, 256>>>(refp);

    // 7) output proj + both residuals: q = attn @ Wp + bp + qn + query
    gemm_tf32_kernel<<<dim3(4, RQ/128), 256>>>(attn, Wp, bp, qn, query, q,
                                               RQ, CDIM, CDIM, ACT_NONE);

    // 8) LN2 -> q2
    ln_kernel<<<RQ, 256>>>(q, g2, b2, nullptr, q2, nullptr);

    // 9) FFN up + GELU: h = gelu(q2 @ Wf1 + bf1)   [RQ x 1024]
    gemm_tf32_kernel<<<dim3(16, RQ/128), 256>>>(q2, Wf1, bf1, nullptr, nullptr, hbuf,
                                                RQ, HID, CDIM, ACT_GELU);

    // 10) FFN down + residual: out = h @ Wf2 + bf2 + q
    gemm_tf32_kernel<<<dim3(4, RQ/128), 256>>>(hbuf, Wf2, bf2, q, nullptr, out,
                                               RQ, CDIM, HID, ACT_NONE);
}

// round 6
// speedup vs baseline: 2.5580x; 1.4993x over previous
#include <cuda_runtime.h>
#include <cstdint>
#include <math.h>

// ---------------- problem constants (fixed shapes) ----------------
#define BATCH 2
#define NQ    8192
#define RQ    (BATCH*NQ)     // 16384 query rows
#define CDIM  256
#define HEADS 8
#define DH    32
#define LEV   3
#define PTS   4
#define NV    6300           // 4800+1200+300
#define RV    (BATCH*NV)     // 12600 value rows
#define HID   1024           // MLP*C
#define NOFF  (HEADS*LEV*PTS*2)  // 192
#define NAW   (HEADS*LEV*PTS)    // 96

// ---------------- scratch (static device memory; no allocs allowed) ----------------
__device__ float g_qn   [RQ*CDIM];
__device__ float g_qa   [RQ*CDIM];
__device__ float g_offs [RQ*NOFF];
__device__ float g_logit[RQ*NAW];
__device__ float g_aw   [RQ*NAW];
__device__ float g_v    [RV*CDIM];
__device__ float g_attn [RQ*CDIM];
__device__ float g_q    [RQ*CDIM];
__device__ float g_q2   [RQ*CDIM];
__device__ float g_h    [RQ*HID];

// ---------------- LayerNorm over C=256 (one block per row, 256 threads) ----------------
__global__ void ln_kernel(const float* __restrict__ x,
                          const float* __restrict__ g, const float* __restrict__ b,
                          const float* __restrict__ pos,
                          float* __restrict__ outn, float* __restrict__ outa)
{
    int row = blockIdx.x;
    int t = threadIdx.x;
    float v = x[row*CDIM + t];

    __shared__ float sred[8];
    __shared__ float s_mean, s_var;

    float s = v;
    #pragma unroll
    for (int o = 16; o > 0; o >>= 1) s += __shfl_xor_sync(0xffffffffu, s, o);
    if ((t & 31) == 0) sred[t >> 5] = s;
    __syncthreads();
    if (t == 0) {
        float tot = 0.f;
        #pragma unroll
        for (int i = 0; i < 8; i++) tot += sred[i];
        s_mean = tot * (1.0f / CDIM);
    }
    __syncthreads();
    float mean = s_mean;

    float d = v - mean;
    float s2 = d * d;
    #pragma unroll
    for (int o = 16; o > 0; o >>= 1) s2 += __shfl_xor_sync(0xffffffffu, s2, o);
    __syncthreads();
    if ((t & 31) == 0) sred[t >> 5] = s2;
    __syncthreads();
    if (t == 0) {
        float tot = 0.f;
        #pragma unroll
        for (int i = 0; i < 8; i++) tot += sred[i];
        s_var = tot * (1.0f / CDIM);
    }
    __syncthreads();

    float y = d * rsqrtf(s_var + 1e-5f) * g[t] + b[t];
    outn[row*CDIM + t] = y;
    if (outa) outa[row*CDIM + t] = y + pos[row*CDIM + t];
}

// ---------------- tf32 tensor-core GEMM with cp.async double buffering ----------------
// C = act(A[MxK] @ W[KxN] + bias) (+res1 +res2)
// BM=128, BN=64, BK=32; 256 threads = 8 warps (4 m x 2 n); warp tile 32x32 (2x4 mma m16n8k8).
// A/B fed as raw fp32 bits to tf32 mma (HW truncates mantissa).
#define ACT_NONE 0
#define ACT_GELU 1
#define SA 36   // As row pitch (floats): 144B, 16B-aligned, conflict-free fragment reads
#define SB 72   // Bs row pitch (floats): 288B, 16B-aligned, conflict-free fragment reads

// dynamic smem layout (bytes)
#define AS_BYTES (128*SA*4)          // 18432
#define BS_BYTES (32*SB*4)           // 9216
#define OFF_AS0  0
#define OFF_AS1  AS_BYTES
#define OFF_BS0  (2*AS_BYTES)
#define OFF_BS1  (2*AS_BYTES + BS_BYTES)
#define SMEM_TOT (2*AS_BYTES + 2*BS_BYTES)   // 55296

__device__ __forceinline__ uint32_t smem_u32(const void* p) {
    uint32_t a;
    asm("{ .reg .u64 t; cvta.to.shared.u64 t, %1; cvt.u32.u64 %0, t; }" : "=r"(a) : "l"(p));
    return a;
}
__device__ __forceinline__ void cp_async16(uint32_t dst, const void* src) {
    asm volatile("cp.async.cg.shared.global [%0], [%1], 16;" :: "r"(dst), "l"(src));
}
__device__ __forceinline__ void cp_commit() {
    asm volatile("cp.async.commit_group;" ::: "memory");
}
template<int N>
__device__ __forceinline__ void cp_wait() {
    asm volatile("cp.async.wait_group %0;" :: "n"(N) : "memory");
}

__device__ __forceinline__ void mma_tf32(float4& d,
                                         uint32_t a0, uint32_t a1, uint32_t a2, uint32_t a3,
                                         uint32_t b0, uint32_t b1) {
    asm volatile(
        "mma.sync.aligned.m16n8k8.row.col.f32.tf32.tf32.f32 "
        "{%0,%1,%2,%3}, {%4,%5,%6,%7}, {%8,%9}, {%0,%1,%2,%3};\n"
        : "+f"(d.x), "+f"(d.y), "+f"(d.z), "+f"(d.w)
        : "r"(a0), "r"(a1), "r"(a2), "r"(a3), "r"(b0), "r"(b1));
}

__global__ __launch_bounds__(256)
void gemm_tf32_kernel(const float* __restrict__ A, const float* __restrict__ W,
                      const float* __restrict__ bias,
                      const float* __restrict__ res1, const float* __restrict__ res2,
                      float* __restrict__ Cout,
                      int M, int N, int K, int act)
{
    extern __shared__ char smem[];
    uint32_t smem_base = smem_u32(smem);

    int tid  = threadIdx.x;
    int lane = tid & 31;
    int warp = tid >> 5;
    int g = lane >> 2;      // 0..7
    int t = lane & 3;       // 0..3
    int wm = warp >> 1;     // 0..3
    int wn = warp & 1;      // 0..1
    int m0w = wm * 32;
    int n0w = wn * 32;
    int bm0 = blockIdx.y * 128;
    int bn0 = blockIdx.x * 64;

    // per-thread load coordinates
    const int a_row = tid >> 1;                 // with p-loop: rows tid>>1 twice? see below
    // A: 1024 16B-chunks; thread does 4: idx = p*256+tid -> row idx>>3, c4=(idx&7)*4
    // B: 512 chunks; thread does 2: idx = p*256+tid -> row idx>>4, c=(idx&15)*4
    (void)a_row;

    const uint32_t asb[2] = { smem_base + OFF_AS0, smem_base + OFF_AS1 };
    const uint32_t bsb[2] = { smem_base + OFF_BS0, smem_base + OFF_BS1 };

    float4 acc[2][4];
    #pragma unroll
    for (int i = 0; i < 2; i++)
        #pragma unroll
        for (int j = 0; j < 4; j++)
            acc[i][j] = make_float4(0.f, 0.f, 0.f, 0.f);

    const int nchunks = K >> 5;

    // ---- stage loader ----
    auto load_chunk = [&](int c, int s) {
        int k0 = c << 5;
        #pragma unroll
        for (int p = 0; p < 4; p++) {
            int idx = p * 256 + tid;
            int row = idx >> 3;
            int c4  = (idx & 7) * 4;
            int grow = bm0 + row; if (grow > M - 1) grow = M - 1;   // clamp, masked at store
            cp_async16(asb[s] + (uint32_t)(row * SA + c4) * 4u, A + grow * K + k0 + c4);
        }
        #pragma unroll
        for (int p = 0; p < 2; p++) {
            int idx = p * 256 + tid;
            int row = idx >> 4;
            int c   = (idx & 15) * 4;
            int gc  = bn0 + c; if (gc > N - 4) gc = N - 4;          // clamp, masked at store
            cp_async16(bsb[s] + (uint32_t)(row * SB + c) * 4u, W + (k0 + row) * N + gc);
        }
        cp_commit();
    };

    load_chunk(0, 0);

    for (int c = 0; c < nchunks; c++) {
        int s = c & 1;
        cp_wait<0>();          // stage s data arrived (and any in-flight next-load too; conservative)
        __syncthreads();
        if (c + 1 < nchunks) load_chunk(c + 1, s ^ 1);   // overlaps with compute below

        const uint32_t* As = reinterpret_cast<const uint32_t*>(smem + (s ? OFF_AS1 : OFF_AS0));
        const uint32_t* Bs = reinterpret_cast<const uint32_t*>(smem + (s ? OFF_BS1 : OFF_BS0));

        #pragma unroll
        for (int ks = 0; ks < 4; ks++) {
            int kk = ks * 8;
            uint32_t a[2][4];
            #pragma unroll
            for (int im = 0; im < 2; im++) {
                int r = m0w + im * 16;
                a[im][0] = As[(r + g    ) * SA + kk + t    ];
                a[im][1] = As[(r + 8 + g) * SA + kk + t    ];
                a[im][2] = As[(r + g    ) * SA + kk + t + 4];
                a[im][3] = As[(r + 8 + g) * SA + kk + t + 4];
            }
            #pragma unroll
            for (int in = 0; in < 4; in++) {
                uint32_t b0 = Bs[(kk + t    ) * SB + n0w + in * 8 + g];
                uint32_t b1 = Bs[(kk + t + 4) * SB + n0w + in * 8 + g];
                mma_tf32(acc[0][in], a[0][0], a[0][1], a[0][2], a[0][3], b0, b1);
                mma_tf32(acc[1][in], a[1][0], a[1][1], a[1][2], a[1][3], b0, b1);
            }
        }
        __syncthreads();       // compute done before stage s is overwritten at c+2
    }

    // ---- epilogue ----
    #pragma unroll
    for (int im = 0; im < 2; im++) {
        int r0 = bm0 + m0w + im * 16 + g;
        int r1 = r0 + 8;
        #pragma unroll
        for (int in = 0; in < 4; in++) {
            int c = bn0 + n0w + in * 8 + 2 * t;
            if (c >= N) continue;   // N even -> c+1 < N too
            float bx = bias[c], by = bias[c + 1];

            float v0 = acc[im][in].x + bx;
            float v1 = acc[im][in].y + by;
            float v2 = acc[im][in].z + bx;
            float v3 = acc[im][in].w + by;
            if (act == ACT_GELU) {
                v0 = 0.5f * v0 * (1.0f + erff(v0 * 0.70710678118654752f));
                v1 = 0.5f * v1 * (1.0f + erff(v1 * 0.70710678118654752f));
                v2 = 0.5f * v2 * (1.0f + erff(v2 * 0.70710678118654752f));
                v3 = 0.5f * v3 * (1.0f + erff(v3 * 0.70710678118654752f));
            }
            if (r0 < M) {
                int oi = r0 * N + c;
                if (res1) { v0 += res1[oi]; v1 += res1[oi + 1]; }
                if (res2) { v0 += res2[oi]; v1 += res2[oi + 1]; }
                *reinterpret_cast<float2*>(Cout + oi) = make_float2(v0, v1);
            }
            if (r1 < M) {
                int oi = r1 * N + c;
                if (res1) { v2 += res1[oi]; v3 += res1[oi + 1]; }
                if (res2) { v2 += res2[oi]; v3 += res2[oi + 1]; }
                *reinterpret_cast<float2*>(Cout + oi) = make_float2(v2, v3);
            }
        }
    }
}

// ---------------- softmax over 12 (L*P) per (row, head) ----------------
__global__ void softmax_kernel()
{
    int idx = blockIdx.x * blockDim.x + threadIdx.x;   // (row*HEADS + h)
    if (idx >= RQ * HEADS) return;
    const float* in = g_logit + idx * (LEV * PTS);
    float* out = g_aw + idx * (LEV * PTS);
    float mx = -1e30f;
    float v[LEV * PTS];
    #pragma unroll
    for (int i = 0; i < LEV * PTS; i++) { v[i] = in[i]; mx = fmaxf(mx, v[i]); }
    float sum = 0.f;
    #pragma unroll
    for (int i = 0; i < LEV * PTS; i++) { v[i] = __expf(v[i] - mx); sum += v[i]; }
    float inv = 1.0f / sum;
    #pragma unroll
    for (int i = 0; i < LEV * PTS; i++) out[i] = v[i] * inv;
}

// ---------------- deformable sampling: one block per query row ----------------
__global__ void sample_kernel(const float* __restrict__ refp)
{
    int row = blockIdx.x;            // 0..RQ-1
    int b   = row / NQ;
    int t   = threadIdx.x;           // 256
    int h   = t >> 5;
    int d   = t & 31;

    __shared__ float s_off[NOFF];
    __shared__ float s_aw[NAW];
    __shared__ float s_ref[LEV * 2];
    if (t < NOFF) s_off[t] = g_offs[row * NOFF + t];
    if (t < NAW)  s_aw[t]  = g_aw[row * NAW + t];
    if (t < LEV * 2) s_ref[t] = refp[row * LEV * 2 + t];
    __syncthreads();

    const int Hl_[LEV] = {60, 30, 15};
    const int Wl_[LEV] = {80, 40, 20};
    const int St_[LEV] = {0, 4800, 6000};

    float acc = 0.f;
    #pragma unroll
    for (int l = 0; l < LEV; l++) {
        int Hl = Hl_[l], Wl = Wl_[l];
        const float* vbase = g_v + (b * NV + St_[l]) * CDIM + h * DH + d;
        float rx = s_ref[l * 2 + 0];
        float ry = s_ref[l * 2 + 1];
        #pragma unroll
        for (int p = 0; p < PTS; p++) {
            int oi = ((h * LEV + l) * PTS + p) * 2;
            float gx = rx * (float)Wl + s_off[oi + 0] - 0.5f;
            float gy = ry * (float)Hl + s_off[oi + 1] - 0.5f;
            float w  = s_aw[(h * LEV + l) * PTS + p];

            float x0f = floorf(gx), y0f = floorf(gy);
            int x0 = (int)x0f, y0 = (int)y0f;
            float wx = gx - x0f, wy = gy - y0f;

            float sv = 0.f;
            #pragma unroll
            for (int dy = 0; dy < 2; dy++) {
                int yi = y0 + dy;
                if (yi < 0 || yi >= Hl) continue;
                float wyv = dy ? wy : (1.f - wy);
                #pragma unroll
                for (int dx = 0; dx < 2; dx++) {
                    int xi = x0 + dx;
                    if (xi < 0 || xi >= Wl) continue;
                    float wxv = dx ? wx : (1.f - wx);
                    sv = fmaf(wyv * wxv, vbase[(yi * Wl + xi) * CDIM], sv);
                }
            }
            acc = fmaf(w, sv, acc);
        }
    }
    g_attn[row * CDIM + h * DH + d] = acc;
}

// ---------------- launch ----------------
extern "C" void kernel_launch(void* const* d_in, const int* in_sizes, int n_in,
                              void* d_out, int out_size)
{
    const float* query = (const float*)d_in[0];
    const float* value = (const float*)d_in[1];
    const float* qpos  = (const float*)d_in[2];
    const float* refp  = (const float*)d_in[3];
    const float* g1  = (const float*)d_in[6];
    const float* b1  = (const float*)d_in[7];
    const float* Wo  = (const float*)d_in[8];
    const float* bo  = (const float*)d_in[9];
    const float* Wa  = (const float*)d_in[10];
    const float* ba  = (const float*)d_in[11];
    const float* Wv  = (const float*)d_in[12];
    const float* bv  = (const float*)d_in[13];
    const float* Wp  = (const float*)d_in[14];
    const float* bp  = (const float*)d_in[15];
    const float* g2  = (const float*)d_in[16];
    const float* b2  = (const float*)d_in[17];
    const float* Wf1 = (const float*)d_in[18];
    const float* bf1 = (const float*)d_in[19];
    const float* Wf2 = (const float*)d_in[20];
    const float* bf2 = (const float*)d_in[21];
    float* out = (float*)d_out;

    float *qn, *qa, *offs, *logit, *vproj, *attn, *q, *q2, *hbuf;
    cudaGetSymbolAddress((void**)&qn,    g_qn);
    cudaGetSymbolAddress((void**)&qa,    g_qa);
    cudaGetSymbolAddress((void**)&offs,  g_offs);
    cudaGetSymbolAddress((void**)&logit, g_logit);
    cudaGetSymbolAddress((void**)&vproj, g_v);
    cudaGetSymbolAddress((void**)&attn,  g_attn);
    cudaGetSymbolAddress((void**)&q,     g_q);
    cudaGetSymbolAddress((void**)&q2,    g_q2);
    cudaGetSymbolAddress((void**)&hbuf,  g_h);

    cudaFuncSetAttribute(gemm_tf32_kernel, cudaFuncAttributeMaxDynamicSharedMemorySize, SMEM_TOT);

    // 1) LN1 (+pos) -> qn, qa
    ln_kernel<<<RQ, 256>>>(query, g1, b1, qpos, qn, qa);

    // 2) offsets: qa @ Wo + bo   [RQ x 192]
    gemm_tf32_kernel<<<dim3(3, RQ/128), 256, SMEM_TOT>>>(qa, Wo, bo, nullptr, nullptr, offs,
                                                         RQ, NOFF, CDIM, ACT_NONE);

    // 3) attention logits: qa @ Wa + ba   [RQ x 96]
    gemm_tf32_kernel<<<dim3(2, RQ/128), 256, SMEM_TOT>>>(qa, Wa, ba, nullptr, nullptr, logit,
                                                         RQ, NAW, CDIM, ACT_NONE);

    // 4) softmax over L*P
    softmax_kernel<<<(RQ*HEADS + 255)/256, 256>>>();

    // 5) value projection: value @ Wv + bv   [RV x 256]
    gemm_tf32_kernel<<<dim3(4, (RV + 127)/128), 256, SMEM_TOT>>>(value, Wv, bv, nullptr, nullptr, vproj,
                                                                 RV, CDIM, CDIM, ACT_NONE);

    // 6) deformable bilinear sampling -> attn [RQ x 256]
    sample_kernel<<<RQ, 256>>>(refp);

    // 7) output proj + both residuals: q = attn @ Wp + bp + qn + query
    gemm_tf32_kernel<<<dim3(4, RQ/128), 256, SMEM_TOT>>>(attn, Wp, bp, qn, query, q,
                                                         RQ, CDIM, CDIM, ACT_NONE);

    // 8) LN2 -> q2
    ln_kernel<<<RQ, 256>>>(q, g2, b2, nullptr, q2, nullptr);

    // 9) FFN up + GELU: h = gelu(q2 @ Wf1 + bf1)   [RQ x 1024]
    gemm_tf32_kernel<<<dim3(16, RQ/128), 256, SMEM_TOT>>>(q2, Wf1, bf1, nullptr, nullptr, hbuf,
                                                          RQ, HID, CDIM, ACT_GELU);

    // 10) FFN down + residual: out = h @ Wf2 + bf2 + q
    gemm_tf32_kernel<<<dim3(4, RQ/128), 256, SMEM_TOT>>>(hbuf, Wf2, bf2, q, nullptr, out,
                                                         RQ, CDIM, HID, ACT_NONE);
}

// round 7
// speedup vs baseline: 2.7415x; 1.0717x over previous
#include <cuda_runtime.h>
#include <cstdint>
#include <math.h>

// ---------------- problem constants (fixed shapes) ----------------
#define BATCH 2
#define NQ    8192
#define RQ    (BATCH*NQ)     // 16384 query rows
#define CDIM  256
#define HEADS 8
#define DH    32
#define LEV   3
#define PTS   4
#define NV    6300           // 4800+1200+300
#define RV    (BATCH*NV)     // 12600 value rows
#define HID   1024           // MLP*C
#define NOFF  (HEADS*LEV*PTS*2)  // 192
#define NAW   (HEADS*LEV*PTS)    // 96

// ---------------- scratch (static device memory; no allocs allowed) ----------------
__device__ float g_qn   [RQ*CDIM];
__device__ float g_qa   [RQ*CDIM];
__device__ float g_offs [RQ*NOFF];
__device__ float g_logit[RQ*NAW];
__device__ float g_v    [RV*CDIM];
__device__ float g_attn [RQ*CDIM];
__device__ float g_q    [RQ*CDIM];
__device__ float g_q2   [RQ*CDIM];
__device__ float g_h    [RQ*HID];

// ---------------- LayerNorm over C=256 (one block per row, 256 threads) ----------------
__global__ void ln_kernel(const float* __restrict__ x,
                          const float* __restrict__ g, const float* __restrict__ b,
                          const float* __restrict__ pos,
                          float* __restrict__ outn, float* __restrict__ outa)
{
    int row = blockIdx.x;
    int t = threadIdx.x;
    float v = x[row*CDIM + t];

    __shared__ float sred[8];
    __shared__ float s_mean, s_var;

    float s = v;
    #pragma unroll
    for (int o = 16; o > 0; o >>= 1) s += __shfl_xor_sync(0xffffffffu, s, o);
    if ((t & 31) == 0) sred[t >> 5] = s;
    __syncthreads();
    if (t == 0) {
        float tot = 0.f;
        #pragma unroll
        for (int i = 0; i < 8; i++) tot += sred[i];
        s_mean = tot * (1.0f / CDIM);
    }
    __syncthreads();
    float mean = s_mean;

    float d = v - mean;
    float s2 = d * d;
    #pragma unroll
    for (int o = 16; o > 0; o >>= 1) s2 += __shfl_xor_sync(0xffffffffu, s2, o);
    __syncthreads();
    if ((t & 31) == 0) sred[t >> 5] = s2;
    __syncthreads();
    if (t == 0) {
        float tot = 0.f;
        #pragma unroll
        for (int i = 0; i < 8; i++) tot += sred[i];
        s_var = tot * (1.0f / CDIM);
    }
    __syncthreads();

    float y = d * rsqrtf(s_var + 1e-5f) * g[t] + b[t];
    outn[row*CDIM + t] = y;
    if (outa) outa[row*CDIM + t] = y + pos[row*CDIM + t];
}

// ---------------- tf32 tensor-core GEMM, 4-stage cp.async pipeline ----------------
// C = act(A[MxK] @ W[KxN] + bias) (+res1 +res2)
// BM=128, BN=64, BK=32; 256 threads = 8 warps (4m x 2n); warp tile 32x32 (2x4 mma m16n8k8).
// Raw fp32 bits fed to tf32 mma (HW truncates mantissa).
#define ACT_NONE 0
#define ACT_GELU 1
#define SA 36   // As row pitch (floats), conflict-free fragment reads
#define SB 72   // Bs row pitch (floats), conflict-free fragment reads

#define AS_BYTES (128*SA*4)          // 18432
#define BS_BYTES (32*SB*4)           // 9216
#define STAGE_BYTES (AS_BYTES + BS_BYTES)   // 27648
#define NSTAGE 4
#define SMEM_TOT (NSTAGE*STAGE_BYTES)       // 110592

__device__ __forceinline__ uint32_t smem_u32(const void* p) {
    uint32_t a;
    asm("{ .reg .u64 t; cvta.to.shared.u64 t, %1; cvt.u32.u64 %0, t; }" : "=r"(a) : "l"(p));
    return a;
}
__device__ __forceinline__ void cp_async16(uint32_t dst, const void* src) {
    asm volatile("cp.async.cg.shared.global [%0], [%1], 16;" :: "r"(dst), "l"(src));
}
__device__ __forceinline__ void cp_commit() {
    asm volatile("cp.async.commit_group;" ::: "memory");
}
template<int N>
__device__ __forceinline__ void cp_wait() {
    asm volatile("cp.async.wait_group %0;" :: "n"(N) : "memory");
}

__device__ __forceinline__ void mma_tf32(float4& d,
                                         uint32_t a0, uint32_t a1, uint32_t a2, uint32_t a3,
                                         uint32_t b0, uint32_t b1) {
    asm volatile(
        "mma.sync.aligned.m16n8k8.row.col.f32.tf32.tf32.f32 "
        "{%0,%1,%2,%3}, {%4,%5,%6,%7}, {%8,%9}, {%0,%1,%2,%3};\n"
        : "+f"(d.x), "+f"(d.y), "+f"(d.z), "+f"(d.w)
        : "r"(a0), "r"(a1), "r"(a2), "r"(a3), "r"(b0), "r"(b1));
}

__global__ __launch_bounds__(256)
void gemm_tf32_kernel(const float* __restrict__ A, const float* __restrict__ W,
                      const float* __restrict__ bias,
                      const float* __restrict__ res1, const float* __restrict__ res2,
                      float* __restrict__ Cout,
                      int M, int N, int K, int act)
{
    extern __shared__ char smem[];
    uint32_t smem_base = smem_u32(smem);

    int tid  = threadIdx.x;
    int lane = tid & 31;
    int warp = tid >> 5;
    int g = lane >> 2;      // 0..7
    int t = lane & 3;       // 0..3
    int wm = warp >> 1;     // 0..3
    int wn = warp & 1;      // 0..1
    int m0w = wm * 32;
    int n0w = wn * 32;
    int bm0 = blockIdx.y * 128;
    int bn0 = blockIdx.x * 64;

    float4 acc[2][4];
    #pragma unroll
    for (int i = 0; i < 2; i++)
        #pragma unroll
        for (int j = 0; j < 4; j++)
            acc[i][j] = make_float4(0.f, 0.f, 0.f, 0.f);

    const int nchunks = K >> 5;

    // ---- stage loader: one commit group per chunk ----
    auto load_chunk = [&](int c, int s) {
        int k0 = c << 5;
        uint32_t as = smem_base + (uint32_t)(s * STAGE_BYTES);
        uint32_t bs = as + AS_BYTES;
        #pragma unroll
        for (int p = 0; p < 4; p++) {
            int idx = p * 256 + tid;
            int row = idx >> 3;
            int c4  = (idx & 7) * 4;
            int grow = bm0 + row; if (grow > M - 1) grow = M - 1;   // clamp, masked at store
            cp_async16(as + (uint32_t)(row * SA + c4) * 4u, A + grow * K + k0 + c4);
        }
        #pragma unroll
        for (int p = 0; p < 2; p++) {
            int idx = p * 256 + tid;
            int row = idx >> 4;
            int c   = (idx & 15) * 4;
            int gc  = bn0 + c; if (gc > N - 4) gc = N - 4;          // clamp, masked at store
            cp_async16(bs + (uint32_t)(row * SB + c) * 4u, W + (k0 + row) * N + gc);
        }
        cp_commit();
    };

    // prologue: 3 chunks in flight
    #pragma unroll
    for (int c0 = 0; c0 < 3; c0++)
        if (c0 < nchunks) load_chunk(c0, c0);

    for (int c = 0; c < nchunks; c++) {
        int s = c & 3;
        cp_wait<2>();          // pending <= 2 => chunk c's group has landed
        __syncthreads();       // all warps: stage visible; prev compute done
        if (c + 3 < nchunks) load_chunk(c + 3, (c + 3) & 3);   // overwrites stage (c-1)&3, safe

        const uint32_t* As = reinterpret_cast<const uint32_t*>(smem + s * STAGE_BYTES);
        const uint32_t* Bs = reinterpret_cast<const uint32_t*>(smem + s * STAGE_BYTES + AS_BYTES);

        #pragma unroll
        for (int ks = 0; ks < 4; ks++) {
            int kk = ks * 8;
            uint32_t a[2][4];
            #pragma unroll
            for (int im = 0; im < 2; im++) {
                int r = m0w + im * 16;
                a[im][0] = As[(r + g    ) * SA + kk + t    ];
                a[im][1] = As[(r + 8 + g) * SA + kk + t    ];
                a[im][2] = As[(r + g    ) * SA + kk + t + 4];
                a[im][3] = As[(r + 8 + g) * SA + kk + t + 4];
            }
            #pragma unroll
            for (int in = 0; in < 4; in++) {
                uint32_t b0 = Bs[(kk + t    ) * SB + n0w + in * 8 + g];
                uint32_t b1 = Bs[(kk + t + 4) * SB + n0w + in * 8 + g];
                mma_tf32(acc[0][in], a[0][0], a[0][1], a[0][2], a[0][3], b0, b1);
                mma_tf32(acc[1][in], a[1][0], a[1][1], a[1][2], a[1][3], b0, b1);
            }
        }
    }

    // ---- epilogue ----
    #pragma unroll
    for (int im = 0; im < 2; im++) {
        int r0 = bm0 + m0w + im * 16 + g;
        int r1 = r0 + 8;
        #pragma unroll
        for (int in = 0; in < 4; in++) {
            int c = bn0 + n0w + in * 8 + 2 * t;
            if (c >= N) continue;   // N even -> c+1 < N too
            float bx = bias[c], by = bias[c + 1];

            float v0 = acc[im][in].x + bx;
            float v1 = acc[im][in].y + by;
            float v2 = acc[im][in].z + bx;
            float v3 = acc[im][in].w + by;
            if (act == ACT_GELU) {
                v0 = 0.5f * v0 * (1.0f + erff(v0 * 0.70710678118654752f));
                v1 = 0.5f * v1 * (1.0f + erff(v1 * 0.70710678118654752f));
                v2 = 0.5f * v2 * (1.0f + erff(v2 * 0.70710678118654752f));
                v3 = 0.5f * v3 * (1.0f + erff(v3 * 0.70710678118654752f));
            }
            if (r0 < M) {
                int oi = r0 * N + c;
                if (res1) { v0 += res1[oi]; v1 += res1[oi + 1]; }
                if (res2) { v0 += res2[oi]; v1 += res2[oi + 1]; }
                *reinterpret_cast<float2*>(Cout + oi) = make_float2(v0, v1);
            }
            if (r1 < M) {
                int oi = r1 * N + c;
                if (res1) { v2 += res1[oi]; v3 += res1[oi + 1]; }
                if (res2) { v2 += res2[oi]; v3 += res2[oi + 1]; }
                *reinterpret_cast<float2*>(Cout + oi) = make_float2(v2, v3);
            }
        }
    }
}

// ---------------- deformable sampling + fused softmax ----------------
// 2 query rows per block, 256 threads. Thread layout: r = t>>7, h = (t>>4)&7, dpair = t&15.
__global__ void sample_kernel(const float* __restrict__ refp)
{
    int row0 = blockIdx.x * 2;
    int t    = threadIdx.x;

    __shared__ float s_off[2][NOFF];
    __shared__ float s_aw [2][NAW];
    __shared__ float s_ref[2][LEV * 2];

    #pragma unroll
    for (int r = 0; r < 2; r++) {
        int row = row0 + r;
        if (t < NOFF)   s_off[r][t] = g_offs[row * NOFF + t];
        if (t < NAW)    s_aw [r][t] = g_logit[row * NAW + t];
        if (t < LEV*2)  s_ref[r][t] = refp[row * LEV * 2 + t];
    }
    __syncthreads();

    // softmax over 12 per (r, h): 16 threads
    if (t < 16) {
        int r = t >> 3, h = t & 7;
        float* v = &s_aw[r][h * (LEV * PTS)];
        float mx = -1e30f;
        float e[LEV * PTS];
        #pragma unroll
        for (int i = 0; i < LEV * PTS; i++) mx = fmaxf(mx, v[i]);
        float sum = 0.f;
        #pragma unroll
        for (int i = 0; i < LEV * PTS; i++) { e[i] = __expf(v[i] - mx); sum += e[i]; }
        float inv = 1.0f / sum;
        #pragma unroll
        for (int i = 0; i < LEV * PTS; i++) v[i] = e[i] * inv;
    }
    __syncthreads();

    int r = t >> 7;                 // 0 or 1 (warps 0-3 vs 4-7)
    int h = (t >> 4) & 7;
    int d = (t & 15) * 2;
    int row = row0 + r;
    int b   = row / NQ;

    const int Hl_[LEV] = {60, 30, 15};
    const int Wl_[LEV] = {80, 40, 20};
    const int St_[LEV] = {0, 4800, 6000};

    float2 acc = make_float2(0.f, 0.f);
    #pragma unroll
    for (int l = 0; l < LEV; l++) {
        int Hl = Hl_[l], Wl = Wl_[l];
        const float* vbase = g_v + (b * NV + St_[l]) * CDIM + h * DH + d;
        float rx = s_ref[r][l * 2 + 0];
        float ry = s_ref[r][l * 2 + 1];
        #pragma unroll
        for (int p = 0; p < PTS; p++) {
            int oi = ((h * LEV + l) * PTS + p) * 2;
            float gx = rx * (float)Wl + s_off[r][oi + 0] - 0.5f;
            float gy = ry * (float)Hl + s_off[r][oi + 1] - 0.5f;
            float w  = s_aw[r][(h * LEV + l) * PTS + p];

            float x0f = floorf(gx), y0f = floorf(gy);
            int x0 = (int)x0f, y0 = (int)y0f;
            float wx = gx - x0f, wy = gy - y0f;

            float2 sv = make_float2(0.f, 0.f);
            #pragma unroll
            for (int dy = 0; dy < 2; dy++) {
                int yi = y0 + dy;
                if (yi < 0 || yi >= Hl) continue;
                float wyv = dy ? wy : (1.f - wy);
                #pragma unroll
                for (int dx = 0; dx < 2; dx++) {
                    int xi = x0 + dx;
                    if (xi < 0 || xi >= Wl) continue;
                    float wxv = dx ? wx : (1.f - wx);
                    float2 vv = *reinterpret_cast<const float2*>(vbase + (yi * Wl + xi) * CDIM);
                    float cw = wyv * wxv;
                    sv.x = fmaf(cw, vv.x, sv.x);
                    sv.y = fmaf(cw, vv.y, sv.y);
                }
            }
            acc.x = fmaf(w, sv.x, acc.x);
            acc.y = fmaf(w, sv.y, acc.y);
        }
    }
    *reinterpret_cast<float2*>(&g_attn[row * CDIM + h * DH + d]) = acc;
}

// ---------------- launch ----------------
extern "C" void kernel_launch(void* const* d_in, const int* in_sizes, int n_in,
                              void* d_out, int out_size)
{
    const float* query = (const float*)d_in[0];
    const float* value = (const float*)d_in[1];
    const float* qpos  = (const float*)d_in[2];
    const float* refp  = (const float*)d_in[3];
    const float* g1  = (const float*)d_in[6];
    const float* b1  = (const float*)d_in[7];
    const float* Wo  = (const float*)d_in[8];
    const float* bo  = (const float*)d_in[9];
    const float* Wa  = (const float*)d_in[10];
    const float* ba  = (const float*)d_in[11];
    const float* Wv  = (const float*)d_in[12];
    const float* bv  = (const float*)d_in[13];
    const float* Wp  = (const float*)d_in[14];
    const float* bp  = (const float*)d_in[15];
    const float* g2  = (const float*)d_in[16];
    const float* b2  = (const float*)d_in[17];
    const float* Wf1 = (const float*)d_in[18];
    const float* bf1 = (const float*)d_in[19];
    const float* Wf2 = (const float*)d_in[20];
    const float* bf2 = (const float*)d_in[21];
    float* out = (float*)d_out;

    float *qn, *qa, *offs, *logit, *vproj, *attn, *q, *q2, *hbuf;
    cudaGetSymbolAddress((void**)&qn,    g_qn);
    cudaGetSymbolAddress((void**)&qa,    g_qa);
    cudaGetSymbolAddress((void**)&offs,  g_offs);
    cudaGetSymbolAddress((void**)&logit, g_logit);
    cudaGetSymbolAddress((void**)&vproj, g_v);
    cudaGetSymbolAddress((void**)&attn,  g_attn);
    cudaGetSymbolAddress((void**)&q,     g_q);
    cudaGetSymbolAddress((void**)&q2,    g_q2);
    cudaGetSymbolAddress((void**)&hbuf,  g_h);

    cudaFuncSetAttribute(gemm_tf32_kernel, cudaFuncAttributeMaxDynamicSharedMemorySize, SMEM_TOT);

    // 1) LN1 (+pos) -> qn, qa
    ln_kernel<<<RQ, 256>>>(query, g1, b1, qpos, qn, qa);

    // 2) offsets: qa @ Wo + bo   [RQ x 192]
    gemm_tf32_kernel<<<dim3(3, RQ/128), 256, SMEM_TOT>>>(qa, Wo, bo, nullptr, nullptr, offs,
                                                         RQ, NOFF, CDIM, ACT_NONE);

    // 3) attention logits: qa @ Wa + ba   [RQ x 96]
    gemm_tf32_kernel<<<dim3(2, RQ/128), 256, SMEM_TOT>>>(qa, Wa, ba, nullptr, nullptr, logit,
                                                         RQ, NAW, CDIM, ACT_NONE);

    // 4) value projection: value @ Wv + bv   [RV x 256]
    gemm_tf32_kernel<<<dim3(4, (RV + 127)/128), 256, SMEM_TOT>>>(value, Wv, bv, nullptr, nullptr, vproj,
                                                                 RV, CDIM, CDIM, ACT_NONE);

    // 5) fused softmax + deformable bilinear sampling -> attn [RQ x 256]
    sample_kernel<<<RQ/2, 256>>>(refp);

    // 6) output proj + both residuals: q = attn @ Wp + bp + qn + query
    gemm_tf32_kernel<<<dim3(4, RQ/128), 256, SMEM_TOT>>>(attn, Wp, bp, qn, query, q,
                                                         RQ, CDIM, CDIM, ACT_NONE);

    // 7) LN2 -> q2
    ln_kernel<<<RQ, 256>>>(q, g2, b2, nullptr, q2, nullptr);

    // 8) FFN up + GELU: h = gelu(q2 @ Wf1 + bf1)   [RQ x 1024]
    gemm_tf32_kernel<<<dim3(16, RQ/128), 256, SMEM_TOT>>>(q2, Wf1, bf1, nullptr, nullptr, hbuf,
                                                          RQ, HID, CDIM, ACT_GELU);

    // 9) FFN down + residual: out = h @ Wf2 + bf2 + q
    gemm_tf32_kernel<<<dim3(4, RQ/128), 256, SMEM_TOT>>>(hbuf, Wf2, bf2, q, nullptr, out,
                                                         RQ, CDIM, HID, ACT_NONE);
}

// round 8
// speedup vs baseline: 2.7999x; 1.0213x over previous
#include <cuda_runtime.h>
#include <cuda_fp16.h>
#include <cstdint>
#include <math.h>

// ---------------- problem constants (fixed shapes) ----------------
#define BATCH 2
#define NQ    8192
#define RQ    (BATCH*NQ)     // 16384 query rows
#define CDIM  256
#define HEADS 8
#define DH    32
#define LEV   3
#define PTS   4
#define NV    6300           // 4800+1200+300
#define RV    (BATCH*NV)     // 12600 value rows
#define HID   1024           // MLP*C
#define NOFF  (HEADS*LEV*PTS*2)  // 192
#define NAW   (HEADS*LEV*PTS)    // 96
#define NOL   (NOFF+NAW)         // 288 fused offs+logits width

// ---------------- scratch (static device memory; no allocs allowed) ----------------
__device__ float  g_qn  [RQ*CDIM];
__device__ float  g_qa  [RQ*CDIM];
__device__ float  g_ol  [RQ*NOL];      // fused offsets(0..191) + logits(192..287)
__device__ __half g_v   [RV*CDIM];     // fp16 projected values
__device__ float  g_attn[RQ*CDIM];
__device__ float  g_q   [RQ*CDIM];
__device__ float  g_q2  [RQ*CDIM];
__device__ float  g_h   [RQ*HID];
__device__ float  g_wcat[CDIM*NOL];    // [K][288] concat of Wo|Wa
__device__ float  g_bcat[NOL];

// ---------------- weight concat: Wcat[k][0:192)=Wo, [192:288)=Wa ----------------
__global__ void concat_kernel(const float* __restrict__ Wo, const float* __restrict__ Wa,
                              const float* __restrict__ bo, const float* __restrict__ ba)
{
    int i = blockIdx.x * 256 + threadIdx.x;
    if (i < CDIM * NOL) {
        int k = i / NOL, n = i % NOL;
        g_wcat[i] = (n < NOFF) ? Wo[k * NOFF + n] : Wa[k * NAW + (n - NOFF)];
    }
    if (i < NOL) g_bcat[i] = (i < NOFF) ? bo[i] : ba[i - NOFF];
}

// ---------------- LayerNorm over C=256 (one block per row, 256 threads) ----------------
__global__ void ln_kernel(const float* __restrict__ x,
                          const float* __restrict__ g, const float* __restrict__ b,
                          const float* __restrict__ pos,
                          float* __restrict__ outn, float* __restrict__ outa)
{
    int row = blockIdx.x;
    int t = threadIdx.x;
    float v = x[row*CDIM + t];

    __shared__ float sred[8];
    __shared__ float s_mean, s_var;

    float s = v;
    #pragma unroll
    for (int o = 16; o > 0; o >>= 1) s += __shfl_xor_sync(0xffffffffu, s, o);
    if ((t & 31) == 0) sred[t >> 5] = s;
    __syncthreads();
    if (t == 0) {
        float tot = 0.f;
        #pragma unroll
        for (int i = 0; i < 8; i++) tot += sred[i];
        s_mean = tot * (1.0f / CDIM);
    }
    __syncthreads();
    float mean = s_mean;

    float d = v - mean;
    float s2 = d * d;
    #pragma unroll
    for (int o = 16; o > 0; o >>= 1) s2 += __shfl_xor_sync(0xffffffffu, s2, o);
    __syncthreads();
    if ((t & 31) == 0) sred[t >> 5] = s2;
    __syncthreads();
    if (t == 0) {
        float tot = 0.f;
        #pragma unroll
        for (int i = 0; i < 8; i++) tot += sred[i];
        s_var = tot * (1.0f / CDIM);
    }
    __syncthreads();

    float y = d * rsqrtf(s_var + 1e-5f) * g[t] + b[t];
    outn[row*CDIM + t] = y;
    if (outa) outa[row*CDIM + t] = y + pos[row*CDIM + t];
}

// ---------------- tf32 tensor-core GEMM, 4-stage cp.async pipeline ----------------
// C = act(A[MxK] @ W[KxN] + bias) (+res1 +res2); optional fp16 output.
// BM=128, BN=64, BK=32; 256 threads = 8 warps (4m x 2n); warp tile 32x32 (2x4 mma m16n8k8).
#define ACT_NONE 0
#define ACT_GELU 1
#define SA 36
#define SB 72

#define AS_BYTES (128*SA*4)          // 18432
#define BS_BYTES (32*SB*4)           // 9216
#define STAGE_BYTES (AS_BYTES + BS_BYTES)   // 27648
#define NSTAGE 4
#define SMEM_TOT (NSTAGE*STAGE_BYTES)       // 110592

__device__ __forceinline__ uint32_t smem_u32(const void* p) {
    uint32_t a;
    asm("{ .reg .u64 t; cvta.to.shared.u64 t, %1; cvt.u32.u64 %0, t; }" : "=r"(a) : "l"(p));
    return a;
}
__device__ __forceinline__ void cp_async16(uint32_t dst, const void* src) {
    asm volatile("cp.async.cg.shared.global [%0], [%1], 16;" :: "r"(dst), "l"(src));
}
__device__ __forceinline__ void cp_commit() {
    asm volatile("cp.async.commit_group;" ::: "memory");
}
template<int N>
__device__ __forceinline__ void cp_wait() {
    asm volatile("cp.async.wait_group %0;" :: "n"(N) : "memory");
}

__device__ __forceinline__ void mma_tf32(float4& d,
                                         uint32_t a0, uint32_t a1, uint32_t a2, uint32_t a3,
                                         uint32_t b0, uint32_t b1) {
    asm volatile(
        "mma.sync.aligned.m16n8k8.row.col.f32.tf32.tf32.f32 "
        "{%0,%1,%2,%3}, {%4,%5,%6,%7}, {%8,%9}, {%0,%1,%2,%3};\n"
        : "+f"(d.x), "+f"(d.y), "+f"(d.z), "+f"(d.w)
        : "r"(a0), "r"(a1), "r"(a2), "r"(a3), "r"(b0), "r"(b1));
}

__global__ __launch_bounds__(256)
void gemm_tf32_kernel(const float* __restrict__ A, const float* __restrict__ W,
                      const float* __restrict__ bias,
                      const float* __restrict__ res1, const float* __restrict__ res2,
                      void* __restrict__ Cout,
                      int M, int N, int K, int act, int out_half)
{
    extern __shared__ char smem[];
    uint32_t smem_base = smem_u32(smem);

    int tid  = threadIdx.x;
    int lane = tid & 31;
    int warp = tid >> 5;
    int g = lane >> 2;
    int t = lane & 3;
    int wm = warp >> 1;
    int wn = warp & 1;
    int m0w = wm * 32;
    int n0w = wn * 32;
    int bm0 = blockIdx.y * 128;
    int bn0 = blockIdx.x * 64;

    float4 acc[2][4];
    #pragma unroll
    for (int i = 0; i < 2; i++)
        #pragma unroll
        for (int j = 0; j < 4; j++)
            acc[i][j] = make_float4(0.f, 0.f, 0.f, 0.f);

    const int nchunks = K >> 5;

    auto load_chunk = [&](int c, int s) {
        int k0 = c << 5;
        uint32_t as = smem_base + (uint32_t)(s * STAGE_BYTES);
        uint32_t bs = as + AS_BYTES;
        #pragma unroll
        for (int p = 0; p < 4; p++) {
            int idx = p * 256 + tid;
            int row = idx >> 3;
            int c4  = (idx & 7) * 4;
            int grow = bm0 + row; if (grow > M - 1) grow = M - 1;
            cp_async16(as + (uint32_t)(row * SA + c4) * 4u, A + grow * K + k0 + c4);
        }
        #pragma unroll
        for (int p = 0; p < 2; p++) {
            int idx = p * 256 + tid;
            int row = idx >> 4;
            int c   = (idx & 15) * 4;
            int gc  = bn0 + c; if (gc > N - 4) gc = N - 4;
            cp_async16(bs + (uint32_t)(row * SB + c) * 4u, W + (k0 + row) * N + gc);
        }
        cp_commit();
    };

    #pragma unroll
    for (int c0 = 0; c0 < 3; c0++)
        if (c0 < nchunks) load_chunk(c0, c0);

    for (int c = 0; c < nchunks; c++) {
        int s = c & 3;
        cp_wait<2>();
        __syncthreads();
        if (c + 3 < nchunks) load_chunk(c + 3, (c + 3) & 3);

        const uint32_t* As = reinterpret_cast<const uint32_t*>(smem + s * STAGE_BYTES);
        const uint32_t* Bs = reinterpret_cast<const uint32_t*>(smem + s * STAGE_BYTES + AS_BYTES);

        #pragma unroll
        for (int ks = 0; ks < 4; ks++) {
            int kk = ks * 8;
            uint32_t a[2][4];
            #pragma unroll
            for (int im = 0; im < 2; im++) {
                int r = m0w + im * 16;
                a[im][0] = As[(r + g    ) * SA + kk + t    ];
                a[im][1] = As[(r + 8 + g) * SA + kk + t    ];
                a[im][2] = As[(r + g    ) * SA + kk + t + 4];
                a[im][3] = As[(r + 8 + g) * SA + kk + t + 4];
            }
            #pragma unroll
            for (int in = 0; in < 4; in++) {
                uint32_t b0 = Bs[(kk + t    ) * SB + n0w + in * 8 + g];
                uint32_t b1 = Bs[(kk + t + 4) * SB + n0w + in * 8 + g];
                mma_tf32(acc[0][in], a[0][0], a[0][1], a[0][2], a[0][3], b0, b1);
                mma_tf32(acc[1][in], a[1][0], a[1][1], a[1][2], a[1][3], b0, b1);
            }
        }
    }

    // ---- epilogue ----
    #pragma unroll
    for (int im = 0; im < 2; im++) {
        int r0 = bm0 + m0w + im * 16 + g;
        int r1 = r0 + 8;
        #pragma unroll
        for (int in = 0; in < 4; in++) {
            int c = bn0 + n0w + in * 8 + 2 * t;
            if (c >= N) continue;
            float bx = bias[c], by = bias[c + 1];

            float v0 = acc[im][in].x + bx;
            float v1 = acc[im][in].y + by;
            float v2 = acc[im][in].z + bx;
            float v3 = acc[im][in].w + by;
            if (act == ACT_GELU) {
                v0 = 0.5f * v0 * (1.0f + erff(v0 * 0.70710678118654752f));
                v1 = 0.5f * v1 * (1.0f + erff(v1 * 0.70710678118654752f));
                v2 = 0.5f * v2 * (1.0f + erff(v2 * 0.70710678118654752f));
                v3 = 0.5f * v3 * (1.0f + erff(v3 * 0.70710678118654752f));
            }
            if (r0 < M) {
                int oi = r0 * N + c;
                if (res1) { v0 += res1[oi]; v1 += res1[oi + 1]; }
                if (res2) { v0 += res2[oi]; v1 += res2[oi + 1]; }
                if (out_half)
                    *reinterpret_cast<__half2*>((__half*)Cout + oi) = __floats2half2_rn(v0, v1);
                else
                    *reinterpret_cast<float2*>((float*)Cout + oi) = make_float2(v0, v1);
            }
            if (r1 < M) {
                int oi = r1 * N + c;
                if (res1) { v2 += res1[oi]; v3 += res1[oi + 1]; }
                if (res2) { v2 += res2[oi]; v3 += res2[oi + 1]; }
                if (out_half)
                    *reinterpret_cast<__half2*>((__half*)Cout + oi) = __floats2half2_rn(v2, v3);
                else
                    *reinterpret_cast<float2*>((float*)Cout + oi) = make_float2(v2, v3);
            }
        }
    }
}

// ---------------- deformable sampling + fused softmax (fp16 values) ----------------
// 2 query rows per block, 256 threads. r = t>>7, h = (t>>4)&7, dpair = t&15.
__global__ void sample_kernel(const float* __restrict__ refp)
{
    int row0 = blockIdx.x * 2;
    int t    = threadIdx.x;

    __shared__ float s_off[2][NOFF];
    __shared__ float s_aw [2][NAW];
    __shared__ float s_ref[2][LEV * 2];

    #pragma unroll
    for (int r = 0; r < 2; r++) {
        int row = row0 + r;
        if (t < NOFF)   s_off[r][t] = g_ol[row * NOL + t];
        if (t < NAW)    s_aw [r][t] = g_ol[row * NOL + NOFF + t];
        if (t < LEV*2)  s_ref[r][t] = refp[row * LEV * 2 + t];
    }
    __syncthreads();

    if (t < 16) {
        int r = t >> 3, h = t & 7;
        float* v = &s_aw[r][h * (LEV * PTS)];
        float mx = -1e30f;
        float e[LEV * PTS];
        #pragma unroll
        for (int i = 0; i < LEV * PTS; i++) mx = fmaxf(mx, v[i]);
        float sum = 0.f;
        #pragma unroll
        for (int i = 0; i < LEV * PTS; i++) { e[i] = __expf(v[i] - mx); sum += e[i]; }
        float inv = 1.0f / sum;
        #pragma unroll
        for (int i = 0; i < LEV * PTS; i++) v[i] = e[i] * inv;
    }
    __syncthreads();

    int r = t >> 7;
    int h = (t >> 4) & 7;
    int d = (t & 15) * 2;
    int row = row0 + r;
    int b   = row / NQ;

    const int Hl_[LEV] = {60, 30, 15};
    const int Wl_[LEV] = {80, 40, 20};
    const int St_[LEV] = {0, 4800, 6000};

    float2 acc = make_float2(0.f, 0.f);
    #pragma unroll
    for (int l = 0; l < LEV; l++) {
        int Hl = Hl_[l], Wl = Wl_[l];
        const __half* vbase = g_v + (b * NV + St_[l]) * CDIM + h * DH + d;
        float rx = s_ref[r][l * 2 + 0];
        float ry = s_ref[r][l * 2 + 1];
        #pragma unroll
        for (int p = 0; p < PTS; p++) {
            int oi = ((h * LEV + l) * PTS + p) * 2;
            float gx = rx * (float)Wl + s_off[r][oi + 0] - 0.5f;
            float gy = ry * (float)Hl + s_off[r][oi + 1] - 0.5f;
            float w  = s_aw[r][(h * LEV + l) * PTS + p];

            float x0f = floorf(gx), y0f = floorf(gy);
            int x0 = (int)x0f, y0 = (int)y0f;
            float wx = gx - x0f, wy = gy - y0f;

            float2 sv = make_float2(0.f, 0.f);
            #pragma unroll
            for (int dy = 0; dy < 2; dy++) {
                int yi = y0 + dy;
                if (yi < 0 || yi >= Hl) continue;
                float wyv = dy ? wy : (1.f - wy);
                #pragma unroll
                for (int dx = 0; dx < 2; dx++) {
                    int xi = x0 + dx;
                    if (xi < 0 || xi >= Wl) continue;
                    float wxv = dx ? wx : (1.f - wx);
                    __half2 hv = *reinterpret_cast<const __half2*>(vbase + (yi * Wl + xi) * CDIM);
                    float2 vv = __half22float2(hv);
                    float cw = wyv * wxv;
                    sv.x = fmaf(cw, vv.x, sv.x);
                    sv.y = fmaf(cw, vv.y, sv.y);
                }
            }
            acc.x = fmaf(w, sv.x, acc.x);
            acc.y = fmaf(w, sv.y, acc.y);
        }
    }
    *reinterpret_cast<float2*>(&g_attn[row * CDIM + h * DH + d]) = acc;
}

// ---------------- launch ----------------
extern "C" void kernel_launch(void* const* d_in, const int* in_sizes, int n_in,
                              void* d_out, int out_size)
{
    const float* query = (const float*)d_in[0];
    const float* value = (const float*)d_in[1];
    const float* qpos  = (const float*)d_in[2];
    const float* refp  = (const float*)d_in[3];
    const float* g1  = (const float*)d_in[6];
    const float* b1  = (const float*)d_in[7];
    const float* Wo  = (const float*)d_in[8];
    const float* bo  = (const float*)d_in[9];
    const float* Wa  = (const float*)d_in[10];
    const float* ba  = (const float*)d_in[11];
    const float* Wv  = (const float*)d_in[12];
    const float* bv  = (const float*)d_in[13];
    const float* Wp  = (const float*)d_in[14];
    const float* bp  = (const float*)d_in[15];
    const float* g2  = (const float*)d_in[16];
    const float* b2  = (const float*)d_in[17];
    const float* Wf1 = (const float*)d_in[18];
    const float* bf1 = (const float*)d_in[19];
    const float* Wf2 = (const float*)d_in[20];
    const float* bf2 = (const float*)d_in[21];
    float* out = (float*)d_out;

    float *qn, *qa, *olbuf, *attn, *q, *q2, *hbuf, *wcat, *bcat;
    __half* vproj;
    cudaGetSymbolAddress((void**)&qn,    g_qn);
    cudaGetSymbolAddress((void**)&qa,    g_qa);
    cudaGetSymbolAddress((void**)&olbuf, g_ol);
    cudaGetSymbolAddress((void**)&vproj, g_v);
    cudaGetSymbolAddress((void**)&attn,  g_attn);
    cudaGetSymbolAddress((void**)&q,     g_q);
    cudaGetSymbolAddress((void**)&q2,    g_q2);
    cudaGetSymbolAddress((void**)&hbuf,  g_h);
    cudaGetSymbolAddress((void**)&wcat,  g_wcat);
    cudaGetSymbolAddress((void**)&bcat,  g_bcat);

    cudaFuncSetAttribute(gemm_tf32_kernel, cudaFuncAttributeMaxDynamicSharedMemorySize, SMEM_TOT);

    // 0) weight concat for fused offs+logits GEMM
    concat_kernel<<<(CDIM*NOL + 255)/256, 256>>>(Wo, Wa, bo, ba);

    // 1) LN1 (+pos) -> qn, qa
    ln_kernel<<<RQ, 256>>>(query, g1, b1, qpos, qn, qa);

    // 2) fused offsets+logits: qa @ Wcat + bcat   [RQ x 288]
    gemm_tf32_kernel<<<dim3((NOL + 63)/64, RQ/128), 256, SMEM_TOT>>>(
        qa, wcat, bcat, nullptr, nullptr, olbuf, RQ, NOL, CDIM, ACT_NONE, 0);

    // 3) value projection -> fp16: value @ Wv + bv   [RV x 256]
    gemm_tf32_kernel<<<dim3(4, (RV + 127)/128), 256, SMEM_TOT>>>(
        value, Wv, bv, nullptr, nullptr, vproj, RV, CDIM, CDIM, ACT_NONE, 1);

    // 4) fused softmax + deformable bilinear sampling -> attn [RQ x 256]
    sample_kernel<<<RQ/2, 256>>>(refp);

    // 5) output proj + both residuals: q = attn @ Wp + bp + qn + query
    gemm_tf32_kernel<<<dim3(4, RQ/128), 256, SMEM_TOT>>>(
        attn, Wp, bp, qn, query, q, RQ, CDIM, CDIM, ACT_NONE, 0);

    // 6) LN2 -> q2
    ln_kernel<<<RQ, 256>>>(q, g2, b2, nullptr, q2, nullptr);

    // 7) FFN up + GELU: h = gelu(q2 @ Wf1 + bf1)   [RQ x 1024]
    gemm_tf32_kernel<<<dim3(16, RQ/128), 256, SMEM_TOT>>>(
        q2, Wf1, bf1, nullptr, nullptr, hbuf, RQ, HID, CDIM, ACT_GELU, 0);

    // 8) FFN down + residual: out = h @ Wf2 + bf2 + q
    gemm_tf32_kernel<<<dim3(4, RQ/128), 256, SMEM_TOT>>>(
        hbuf, Wf2, bf2, q, nullptr, out, RQ, CDIM, HID, ACT_NONE, 0);
}

// round 11
// speedup vs baseline: 3.3172x; 1.1847x over previous
#include <cuda_runtime.h>
#include <cuda_fp16.h>
#include <cstdint>
#include <math.h>

// ---------------- problem constants (fixed shapes) ----------------
#define BATCH 2
#define NQ    8192
#define RQ    (BATCH*NQ)     // 16384 query rows
#define CDIM  256
#define HEADS 8
#define DH    32
#define LEV   3
#define PTS   4
#define NV    6300           // 4800+1200+300
#define RV    (BATCH*NV)     // 12600 value rows
#define HID   1024           // MLP*C
#define NOFF  (HEADS*LEV*PTS*2)  // 192
#define NAW   (HEADS*LEV*PTS)    // 96
#define NOL   (NOFF+NAW)         // 288 fused offs+logits width

// ---------------- scratch (static device memory; no allocs allowed) ----------------
__device__ float  g_qn   [RQ*CDIM];     // LN1 out (residual, fp32)
__device__ __half g_qa_h [RQ*CDIM];     // LN1 out + pos (GEMM A, fp16)
__device__ float  g_ol   [RQ*NOL];      // fused offsets+logits (fp32)
__device__ __half g_val_h[RV*CDIM];     // value input converted to fp16
__device__ __half g_v    [RV*CDIM];     // projected values (fp16)
__device__ __half g_attn_h[RQ*CDIM];    // sampler out (GEMM A, fp16)
__device__ float  g_q    [RQ*CDIM];     // post-attention residual (fp32)
__device__ __half g_q2_h [RQ*CDIM];     // LN2 out (GEMM A, fp16)
__device__ __half g_h_h  [RQ*HID];      // FFN hidden (fp16)
// fp16 transposed weights [N][K]
__device__ __half g_wcatT[NOL*CDIM];    // Wo|Wa concat, rows 0..191 = Wo, 192..287 = Wa
__device__ __half g_wvT  [CDIM*CDIM];
__device__ __half g_wpT  [CDIM*CDIM];
__device__ __half g_wf1T [HID*CDIM];
__device__ __half g_wf2T [CDIM*HID];
__device__ float  g_bcat [NOL];

// ---------------- small prep kernels ----------------
__global__ void f2h_kernel(const float* __restrict__ src, __half* __restrict__ dst, int n)
{
    int i = (blockIdx.x * 256 + threadIdx.x) * 4;
    if (i < n) {
        float4 v = *reinterpret_cast<const float4*>(src + i);
        __half2 a = __floats2half2_rn(v.x, v.y);
        __half2 b = __floats2half2_rn(v.z, v.w);
        *reinterpret_cast<__half2*>(dst + i)     = a;
        *reinterpret_cast<__half2*>(dst + i + 2) = b;
    }
}

// src [K][N] fp32 -> dst [N][K] fp16
__global__ void transpose_h_kernel(const float* __restrict__ src, __half* __restrict__ dst,
                                   int K, int N)
{
    __shared__ float tile[32][33];
    int k0 = blockIdx.y * 32, n0 = blockIdx.x * 32;
    int tx = threadIdx.x, ty = threadIdx.y;   // 32 x 8
    #pragma unroll
    for (int i = ty; i < 32; i += 8)
        tile[i][tx] = src[(k0 + i) * N + (n0 + tx)];
    __syncthreads();
    #pragma unroll
    for (int i = ty; i < 32; i += 8)
        dst[(n0 + i) * K + (k0 + tx)] = __float2half_rn(tile[tx][i]);
}

__global__ void bias_concat_kernel(const float* __restrict__ bo, const float* __restrict__ ba)
{
    int i = threadIdx.x;
    if (i < NOL) g_bcat[i] = (i < NOFF) ? bo[i] : ba[i - NOFF];
}

// ---------------- LayerNorm over C=256 (one block per row, 256 threads) ----------------
__global__ void ln_kernel(const float* __restrict__ x,
                          const float* __restrict__ g, const float* __restrict__ b,
                          const float* __restrict__ pos,
                          float* __restrict__ outn, __half* __restrict__ outh)
{
    int row = blockIdx.x;
    int t = threadIdx.x;
    float v = x[row*CDIM + t];

    __shared__ float sred[8];
    __shared__ float s_mean, s_var;

    float s = v;
    #pragma unroll
    for (int o = 16; o > 0; o >>= 1) s += __shfl_xor_sync(0xffffffffu, s, o);
    if ((t & 31) == 0) sred[t >> 5] = s;
    __syncthreads();
    if (t == 0) {
        float tot = 0.f;
        #pragma unroll
        for (int i = 0; i < 8; i++) tot += sred[i];
        s_mean = tot * (1.0f / CDIM);
    }
    __syncthreads();
    float mean = s_mean;

    float d = v - mean;
    float s2 = d * d;
    #pragma unroll
    for (int o = 16; o > 0; o >>= 1) s2 += __shfl_xor_sync(0xffffffffu, s2, o);
    __syncthreads();
    if ((t & 31) == 0) sred[t >> 5] = s2;
    __syncthreads();
    if (t == 0) {
        float tot = 0.f;
        #pragma unroll
        for (int i = 0; i < 8; i++) tot += sred[i];
        s_var = tot * (1.0f / CDIM);
    }
    __syncthreads();

    float y = d * rsqrtf(s_var + 1e-5f) * g[t] + b[t];
    if (outn) outn[row*CDIM + t] = y;
    float ya = pos ? (y + pos[row*CDIM + t]) : y;
    outh[row*CDIM + t] = __float2half_rn(ya);
}

// ---------------- fp16 tensor-core GEMM, 4-stage cp.async pipeline ----------------
// C = act(A[MxK]h @ WT[NxK]h^T + bias) (+res1 +res2), fp32 accum.
// BM=128, BN=64, BK=64; 256 threads = 8 warps (4m x 2n); warp tile 32x32 (2x4 mma m16n8k16).
#define ACT_NONE 0
#define ACT_GELU 1
#define PH 72    // smem row pitch in halves (144B; 36 b32 words -> 4g+t bank pattern)

#define AS_BYTES (128*PH*2)          // 18432
#define BS_BYTES (64*PH*2)           // 9216
#define STAGE_BYTES (AS_BYTES + BS_BYTES)   // 27648
#define SMEM_TOT (4*STAGE_BYTES)            // 110592

__device__ __forceinline__ uint32_t smem_u32(const void* p) {
    uint32_t a;
    asm("{ .reg .u64 t; cvta.to.shared.u64 t, %1; cvt.u32.u64 %0, t; }" : "=r"(a) : "l"(p));
    return a;
}
__device__ __forceinline__ void cp_async16(uint32_t dst, const void* src) {
    asm volatile("cp.async.cg.shared.global [%0], [%1], 16;" :: "r"(dst), "l"(src));
}
__device__ __forceinline__ void cp_commit() {
    asm volatile("cp.async.commit_group;" ::: "memory");
}
template<int N>
__device__ __forceinline__ void cp_wait() {
    asm volatile("cp.async.wait_group %0;" :: "n"(N) : "memory");
}

__device__ __forceinline__ void mma_f16(float4& d,
                                        uint32_t a0, uint32_t a1, uint32_t a2, uint32_t a3,
                                        uint32_t b0, uint32_t b1) {
    asm volatile(
        "mma.sync.aligned.m16n8k16.row.col.f32.f16.f16.f32 "
        "{%0,%1,%2,%3}, {%4,%5,%6,%7}, {%8,%9}, {%0,%1,%2,%3};\n"
        : "+f"(d.x), "+f"(d.y), "+f"(d.z), "+f"(d.w)
        : "r"(a0), "r"(a1), "r"(a2), "r"(a3), "r"(b0), "r"(b1));
}

__global__ __launch_bounds__(256)
void gemm_f16_kernel(const __half* __restrict__ A, const __half* __restrict__ WT,
                     const float* __restrict__ bias,
                     const float* __restrict__ res1, const float* __restrict__ res2,
                     void* __restrict__ Cout,
                     int M, int N, int K, int act, int out_half)
{
    extern __shared__ char smem[];
    uint32_t smem_base = smem_u32(smem);

    int tid  = threadIdx.x;
    int lane = tid & 31;
    int warp = tid >> 5;
    int g = lane >> 2;      // 0..7
    int t = lane & 3;       // 0..3
    int wm = warp >> 1;     // 0..3
    int wn = warp & 1;      // 0..1
    int m0w = wm * 32;
    int n0w = wn * 32;
    int bm0 = blockIdx.y * 128;
    int bn0 = blockIdx.x * 64;

    float4 acc[2][4];
    #pragma unroll
    for (int i = 0; i < 2; i++)
        #pragma unroll
        for (int j = 0; j < 4; j++)
            acc[i][j] = make_float4(0.f, 0.f, 0.f, 0.f);

    const int nchunks = K >> 6;     // BK=64

    // ---- stage loader: A 128x64h, B 64x64h; exactly one commit group ----
    auto load_chunk = [&](int c, int s) {
        int k0 = c << 6;
        uint32_t as = smem_base + (uint32_t)(s * STAGE_BYTES);
        uint32_t bs = as + AS_BYTES;
        #pragma unroll
        for (int p = 0; p < 4; p++) {
            int idx = p * 256 + tid;
            int row = idx >> 3;
            int c8  = (idx & 7) * 8;     // halves
            int grow = bm0 + row; if (grow > M - 1) grow = M - 1;
            cp_async16(as + (uint32_t)(row * PH + c8) * 2u, A + grow * K + k0 + c8);
        }
        #pragma unroll
        for (int p = 0; p < 2; p++) {
            int idx = p * 256 + tid;
            int row = idx >> 3;
            int c8  = (idx & 7) * 8;
            int gn  = bn0 + row; if (gn > N - 1) gn = N - 1;
            cp_async16(bs + (uint32_t)(row * PH + c8) * 2u, WT + gn * K + k0 + c8);
        }
        cp_commit();
    };

    #pragma unroll
    for (int c0 = 0; c0 < 3; c0++)
        if (c0 < nchunks) load_chunk(c0, c0);

    for (int c = 0; c < nchunks; c++) {
        int s = c & 3;
        cp_wait<2>();          // exactly 3 groups pending at every iteration -> chunk c landed
        __syncthreads();
        if (c + 3 < nchunks) load_chunk(c + 3, (c + 3) & 3);
        else cp_commit();      // EMPTY group: keeps pending-count invariant in the tail (fixes R9 race)

        const uint32_t* As = reinterpret_cast<const uint32_t*>(smem + s * STAGE_BYTES);
        const uint32_t* Bs = reinterpret_cast<const uint32_t*>(smem + s * STAGE_BYTES + AS_BYTES);

        #pragma unroll
        for (int ks = 0; ks < 4; ks++) {
            int kw = ks * 8;   // b32 words; k-halves = ks*16
            uint32_t a[2][4];
            #pragma unroll
            for (int im = 0; im < 2; im++) {
                int r = m0w + im * 16;
                a[im][0] = As[(r + g    ) * (PH/2) + kw + t    ];
                a[im][1] = As[(r + 8 + g) * (PH/2) + kw + t    ];
                a[im][2] = As[(r + g    ) * (PH/2) + kw + t + 4];
                a[im][3] = As[(r + 8 + g) * (PH/2) + kw + t + 4];
            }
            #pragma unroll
            for (int in = 0; in < 4; in++) {
                int n = n0w + in * 8 + g;
                uint32_t b0 = Bs[n * (PH/2) + kw + t    ];
                uint32_t b1 = Bs[n * (PH/2) + kw + t + 4];
                mma_f16(acc[0][in], a[0][0], a[0][1], a[0][2], a[0][3], b0, b1);
                mma_f16(acc[1][in], a[1][0], a[1][1], a[1][2], a[1][3], b0, b1);
            }
        }
    }

    // ---- epilogue ----
    #pragma unroll
    for (int im = 0; im < 2; im++) {
        int r0 = bm0 + m0w + im * 16 + g;
        int r1 = r0 + 8;
        #pragma unroll
        for (int in = 0; in < 4; in++) {
            int c = bn0 + n0w + in * 8 + 2 * t;
            if (c >= N) continue;   // N even -> c+1 < N too
            float bx = bias[c], by = bias[c + 1];

            float v0 = acc[im][in].x + bx;
            float v1 = acc[im][in].y + by;
            float v2 = acc[im][in].z + bx;
            float v3 = acc[im][in].w + by;
            if (act == ACT_GELU) {
                v0 = 0.5f * v0 * (1.0f + erff(v0 * 0.70710678118654752f));
                v1 = 0.5f * v1 * (1.0f + erff(v1 * 0.70710678118654752f));
                v2 = 0.5f * v2 * (1.0f + erff(v2 * 0.70710678118654752f));
                v3 = 0.5f * v3 * (1.0f + erff(v3 * 0.70710678118654752f));
            }
            if (r0 < M) {
                int oi = r0 * N + c;
                if (res1) { v0 += res1[oi]; v1 += res1[oi + 1]; }
                if (res2) { v0 += res2[oi]; v1 += res2[oi + 1]; }
                if (out_half)
                    *reinterpret_cast<__half2*>((__half*)Cout + oi) = __floats2half2_rn(v0, v1);
                else
                    *reinterpret_cast<float2*>((float*)Cout + oi) = make_float2(v0, v1);
            }
            if (r1 < M) {
                int oi = r1 * N + c;
                if (res1) { v2 += res1[oi]; v3 += res1[oi + 1]; }
                if (res2) { v2 += res2[oi]; v3 += res2[oi + 1]; }
                if (out_half)
                    *reinterpret_cast<__half2*>((__half*)Cout + oi) = __floats2half2_rn(v2, v3);
                else
                    *reinterpret_cast<float2*>((float*)Cout + oi) = make_float2(v2, v3);
            }
        }
    }
}

// ---------------- deformable sampling + fused softmax (fp16 values, fp16 out) ----------------
__global__ void sample_kernel(const float* __restrict__ refp)
{
    int row0 = blockIdx.x * 2;
    int t    = threadIdx.x;

    __shared__ float s_off[2][NOFF];
    __shared__ float s_aw [2][NAW];
    __shared__ float s_ref[2][LEV * 2];

    #pragma unroll
    for (int r = 0; r < 2; r++) {
        int row = row0 + r;
        if (t < NOFF)   s_off[r][t] = g_ol[row * NOL + t];
        if (t < NAW)    s_aw [r][t] = g_ol[row * NOL + NOFF + t];
        if (t < LEV*2)  s_ref[r][t] = refp[row * LEV * 2 + t];
    }
    __syncthreads();

    if (t < 16) {
        int r = t >> 3, h = t & 7;
        float* v = &s_aw[r][h * (LEV * PTS)];
        float mx = -1e30f;
        float e[LEV * PTS];
        #pragma unroll
        for (int i = 0; i < LEV * PTS; i++) mx = fmaxf(mx, v[i]);
        float sum = 0.f;
        #pragma unroll
        for (int i = 0; i < LEV * PTS; i++) { e[i] = __expf(v[i] - mx); sum += e[i]; }
        float inv = 1.0f / sum;
        #pragma unroll
        for (int i = 0; i < LEV * PTS; i++) v[i] = e[i] * inv;
    }
    __syncthreads();

    int r = t >> 7;
    int h = (t >> 4) & 7;
    int d = (t & 15) * 2;
    int row = row0 + r;
    int b   = row / NQ;

    const int Hl_[LEV] = {60, 30, 15};
    const int Wl_[LEV] = {80, 40, 20};
    const int St_[LEV] = {0, 4800, 6000};

    float2 acc = make_float2(0.f, 0.f);
    #pragma unroll
    for (int l = 0; l < LEV; l++) {
        int Hl = Hl_[l], Wl = Wl_[l];
        const __half* vbase = g_v + (b * NV + St_[l]) * CDIM + h * DH + d;
        float rx = s_ref[r][l * 2 + 0];
        float ry = s_ref[r][l * 2 + 1];
        #pragma unroll
        for (int p = 0; p < PTS; p++) {
            int oi = ((h * LEV + l) * PTS + p) * 2;
            float gx = rx * (float)Wl + s_off[r][oi + 0] - 0.5f;
            float gy = ry * (float)Hl + s_off[r][oi + 1] - 0.5f;
            float w  = s_aw[r][(h * LEV + l) * PTS + p];

            float x0f = floorf(gx), y0f = floorf(gy);
            int x0 = (int)x0f, y0 = (int)y0f;
            float wx = gx - x0f, wy = gy - y0f;

            float2 sv = make_float2(0.f, 0.f);
            #pragma unroll
            for (int dy = 0; dy < 2; dy++) {
                int yi = y0 + dy;
                if (yi < 0 || yi >= Hl) continue;
                float wyv = dy ? wy : (1.f - wy);
                #pragma unroll
                for (int dx = 0; dx < 2; dx++) {
                    int xi = x0 + dx;
                    if (xi < 0 || xi >= Wl) continue;
                    float wxv = dx ? wx : (1.f - wx);
                    __half2 hv = *reinterpret_cast<const __half2*>(vbase + (yi * Wl + xi) * CDIM);
                    float2 vv = __half22float2(hv);
                    float cw = wyv * wxv;
                    sv.x = fmaf(cw, vv.x, sv.x);
                    sv.y = fmaf(cw, vv.y, sv.y);
                }
            }
            acc.x = fmaf(w, sv.x, acc.x);
            acc.y = fmaf(w, sv.y, acc.y);
        }
    }
    *reinterpret_cast<__half2*>(&g_attn_h[row * CDIM + h * DH + d]) = __floats2half2_rn(acc.x, acc.y);
}

// ---------------- launch ----------------
extern "C" void kernel_launch(void* const* d_in, const int* in_sizes, int n_in,
                              void* d_out, int out_size)
{
    const float* query = (const float*)d_in[0];
    const float* value = (const float*)d_in[1];
    const float* qpos  = (const float*)d_in[2];
    const float* refp  = (const float*)d_in[3];
    const float* g1  = (const float*)d_in[6];
    const float* b1  = (const float*)d_in[7];
    const float* Wo  = (const float*)d_in[8];
    const float* bo  = (const float*)d_in[9];
    const float* Wa  = (const float*)d_in[10];
    const float* ba  = (const float*)d_in[11];
    const float* Wv  = (const float*)d_in[12];
    const float* bv  = (const float*)d_in[13];
    const float* Wp  = (const float*)d_in[14];
    const float* bp  = (const float*)d_in[15];
    const float* g2  = (const float*)d_in[16];
    const float* b2  = (const float*)d_in[17];
    const float* Wf1 = (const float*)d_in[18];
    const float* bf1 = (const float*)d_in[19];
    const float* Wf2 = (const float*)d_in[20];
    const float* bf2 = (const float*)d_in[21];
    float* out = (float*)d_out;

    float *qn, *olbuf, *q, *bcat;
    __half *qa_h, *val_h, *vproj, *attn_h, *q2_h, *h_h;
    __half *wcatT, *wvT, *wpT, *wf1T, *wf2T;
    cudaGetSymbolAddress((void**)&qn,     g_qn);
    cudaGetSymbolAddress((void**)&qa_h,   g_qa_h);
    cudaGetSymbolAddress((void**)&olbuf,  g_ol);
    cudaGetSymbolAddress((void**)&val_h,  g_val_h);
    cudaGetSymbolAddress((void**)&vproj,  g_v);
    cudaGetSymbolAddress((void**)&attn_h, g_attn_h);
    cudaGetSymbolAddress((void**)&q,      g_q);
    cudaGetSymbolAddress((void**)&q2_h,   g_q2_h);
    cudaGetSymbolAddress((void**)&h_h,    g_h_h);
    cudaGetSymbolAddress((void**)&wcatT,  g_wcatT);
    cudaGetSymbolAddress((void**)&wvT,    g_wvT);
    cudaGetSymbolAddress((void**)&wpT,    g_wpT);
    cudaGetSymbolAddress((void**)&wf1T,   g_wf1T);
    cudaGetSymbolAddress((void**)&wf2T,   g_wf2T);
    cudaGetSymbolAddress((void**)&bcat,   g_bcat);

    cudaFuncSetAttribute(gemm_f16_kernel, cudaFuncAttributeMaxDynamicSharedMemorySize, SMEM_TOT);

    dim3 tb(32, 8);
    // 0) weight prep (convert + transpose to [N][K] fp16)
    transpose_h_kernel<<<dim3(NOFF/32, CDIM/32), tb>>>(Wo, wcatT, CDIM, NOFF);
    transpose_h_kernel<<<dim3(NAW/32,  CDIM/32), tb>>>(Wa, wcatT + NOFF*CDIM, CDIM, NAW);
    transpose_h_kernel<<<dim3(CDIM/32, CDIM/32), tb>>>(Wv, wvT,  CDIM, CDIM);
    transpose_h_kernel<<<dim3(CDIM/32, CDIM/32), tb>>>(Wp, wpT,  CDIM, CDIM);
    transpose_h_kernel<<<dim3(HID/32,  CDIM/32), tb>>>(Wf1, wf1T, CDIM, HID);
    transpose_h_kernel<<<dim3(CDIM/32, HID/32),  tb>>>(Wf2, wf2T, HID, CDIM);
    bias_concat_kernel<<<1, NOL>>>(bo, ba);
    f2h_kernel<<<(RV*CDIM/4 + 255)/256, 256>>>(value, val_h, RV*CDIM);

    // 1) LN1: qn fp32 (residual), qa_h fp16 = LN + pos
    ln_kernel<<<RQ, 256>>>(query, g1, b1, qpos, qn, qa_h);

    // 2) fused offsets+logits: qa @ Wcat   [RQ x 288]
    gemm_f16_kernel<<<dim3((NOL + 63)/64, RQ/128), 256, SMEM_TOT>>>(
        qa_h, wcatT, bcat, nullptr, nullptr, olbuf, RQ, NOL, CDIM, ACT_NONE, 0);

    // 3) value projection -> fp16
    gemm_f16_kernel<<<dim3(4, (RV + 127)/128), 256, SMEM_TOT>>>(
        val_h, wvT, bv, nullptr, nullptr, vproj, RV, CDIM, CDIM, ACT_NONE, 1);

    // 4) fused softmax + sampling -> attn_h (fp16)
    sample_kernel<<<RQ/2, 256>>>(refp);

    // 5) output proj + both residuals: q = attn @ Wp + bp + qn + query (fp32)
    gemm_f16_kernel<<<dim3(4, RQ/128), 256, SMEM_TOT>>>(
        attn_h, wpT, bp, qn, query, q, RQ, CDIM, CDIM, ACT_NONE, 0);

    // 6) LN2 -> q2_h fp16
    ln_kernel<<<RQ, 256>>>(q, g2, b2, nullptr, nullptr, q2_h);

    // 7) FFN up + GELU -> h_h fp16  [RQ x 1024]
    gemm_f16_kernel<<<dim3(16, RQ/128), 256, SMEM_TOT>>>(
        q2_h, wf1T, bf1, nullptr, nullptr, h_h, RQ, HID, CDIM, ACT_GELU, 1);

    // 8) FFN down + residual: out = h @ Wf2 + bf2 + q (fp32)
    gemm_f16_kernel<<<dim3(4, RQ/128), 256, SMEM_TOT>>>(
        h_h, wf2T, bf2, q, nullptr, out, RQ, CDIM, HID, ACT_NONE, 0);
}

// round 12
// speedup vs baseline: 3.4278x; 1.0334x over previous
#include <cuda_runtime.h>
#include <cuda_fp16.h>
#include <cstdint>
#include <math.h>

// ---------------- problem constants (fixed shapes) ----------------
#define BATCH 2
#define NQ    8192
#define RQ    (BATCH*NQ)     // 16384 query rows
#define CDIM  256
#define HEADS 8
#define DH    32
#define LEV   3
#define PTS   4
#define NV    6300           // 4800+1200+300
#define RV    (BATCH*NV)     // 12600 value rows
#define HID   1024           // MLP*C
#define NOFF  (HEADS*LEV*PTS*2)  // 192
#define NAW   (HEADS*LEV*PTS)    // 96
#define NOL   (NOFF+NAW)         // 288

// ---------------- scratch (static device memory; no allocs allowed) ----------------
__device__ float  g_qn   [RQ*CDIM];
__device__ __half g_qa_h [RQ*CDIM];
__device__ float  g_ol   [RQ*NOL];
__device__ __half g_val_h[RV*CDIM];
__device__ __half g_v    [RV*CDIM];
__device__ __half g_attn_h[RQ*CDIM];
__device__ float  g_q    [RQ*CDIM];
__device__ __half g_q2_h [RQ*CDIM];
__device__ __half g_h_h  [RQ*HID];
__device__ __half g_wcatT[NOL*CDIM];
__device__ __half g_wvT  [CDIM*CDIM];
__device__ __half g_wpT  [CDIM*CDIM];
__device__ __half g_wf1T [HID*CDIM];
__device__ __half g_wf2T [CDIM*HID];
__device__ float  g_bcat [NOL];

// ---------------- combined prep: all 6 weight transposes (+bias concat), 1 launch ----------------
// 32x32 tiles, flat block id. Tile counts: Wo 48, Wa 24, Wv 64, Wp 64, Wf1 256, Wf2 256 -> 712.
__global__ void prep_kernel(const float* __restrict__ Wo, const float* __restrict__ Wa,
                            const float* __restrict__ Wv, const float* __restrict__ Wp,
                            const float* __restrict__ Wf1, const float* __restrict__ Wf2,
                            const float* __restrict__ bo, const float* __restrict__ ba)
{
    int bid = blockIdx.x;
    int tx = threadIdx.x, ty = threadIdx.y;     // 32 x 8
    int tid = ty * 32 + tx;

    int flat = bid * 256 + tid;
    if (flat < NOL) g_bcat[flat] = (flat < NOFF) ? bo[flat] : ba[flat - NOFF];

    const float* src; __half* dst; int K, N, t0;
    if (bid < 48)       { src = Wo;  dst = g_wcatT;               K = CDIM; N = NOFF; t0 = 0;   }
    else if (bid < 72)  { src = Wa;  dst = g_wcatT + NOFF*CDIM;   K = CDIM; N = NAW;  t0 = 48;  }
    else if (bid < 136) { src = Wv;  dst = g_wvT;                 K = CDIM; N = CDIM; t0 = 72;  }
    else if (bid < 200) { src = Wp;  dst = g_wpT;                 K = CDIM; N = CDIM; t0 = 136; }
    else if (bid < 456) { src = Wf1; dst = g_wf1T;                K = CDIM; N = HID;  t0 = 200; }
    else                { src = Wf2; dst = g_wf2T;                K = HID;  N = CDIM; t0 = 456; }

    int t  = bid - t0;
    int nx = N / 32;
    int n0 = (t % nx) * 32, k0 = (t / nx) * 32;

    __shared__ float tile[32][33];
    #pragma unroll
    for (int i = ty; i < 32; i += 8)
        tile[i][tx] = src[(k0 + i) * N + n0 + tx];
    __syncthreads();
    #pragma unroll
    for (int i = ty; i < 32; i += 8)
        dst[(n0 + i) * K + k0 + tx] = __float2half_rn(tile[tx][i]);
}

__global__ void f2h_kernel(const float* __restrict__ src, __half* __restrict__ dst, int n)
{
    int i = (blockIdx.x * 256 + threadIdx.x) * 4;
    if (i < n) {
        float4 v = *reinterpret_cast<const float4*>(src + i);
        *reinterpret_cast<__half2*>(dst + i)     = __floats2half2_rn(v.x, v.y);
        *reinterpret_cast<__half2*>(dst + i + 2) = __floats2half2_rn(v.z, v.w);
    }
}

// ---------------- LayerNorm over C=256 (one block per row, 256 threads) ----------------
__global__ void ln_kernel(const float* __restrict__ x,
                          const float* __restrict__ g, const float* __restrict__ b,
                          const float* __restrict__ pos,
                          float* __restrict__ outn, __half* __restrict__ outh)
{
    int row = blockIdx.x;
    int t = threadIdx.x;
    float v = x[row*CDIM + t];

    __shared__ float sred[8];
    __shared__ float s_mean, s_var;

    float s = v;
    #pragma unroll
    for (int o = 16; o > 0; o >>= 1) s += __shfl_xor_sync(0xffffffffu, s, o);
    if ((t & 31) == 0) sred[t >> 5] = s;
    __syncthreads();
    if (t == 0) {
        float tot = 0.f;
        #pragma unroll
        for (int i = 0; i < 8; i++) tot += sred[i];
        s_mean = tot * (1.0f / CDIM);
    }
    __syncthreads();
    float mean = s_mean;

    float d = v - mean;
    float s2 = d * d;
    #pragma unroll
    for (int o = 16; o > 0; o >>= 1) s2 += __shfl_xor_sync(0xffffffffu, s2, o);
    __syncthreads();
    if ((t & 31) == 0) sred[t >> 5] = s2;
    __syncthreads();
    if (t == 0) {
        float tot = 0.f;
        #pragma unroll
        for (int i = 0; i < 8; i++) tot += sred[i];
        s_var = tot * (1.0f / CDIM);
    }
    __syncthreads();

    float y = d * rsqrtf(s_var + 1e-5f) * g[t] + b[t];
    if (outn) outn[row*CDIM + t] = y;
    float ya = pos ? (y + pos[row*CDIM + t]) : y;
    outh[row*CDIM + t] = __float2half_rn(ya);
}

// ---------------- fp16 tensor-core GEMM, BM=128 BN=128 BK=64, 3-stage cp.async ----------------
// 256 threads = 8 warps (2m x 4n); warp tile 64x32 = 4x4 mma m16n8k16, fp32 accum.
#define ACT_NONE 0
#define ACT_GELU 1
#define PH 72    // smem row pitch in halves (36 b32 words -> 4g+t bank pattern, conflict-free)

#define A_BYTES (128*PH*2)           // 18432
#define B_BYTES (128*PH*2)           // 18432
#define STAGE_BYTES (A_BYTES + B_BYTES)   // 36864
#define SMEM_TOT (3*STAGE_BYTES)          // 110592

__device__ __forceinline__ uint32_t smem_u32(const void* p) {
    uint32_t a;
    asm("{ .reg .u64 t; cvta.to.shared.u64 t, %1; cvt.u32.u64 %0, t; }" : "=r"(a) : "l"(p));
    return a;
}
__device__ __forceinline__ void cp_async16(uint32_t dst, const void* src) {
    asm volatile("cp.async.cg.shared.global [%0], [%1], 16;" :: "r"(dst), "l"(src));
}
__device__ __forceinline__ void cp_commit() {
    asm volatile("cp.async.commit_group;" ::: "memory");
}
template<int N>
__device__ __forceinline__ void cp_wait() {
    asm volatile("cp.async.wait_group %0;" :: "n"(N) : "memory");
}

__device__ __forceinline__ void mma_f16(float4& d,
                                        uint32_t a0, uint32_t a1, uint32_t a2, uint32_t a3,
                                        uint32_t b0, uint32_t b1) {
    asm volatile(
        "mma.sync.aligned.m16n8k16.row.col.f32.f16.f16.f32 "
        "{%0,%1,%2,%3}, {%4,%5,%6,%7}, {%8,%9}, {%0,%1,%2,%3};\n"
        : "+f"(d.x), "+f"(d.y), "+f"(d.z), "+f"(d.w)
        : "r"(a0), "r"(a1), "r"(a2), "r"(a3), "r"(b0), "r"(b1));
}

__global__ __launch_bounds__(256)
void gemm_f16_kernel(const __half* __restrict__ A, const __half* __restrict__ WT,
                     const float* __restrict__ bias,
                     const float* __restrict__ res1, const float* __restrict__ res2,
                     void* __restrict__ Cout,
                     int M, int N, int K, int act, int out_half)
{
    extern __shared__ char smem[];
    uint32_t smem_base = smem_u32(smem);

    int tid  = threadIdx.x;
    int lane = tid & 31;
    int warp = tid >> 5;
    int g = lane >> 2;      // 0..7
    int t = lane & 3;       // 0..3
    int wm = warp & 1;      // 0..1  (m groups of 64)
    int wn = warp >> 1;     // 0..3  (n groups of 32)
    int m0w = wm * 64;
    int n0w = wn * 32;
    int bm0 = blockIdx.y * 128;
    int bn0 = blockIdx.x * 128;

    float4 acc[4][4];
    #pragma unroll
    for (int i = 0; i < 4; i++)
        #pragma unroll
        for (int j = 0; j < 4; j++)
            acc[i][j] = make_float4(0.f, 0.f, 0.f, 0.f);

    const int nchunks = K >> 6;     // BK=64

    // ---- stage loader: A 128x64h + B 128x64h, one commit group ----
    auto load_chunk = [&](int c, int s) {
        int k0 = c << 6;
        uint32_t as = smem_base + (uint32_t)(s * STAGE_BYTES);
        uint32_t bs = as + A_BYTES;
        #pragma unroll
        for (int p = 0; p < 4; p++) {
            int idx = p * 256 + tid;
            int row = idx >> 3;
            int c8  = (idx & 7) * 8;
            int grow = bm0 + row; if (grow > M - 1) grow = M - 1;
            cp_async16(as + (uint32_t)(row * PH + c8) * 2u, A + grow * K + k0 + c8);
        }
        #pragma unroll
        for (int p = 0; p < 4; p++) {
            int idx = p * 256 + tid;
            int row = idx >> 3;
            int c8  = (idx & 7) * 8;
            int gn  = bn0 + row; if (gn > N - 1) gn = N - 1;
            cp_async16(bs + (uint32_t)(row * PH + c8) * 2u, WT + gn * K + k0 + c8);
        }
        cp_commit();
    };

    // prologue: 2 chunks in flight (3 stages)
    if (0 < nchunks) load_chunk(0, 0);
    if (1 < nchunks) load_chunk(1, 1);

    int s = 0;
    for (int c = 0; c < nchunks; c++) {
        cp_wait<1>();          // pending <= 1 => chunk c landed
        __syncthreads();
        if (c + 2 < nchunks) {
            int s2 = s + 2; if (s2 >= 3) s2 -= 3;
            load_chunk(c + 2, s2);
        } else {
            cp_commit();       // empty group keeps the pending-count invariant in the tail
        }

        const uint32_t* As = reinterpret_cast<const uint32_t*>(smem + s * STAGE_BYTES);
        const uint32_t* Bs = reinterpret_cast<const uint32_t*>(smem + s * STAGE_BYTES + A_BYTES);

        #pragma unroll
        for (int ks = 0; ks < 4; ks++) {
            int kw = ks * 8;   // b32 word offset (16 halves per k-step)
            uint32_t a[4][4];
            #pragma unroll
            for (int im = 0; im < 4; im++) {
                int r = m0w + im * 16;
                a[im][0] = As[(r + g    ) * (PH/2) + kw + t    ];
                a[im][1] = As[(r + 8 + g) * (PH/2) + kw + t    ];
                a[im][2] = As[(r + g    ) * (PH/2) + kw + t + 4];
                a[im][3] = As[(r + 8 + g) * (PH/2) + kw + t + 4];
            }
            #pragma unroll
            for (int in = 0; in < 4; in++) {
                int n = n0w + in * 8 + g;
                uint32_t b0 = Bs[n * (PH/2) + kw + t    ];
                uint32_t b1 = Bs[n * (PH/2) + kw + t + 4];
                #pragma unroll
                for (int im = 0; im < 4; im++)
                    mma_f16(acc[im][in], a[im][0], a[im][1], a[im][2], a[im][3], b0, b1);
            }
        }
        if (++s >= 3) s = 0;
    }

    // ---- epilogue ----
    #pragma unroll
    for (int im = 0; im < 4; im++) {
        int r0 = bm0 + m0w + im * 16 + g;
        int r1 = r0 + 8;
        #pragma unroll
        for (int in = 0; in < 4; in++) {
            int c = bn0 + n0w + in * 8 + 2 * t;
            if (c >= N) continue;   // N even -> c+1 < N too
            float bx = bias[c], by = bias[c + 1];

            float v0 = acc[im][in].x + bx;
            float v1 = acc[im][in].y + by;
            float v2 = acc[im][in].z + bx;
            float v3 = acc[im][in].w + by;
            if (act == ACT_GELU) {
                v0 = 0.5f * v0 * (1.0f + erff(v0 * 0.70710678118654752f));
                v1 = 0.5f * v1 * (1.0f + erff(v1 * 0.70710678118654752f));
                v2 = 0.5f * v2 * (1.0f + erff(v2 * 0.70710678118654752f));
                v3 = 0.5f * v3 * (1.0f + erff(v3 * 0.70710678118654752f));
            }
            if (r0 < M) {
                int oi = r0 * N + c;
                if (res1) { v0 += res1[oi]; v1 += res1[oi + 1]; }
                if (res2) { v0 += res2[oi]; v1 += res2[oi + 1]; }
                if (out_half)
                    *reinterpret_cast<__half2*>((__half*)Cout + oi) = __floats2half2_rn(v0, v1);
                else
                    *reinterpret_cast<float2*>((float*)Cout + oi) = make_float2(v0, v1);
            }
            if (r1 < M) {
                int oi = r1 * N + c;
                if (res1) { v2 += res1[oi]; v3 += res1[oi + 1]; }
                if (res2) { v2 += res2[oi]; v3 += res2[oi + 1]; }
                if (out_half)
                    *reinterpret_cast<__half2*>((__half*)Cout + oi) = __floats2half2_rn(v2, v3);
                else
                    *reinterpret_cast<float2*>((float*)Cout + oi) = make_float2(v2, v3);
            }
        }
    }
}

// ---------------- deformable sampling + fused softmax (fp16 values, fp16 out) ----------------
__global__ void sample_kernel(const float* __restrict__ refp)
{
    int row0 = blockIdx.x * 2;
    int t    = threadIdx.x;

    __shared__ float s_off[2][NOFF];
    __shared__ float s_aw [2][NAW];
    __shared__ float s_ref[2][LEV * 2];

    #pragma unroll
    for (int r = 0; r < 2; r++) {
        int row = row0 + r;
        if (t < NOFF)   s_off[r][t] = g_ol[row * NOL + t];
        if (t < NAW)    s_aw [r][t] = g_ol[row * NOL + NOFF + t];
        if (t < LEV*2)  s_ref[r][t] = refp[row * LEV * 2 + t];
    }
    __syncthreads();

    if (t < 16) {
        int r = t >> 3, h = t & 7;
        float* v = &s_aw[r][h * (LEV * PTS)];
        float mx = -1e30f;
        float e[LEV * PTS];
        #pragma unroll
        for (int i = 0; i < LEV * PTS; i++) mx = fmaxf(mx, v[i]);
        float sum = 0.f;
        #pragma unroll
        for (int i = 0; i < LEV * PTS; i++) { e[i] = __expf(v[i] - mx); sum += e[i]; }
        float inv = 1.0f / sum;
        #pragma unroll
        for (int i = 0; i < LEV * PTS; i++) v[i] = e[i] * inv;
    }
    __syncthreads();

    int r = t >> 7;
    int h = (t >> 4) & 7;
    int d = (t & 15) * 2;
    int row = row0 + r;
    int b   = row / NQ;

    const int Hl_[LEV] = {60, 30, 15};
    const int Wl_[LEV] = {80, 40, 20};
    const int St_[LEV] = {0, 4800, 6000};

    float2 acc = make_float2(0.f, 0.f);
    #pragma unroll
    for (int l = 0; l < LEV; l++) {
        int Hl = Hl_[l], Wl = Wl_[l];
        const __half* vbase = g_v + (b * NV + St_[l]) * CDIM + h * DH + d;
        float rx = s_ref[r][l * 2 + 0];
        float ry = s_ref[r][l * 2 + 1];
        #pragma unroll
        for (int p = 0; p < PTS; p++) {
            int oi = ((h * LEV + l) * PTS + p) * 2;
            float gx = rx * (float)Wl + s_off[r][oi + 0] - 0.5f;
            float gy = ry * (float)Hl + s_off[r][oi + 1] - 0.5f;
            float w  = s_aw[r][(h * LEV + l) * PTS + p];

            float x0f = floorf(gx), y0f = floorf(gy);
            int x0 = (int)x0f, y0 = (int)y0f;
            float wx = gx - x0f, wy = gy - y0f;

            float2 sv = make_float2(0.f, 0.f);
            #pragma unroll
            for (int dy = 0; dy < 2; dy++) {
                int yi = y0 + dy;
                if (yi < 0 || yi >= Hl) continue;
                float wyv = dy ? wy : (1.f - wy);
                #pragma unroll
                for (int dx = 0; dx < 2; dx++) {
                    int xi = x0 + dx;
                    if (xi < 0 || xi >= Wl) continue;
                    float wxv = dx ? wx : (1.f - wx);
                    __half2 hv = *reinterpret_cast<const __half2*>(vbase + (yi * Wl + xi) * CDIM);
                    float2 vv = __half22float2(hv);
                    float cw = wyv * wxv;
                    sv.x = fmaf(cw, vv.x, sv.x);
                    sv.y = fmaf(cw, vv.y, sv.y);
                }
            }
            acc.x = fmaf(w, sv.x, acc.x);
            acc.y = fmaf(w, sv.y, acc.y);
        }
    }
    *reinterpret_cast<__half2*>(&g_attn_h[row * CDIM + h * DH + d]) = __floats2half2_rn(acc.x, acc.y);
}

// ---------------- launch ----------------
extern "C" void kernel_launch(void* const* d_in, const int* in_sizes, int n_in,
                              void* d_out, int out_size)
{
    const float* query = (const float*)d_in[0];
    const float* value = (const float*)d_in[1];
    const float* qpos  = (const float*)d_in[2];
    const float* refp  = (const float*)d_in[3];
    const float* g1  = (const float*)d_in[6];
    const float* b1  = (const float*)d_in[7];
    const float* Wo  = (const float*)d_in[8];
    const float* bo  = (const float*)d_in[9];
    const float* Wa  = (const float*)d_in[10];
    const float* ba  = (const float*)d_in[11];
    const float* Wv  = (const float*)d_in[12];
    const float* bv  = (const float*)d_in[13];
    const float* Wp  = (const float*)d_in[14];
    const float* bp  = (const float*)d_in[15];
    const float* g2  = (const float*)d_in[16];
    const float* b2  = (const float*)d_in[17];
    const float* Wf1 = (const float*)d_in[18];
    const float* bf1 = (const float*)d_in[19];
    const float* Wf2 = (const float*)d_in[20];
    const float* bf2 = (const float*)d_in[21];
    float* out = (float*)d_out;

    float *qn, *olbuf, *q, *bcat;
    __half *qa_h, *val_h, *vproj, *attn_h, *q2_h, *h_h;
    __half *wcatT, *wvT, *wpT, *wf1T, *wf2T;
    cudaGetSymbolAddress((void**)&qn,     g_qn);
    cudaGetSymbolAddress((void**)&qa_h,   g_qa_h);
    cudaGetSymbolAddress((void**)&olbuf,  g_ol);
    cudaGetSymbolAddress((void**)&val_h,  g_val_h);
    cudaGetSymbolAddress((void**)&vproj,  g_v);
    cudaGetSymbolAddress((void**)&attn_h, g_attn_h);
    cudaGetSymbolAddress((void**)&q,      g_q);
    cudaGetSymbolAddress((void**)&q2_h,   g_q2_h);
    cudaGetSymbolAddress((void**)&h_h,    g_h_h);
    cudaGetSymbolAddress((void**)&wcatT,  g_wcatT);
    cudaGetSymbolAddress((void**)&wvT,    g_wvT);
    cudaGetSymbolAddress((void**)&wpT,    g_wpT);
    cudaGetSymbolAddress((void**)&wf1T,   g_wf1T);
    cudaGetSymbolAddress((void**)&wf2T,   g_wf2T);
    cudaGetSymbolAddress((void**)&bcat,   g_bcat);

    cudaFuncSetAttribute(gemm_f16_kernel, cudaFuncAttributeMaxDynamicSharedMemorySize, SMEM_TOT);

    // 0) prep: all weight transposes + bias concat (1 launch) + value f2h (1 launch)
    prep_kernel<<<712, dim3(32, 8)>>>(Wo, Wa, Wv, Wp, Wf1, Wf2, bo, ba);
    f2h_kernel<<<(RV*CDIM/4 + 255)/256, 256>>>(value, val_h, RV*CDIM);

    // 1) LN1: qn fp32 (residual), qa_h fp16 = LN + pos
    ln_kernel<<<RQ, 256>>>(query, g1, b1, qpos, qn, qa_h);

    // 2) fused offsets+logits: qa @ Wcat   [RQ x 288]
    gemm_f16_kernel<<<dim3(3, RQ/128), 256, SMEM_TOT>>>(
        qa_h, wcatT, bcat, nullptr, nullptr, olbuf, RQ, NOL, CDIM, ACT_NONE, 0);

    // 3) value projection -> fp16   [RV x 256]
    gemm_f16_kernel<<<dim3(2, (RV + 127)/128), 256, SMEM_TOT>>>(
        val_h, wvT, bv, nullptr, nullptr, vproj, RV, CDIM, CDIM, ACT_NONE, 1);

    // 4) fused softmax + sampling -> attn_h (fp16)
    sample_kernel<<<RQ/2, 256>>>(refp);

    // 5) output proj + both residuals: q = attn @ Wp + bp + qn + query (fp32)
    gemm_f16_kernel<<<dim3(2, RQ/128), 256, SMEM_TOT>>>(
        attn_h, wpT, bp, qn, query, q, RQ, CDIM, CDIM, ACT_NONE, 0);

    // 6) LN2 -> q2_h fp16
    ln_kernel<<<RQ, 256>>>(q, g2, b2, nullptr, nullptr, q2_h);

    // 7) FFN up + GELU -> h_h fp16  [RQ x 1024]
    gemm_f16_kernel<<<dim3(8, RQ/128), 256, SMEM_TOT>>>(
        q2_h, wf1T, bf1, nullptr, nullptr, h_h, RQ, HID, CDIM, ACT_GELU, 1);

    // 8) FFN down + residual: out = h @ Wf2 + bf2 + q (fp32)
    gemm_f16_kernel<<<dim3(2, RQ/128), 256, SMEM_TOT>>>(
        h_h, wf2T, bf2, q, nullptr, out, RQ, CDIM, HID, ACT_NONE, 0);
}

// round 13
// speedup vs baseline: 3.4580x; 1.0088x over previous
#include <cuda_runtime.h>
#include <cuda_fp16.h>
#include <cstdint>
#include <math.h>

// ---------------- problem constants (fixed shapes) ----------------
#define BATCH 2
#define NQ    8192
#define RQ    (BATCH*NQ)     // 16384 query rows
#define CDIM  256
#define HEADS 8
#define DH    32
#define LEV   3
#define PTS   4
#define NV    6300           // 4800+1200+300
#define RV    (BATCH*NV)     // 12600 value rows
#define HID   1024           // MLP*C
#define NOFF  (HEADS*LEV*PTS*2)  // 192
#define NAW   (HEADS*LEV*PTS)    // 96
#define NOL   (NOFF+NAW)         // 288

// ---------------- scratch (static device memory; no allocs allowed) ----------------
__device__ float  g_qn   [RQ*CDIM];
__device__ __half g_qa_h [RQ*CDIM];
__device__ float  g_ol   [RQ*NOL];
__device__ __half g_val_h[RV*CDIM];
__device__ __half g_v    [RV*CDIM];
__device__ __half g_attn_h[RQ*CDIM];
__device__ float  g_q    [RQ*CDIM];
__device__ __half g_q2_h [RQ*CDIM];
__device__ __half g_h_h  [RQ*HID];
__device__ __half g_wcatT[NOL*CDIM];
__device__ __half g_wvT  [CDIM*CDIM];
__device__ __half g_wpT  [CDIM*CDIM];
__device__ __half g_wf1T [HID*CDIM];
__device__ __half g_wf2T [CDIM*HID];
__device__ float  g_bcat [NOL];

// ---------------- combined prep: all 6 weight transposes (+bias concat), 1 launch ----------------
__global__ void prep_kernel(const float* __restrict__ Wo, const float* __restrict__ Wa,
                            const float* __restrict__ Wv, const float* __restrict__ Wp,
                            const float* __restrict__ Wf1, const float* __restrict__ Wf2,
                            const float* __restrict__ bo, const float* __restrict__ ba)
{
    int bid = blockIdx.x;
    int tx = threadIdx.x, ty = threadIdx.y;     // 32 x 8
    int tid = ty * 32 + tx;

    int flat = bid * 256 + tid;
    if (flat < NOL) g_bcat[flat] = (flat < NOFF) ? bo[flat] : ba[flat - NOFF];

    const float* src; __half* dst; int K, N, t0;
    if (bid < 48)       { src = Wo;  dst = g_wcatT;               K = CDIM; N = NOFF; t0 = 0;   }
    else if (bid < 72)  { src = Wa;  dst = g_wcatT + NOFF*CDIM;   K = CDIM; N = NAW;  t0 = 48;  }
    else if (bid < 136) { src = Wv;  dst = g_wvT;                 K = CDIM; N = CDIM; t0 = 72;  }
    else if (bid < 200) { src = Wp;  dst = g_wpT;                 K = CDIM; N = CDIM; t0 = 136; }
    else if (bid < 456) { src = Wf1; dst = g_wf1T;                K = CDIM; N = HID;  t0 = 200; }
    else                { src = Wf2; dst = g_wf2T;                K = HID;  N = CDIM; t0 = 456; }

    int t  = bid - t0;
    int nx = N / 32;
    int n0 = (t % nx) * 32, k0 = (t / nx) * 32;

    __shared__ float tile[32][33];
    #pragma unroll
    for (int i = ty; i < 32; i += 8)
        tile[i][tx] = src[(k0 + i) * N + n0 + tx];
    __syncthreads();
    #pragma unroll
    for (int i = ty; i < 32; i += 8)
        dst[(n0 + i) * K + k0 + tx] = __float2half_rn(tile[tx][i]);
}

__global__ void f2h_kernel(const float* __restrict__ src, __half* __restrict__ dst, int n)
{
    int i = (blockIdx.x * 256 + threadIdx.x) * 4;
    if (i < n) {
        float4 v = *reinterpret_cast<const float4*>(src + i);
        *reinterpret_cast<__half2*>(dst + i)     = __floats2half2_rn(v.x, v.y);
        *reinterpret_cast<__half2*>(dst + i + 2) = __floats2half2_rn(v.z, v.w);
    }
}

// ---------------- LayerNorm over C=256 (one block per row, 256 threads) ----------------
__global__ void ln_kernel(const float* __restrict__ x,
                          const float* __restrict__ g, const float* __restrict__ b,
                          const float* __restrict__ pos,
                          float* __restrict__ outn, __half* __restrict__ outh)
{
    int row = blockIdx.x;
    int t = threadIdx.x;
    float v = x[row*CDIM + t];

    __shared__ float sred[8];
    __shared__ float s_mean, s_var;

    float s = v;
    #pragma unroll
    for (int o = 16; o > 0; o >>= 1) s += __shfl_xor_sync(0xffffffffu, s, o);
    if ((t & 31) == 0) sred[t >> 5] = s;
    __syncthreads();
    if (t == 0) {
        float tot = 0.f;
        #pragma unroll
        for (int i = 0; i < 8; i++) tot += sred[i];
        s_mean = tot * (1.0f / CDIM);
    }
    __syncthreads();
    float mean = s_mean;

    float d = v - mean;
    float s2 = d * d;
    #pragma unroll
    for (int o = 16; o > 0; o >>= 1) s2 += __shfl_xor_sync(0xffffffffu, s2, o);
    __syncthreads();
    if ((t & 31) == 0) sred[t >> 5] = s2;
    __syncthreads();
    if (t == 0) {
        float tot = 0.f;
        #pragma unroll
        for (int i = 0; i < 8; i++) tot += sred[i];
        s_var = tot * (1.0f / CDIM);
    }
    __syncthreads();

    float y = d * rsqrtf(s_var + 1e-5f) * g[t] + b[t];
    if (outn) outn[row*CDIM + t] = y;
    float ya = pos ? (y + pos[row*CDIM + t]) : y;
    outh[row*CDIM + t] = __float2half_rn(ya);
}

// ---------------- fp16 tensor-core GEMM, BM=128 BN=128 BK=64, 3-stage cp.async, ldmatrix ----------------
#define ACT_NONE 0
#define ACT_GELU 1
#define PH 72    // smem row pitch in halves (144B). ldmatrix phases: 8 rows at 16i mod 128 -> all banks once.

#define A_BYTES (128*PH*2)           // 18432
#define B_BYTES (128*PH*2)           // 18432
#define STAGE_BYTES (A_BYTES + B_BYTES)   // 36864
#define SMEM_TOT (3*STAGE_BYTES)          // 110592

__device__ __forceinline__ uint32_t smem_u32(const void* p) {
    uint32_t a;
    asm("{ .reg .u64 t; cvta.to.shared.u64 t, %1; cvt.u32.u64 %0, t; }" : "=r"(a) : "l"(p));
    return a;
}
__device__ __forceinline__ void cp_async16(uint32_t dst, const void* src) {
    asm volatile("cp.async.cg.shared.global [%0], [%1], 16;" :: "r"(dst), "l"(src));
}
__device__ __forceinline__ void cp_commit() {
    asm volatile("cp.async.commit_group;" ::: "memory");
}
template<int N>
__device__ __forceinline__ void cp_wait() {
    asm volatile("cp.async.wait_group %0;" :: "n"(N) : "memory");
}
__device__ __forceinline__ void ldsm_x4(uint32_t& r0, uint32_t& r1, uint32_t& r2, uint32_t& r3,
                                        uint32_t addr) {
    asm volatile("ldmatrix.sync.aligned.m8n8.x4.shared.b16 {%0,%1,%2,%3}, [%4];"
                 : "=r"(r0), "=r"(r1), "=r"(r2), "=r"(r3) : "r"(addr));
}
__device__ __forceinline__ void ldsm_x2(uint32_t& r0, uint32_t& r1, uint32_t addr) {
    asm volatile("ldmatrix.sync.aligned.m8n8.x2.shared.b16 {%0,%1}, [%2];"
                 : "=r"(r0), "=r"(r1) : "r"(addr));
}
__device__ __forceinline__ void mma_f16(float4& d,
                                        uint32_t a0, uint32_t a1, uint32_t a2, uint32_t a3,
                                        uint32_t b0, uint32_t b1) {
    asm volatile(
        "mma.sync.aligned.m16n8k16.row.col.f32.f16.f16.f32 "
        "{%0,%1,%2,%3}, {%4,%5,%6,%7}, {%8,%9}, {%0,%1,%2,%3};\n"
        : "+f"(d.x), "+f"(d.y), "+f"(d.z), "+f"(d.w)
        : "r"(a0), "r"(a1), "r"(a2), "r"(a3), "r"(b0), "r"(b1));
}

__global__ __launch_bounds__(256)
void gemm_f16_kernel(const __half* __restrict__ A, const __half* __restrict__ WT,
                     const float* __restrict__ bias,
                     const float* __restrict__ res1, const float* __restrict__ res2,
                     void* __restrict__ Cout,
                     int M, int N, int K, int act, int out_half)
{
    extern __shared__ char smem[];
    uint32_t smem_base = smem_u32(smem);

    int tid  = threadIdx.x;
    int lane = tid & 31;
    int warp = tid >> 5;
    int g = lane >> 2;      // 0..7
    int t = lane & 3;       // 0..3
    int wm = warp & 1;      // 0..1  (m groups of 64)
    int wn = warp >> 1;     // 0..3  (n groups of 32)
    int m0w = wm * 64;
    int n0w = wn * 32;
    int bm0 = blockIdx.y * 128;
    int bn0 = blockIdx.x * 128;

    // per-lane ldmatrix byte offsets within a stage
    // A x4 (16x16): matrices m0=rows0-7/k0-7, m1=rows8-15/k0-7, m2=rows0-7/k8-15, m3=rows8-15/k8-15
    //   lane 0-15 -> row (lane&15), first 16B; lane 16-31 -> row (lane&15), second 16B
    uint32_t a_off = (uint32_t)((m0w + (lane & 15)) * (PH * 2) + (lane >> 4) * 16);
    // B x2 (8x16): m0 = k0-7 (16B), m1 = k8-15; lanes 0-7 -> rows, 8-15 -> rows +16B
    uint32_t b_off = (uint32_t)((n0w + (lane & 7)) * (PH * 2) + ((lane >> 3) & 1) * 16);

    float4 acc[4][4];
    #pragma unroll
    for (int i = 0; i < 4; i++)
        #pragma unroll
        for (int j = 0; j < 4; j++)
            acc[i][j] = make_float4(0.f, 0.f, 0.f, 0.f);

    const int nchunks = K >> 6;     // BK=64

    auto load_chunk = [&](int c, int s) {
        int k0 = c << 6;
        uint32_t as = smem_base + (uint32_t)(s * STAGE_BYTES);
        uint32_t bs = as + A_BYTES;
        #pragma unroll
        for (int p = 0; p < 4; p++) {
            int idx = p * 256 + tid;
            int row = idx >> 3;
            int c8  = (idx & 7) * 8;
            int grow = bm0 + row; if (grow > M - 1) grow = M - 1;
            cp_async16(as + (uint32_t)(row * PH + c8) * 2u, A + grow * K + k0 + c8);
        }
        #pragma unroll
        for (int p = 0; p < 4; p++) {
            int idx = p * 256 + tid;
            int row = idx >> 3;
            int c8  = (idx & 7) * 8;
            int gn  = bn0 + row; if (gn > N - 1) gn = N - 1;
            cp_async16(bs + (uint32_t)(row * PH + c8) * 2u, WT + gn * K + k0 + c8);
        }
        cp_commit();
    };

    if (0 < nchunks) load_chunk(0, 0);
    if (1 < nchunks) load_chunk(1, 1);

    int s = 0;
    for (int c = 0; c < nchunks; c++) {
        cp_wait<1>();
        __syncthreads();
        if (c + 2 < nchunks) {
            int s2 = s + 2; if (s2 >= 3) s2 -= 3;
            load_chunk(c + 2, s2);
        } else {
            cp_commit();       // empty group keeps pending-count invariant in the tail
        }

        uint32_t as = smem_base + (uint32_t)(s * STAGE_BYTES);
        uint32_t bs = as + A_BYTES;

        #pragma unroll
        for (int ks = 0; ks < 4; ks++) {
            uint32_t kofs = (uint32_t)(ks * 32);   // 16 halves = 32B per k-step
            uint32_t a[4][4];
            #pragma unroll
            for (int im = 0; im < 4; im++)
                ldsm_x4(a[im][0], a[im][1], a[im][2], a[im][3],
                        as + a_off + (uint32_t)(im * 16 * PH * 2) + kofs);
            #pragma unroll
            for (int in = 0; in < 4; in++) {
                uint32_t b0, b1;
                ldsm_x2(b0, b1, bs + b_off + (uint32_t)(in * 8 * PH * 2) + kofs);
                #pragma unroll
                for (int im = 0; im < 4; im++)
                    mma_f16(acc[im][in], a[im][0], a[im][1], a[im][2], a[im][3], b0, b1);
            }
        }
        if (++s >= 3) s = 0;
    }

    // ---- epilogue ----
    #pragma unroll
    for (int im = 0; im < 4; im++) {
        int r0 = bm0 + m0w + im * 16 + g;
        int r1 = r0 + 8;
        #pragma unroll
        for (int in = 0; in < 4; in++) {
            int c = bn0 + n0w + in * 8 + 2 * t;
            if (c >= N) continue;   // N even -> c+1 < N too
            float bx = bias[c], by = bias[c + 1];

            float v0 = acc[im][in].x + bx;
            float v1 = acc[im][in].y + by;
            float v2 = acc[im][in].z + bx;
            float v3 = acc[im][in].w + by;
            if (act == ACT_GELU) {
                v0 = 0.5f * v0 * (1.0f + erff(v0 * 0.70710678118654752f));
                v1 = 0.5f * v1 * (1.0f + erff(v1 * 0.70710678118654752f));
                v2 = 0.5f * v2 * (1.0f + erff(v2 * 0.70710678118654752f));
                v3 = 0.5f * v3 * (1.0f + erff(v3 * 0.70710678118654752f));
            }
            if (r0 < M) {
                int oi = r0 * N + c;
                if (res1) { v0 += res1[oi]; v1 += res1[oi + 1]; }
                if (res2) { v0 += res2[oi]; v1 += res2[oi + 1]; }
                if (out_half)
                    *reinterpret_cast<__half2*>((__half*)Cout + oi) = __floats2half2_rn(v0, v1);
                else
                    *reinterpret_cast<float2*>((float*)Cout + oi) = make_float2(v0, v1);
            }
            if (r1 < M) {
                int oi = r1 * N + c;
                if (res1) { v2 += res1[oi]; v3 += res1[oi + 1]; }
                if (res2) { v2 += res2[oi]; v3 += res2[oi + 1]; }
                if (out_half)
                    *reinterpret_cast<__half2*>((__half*)Cout + oi) = __floats2half2_rn(v2, v3);
                else
                    *reinterpret_cast<float2*>((float*)Cout + oi) = make_float2(v2, v3);
            }
        }
    }
}

// ---------------- deformable sampling + fused softmax (fp16 values, fp16 out) ----------------
__global__ void sample_kernel(const float* __restrict__ refp)
{
    int row0 = blockIdx.x * 2;
    int t    = threadIdx.x;

    __shared__ float s_off[2][NOFF];
    __shared__ float s_aw [2][NAW];
    __shared__ float s_ref[2][LEV * 2];

    #pragma unroll
    for (int r = 0; r < 2; r++) {
        int row = row0 + r;
        if (t < NOFF)   s_off[r][t] = g_ol[row * NOL + t];
        if (t < NAW)    s_aw [r][t] = g_ol[row * NOL + NOFF + t];
        if (t < LEV*2)  s_ref[r][t] = refp[row * LEV * 2 + t];
    }
    __syncthreads();

    if (t < 16) {
        int r = t >> 3, h = t & 7;
        float* v = &s_aw[r][h * (LEV * PTS)];
        float mx = -1e30f;
        float e[LEV * PTS];
        #pragma unroll
        for (int i = 0; i < LEV * PTS; i++) mx = fmaxf(mx, v[i]);
        float sum = 0.f;
        #pragma unroll
        for (int i = 0; i < LEV * PTS; i++) { e[i] = __expf(v[i] - mx); sum += e[i]; }
        float inv = 1.0f / sum;
        #pragma unroll
        for (int i = 0; i < LEV * PTS; i++) v[i] = e[i] * inv;
    }
    __syncthreads();

    int r = t >> 7;
    int h = (t >> 4) & 7;
    int d = (t & 15) * 2;
    int row = row0 + r;
    int b   = row / NQ;

    const int Hl_[LEV] = {60, 30, 15};
    const int Wl_[LEV] = {80, 40, 20};
    const int St_[LEV] = {0, 4800, 6000};

    float2 acc = make_float2(0.f, 0.f);
    #pragma unroll
    for (int l = 0; l < LEV; l++) {
        int Hl = Hl_[l], Wl = Wl_[l];
        const __half* vbase = g_v + (b * NV + St_[l]) * CDIM + h * DH + d;
        float rx = s_ref[r][l * 2 + 0];
        float ry = s_ref[r][l * 2 + 1];
        #pragma unroll
        for (int p = 0; p < PTS; p++) {
            int oi = ((h * LEV + l) * PTS + p) * 2;
            float gx = rx * (float)Wl + s_off[r][oi + 0] - 0.5f;
            float gy = ry * (float)Hl + s_off[r][oi + 1] - 0.5f;
            float w  = s_aw[r][(h * LEV + l) * PTS + p];

            float x0f = floorf(gx), y0f = floorf(gy);
            int x0 = (int)x0f, y0 = (int)y0f;
            float wx = gx - x0f, wy = gy - y0f;

            float2 sv = make_float2(0.f, 0.f);
            #pragma unroll
            for (int dy = 0; dy < 2; dy++) {
                int yi = y0 + dy;
                if (yi < 0 || yi >= Hl) continue;
                float wyv = dy ? wy : (1.f - wy);
                #pragma unroll
                for (int dx = 0; dx < 2; dx++) {
                    int xi = x0 + dx;
                    if (xi < 0 || xi >= Wl) continue;
                    float wxv = dx ? wx : (1.f - wx);
                    __half2 hv = *reinterpret_cast<const __half2*>(vbase + (yi * Wl + xi) * CDIM);
                    float2 vv = __half22float2(hv);
                    float cw = wyv * wxv;
                    sv.x = fmaf(cw, vv.x, sv.x);
                    sv.y = fmaf(cw, vv.y, sv.y);
                }
            }
            acc.x = fmaf(w, sv.x, acc.x);
            acc.y = fmaf(w, sv.y, acc.y);
        }
    }
    *reinterpret_cast<__half2*>(&g_attn_h[row * CDIM + h * DH + d]) = __floats2half2_rn(acc.x, acc.y);
}

// ---------------- launch ----------------
extern "C" void kernel_launch(void* const* d_in, const int* in_sizes, int n_in,
                              void* d_out, int out_size)
{
    const float* query = (const float*)d_in[0];
    const float* value = (const float*)d_in[1];
    const float* qpos  = (const float*)d_in[2];
    const float* refp  = (const float*)d_in[3];
    const float* g1  = (const float*)d_in[6];
    const float* b1  = (const float*)d_in[7];
    const float* Wo  = (const float*)d_in[8];
    const float* bo  = (const float*)d_in[9];
    const float* Wa  = (const float*)d_in[10];
    const float* ba  = (const float*)d_in[11];
    const float* Wv  = (const float*)d_in[12];
    const float* bv  = (const float*)d_in[13];
    const float* Wp  = (const float*)d_in[14];
    const float* bp  = (const float*)d_in[15];
    const float* g2  = (const float*)d_in[16];
    const float* b2  = (const float*)d_in[17];
    const float* Wf1 = (const float*)d_in[18];
    const float* bf1 = (const float*)d_in[19];
    const float* Wf2 = (const float*)d_in[20];
    const float* bf2 = (const float*)d_in[21];
    float* out = (float*)d_out;

    float *qn, *olbuf, *q, *bcat;
    __half *qa_h, *val_h, *vproj, *attn_h, *q2_h, *h_h;
    __half *wcatT, *wvT, *wpT, *wf1T, *wf2T;
    cudaGetSymbolAddress((void**)&qn,     g_qn);
    cudaGetSymbolAddress((void**)&qa_h,   g_qa_h);
    cudaGetSymbolAddress((void**)&olbuf,  g_ol);
    cudaGetSymbolAddress((void**)&val_h,  g_val_h);
    cudaGetSymbolAddress((void**)&vproj,  g_v);
    cudaGetSymbolAddress((void**)&attn_h, g_attn_h);
    cudaGetSymbolAddress((void**)&q,      g_q);
    cudaGetSymbolAddress((void**)&q2_h,   g_q2_h);
    cudaGetSymbolAddress((void**)&h_h,    g_h_h);
    cudaGetSymbolAddress((void**)&wcatT,  g_wcatT);
    cudaGetSymbolAddress((void**)&wvT,    g_wvT);
    cudaGetSymbolAddress((void**)&wpT,    g_wpT);
    cudaGetSymbolAddress((void**)&wf1T,   g_wf1T);
    cudaGetSymbolAddress((void**)&wf2T,   g_wf2T);
    cudaGetSymbolAddress((void**)&bcat,   g_bcat);

    cudaFuncSetAttribute(gemm_f16_kernel, cudaFuncAttributeMaxDynamicSharedMemorySize, SMEM_TOT);

    // 0) prep
    prep_kernel<<<712, dim3(32, 8)>>>(Wo, Wa, Wv, Wp, Wf1, Wf2, bo, ba);
    f2h_kernel<<<(RV*CDIM/4 + 255)/256, 256>>>(value, val_h, RV*CDIM);

    // 1) LN1
    ln_kernel<<<RQ, 256>>>(query, g1, b1, qpos, qn, qa_h);

    // 2) fused offsets+logits [RQ x 288]
    gemm_f16_kernel<<<dim3(3, RQ/128), 256, SMEM_TOT>>>(
        qa_h, wcatT, bcat, nullptr, nullptr, olbuf, RQ, NOL, CDIM, ACT_NONE, 0);

    // 3) value projection -> fp16 [RV x 256]
    gemm_f16_kernel<<<dim3(2, (RV + 127)/128), 256, SMEM_TOT>>>(
        val_h, wvT, bv, nullptr, nullptr, vproj, RV, CDIM, CDIM, ACT_NONE, 1);

    // 4) fused softmax + sampling -> attn_h
    sample_kernel<<<RQ/2, 256>>>(refp);

    // 5) output proj + residuals (fp32)
    gemm_f16_kernel<<<dim3(2, RQ/128), 256, SMEM_TOT>>>(
        attn_h, wpT, bp, qn, query, q, RQ, CDIM, CDIM, ACT_NONE, 0);

    // 6) LN2 -> fp16
    ln_kernel<<<RQ, 256>>>(q, g2, b2, nullptr, nullptr, q2_h);

    // 7) FFN up + GELU -> fp16 [RQ x 1024]
    gemm_f16_kernel<<<dim3(8, RQ/128), 256, SMEM_TOT>>>(
        q2_h, wf1T, bf1, nullptr, nullptr, h_h, RQ, HID, CDIM, ACT_GELU, 1);

    // 8) FFN down + residual (fp32)
    gemm_f16_kernel<<<dim3(2, RQ/128), 256, SMEM_TOT>>>(
        h_h, wf2T, bf2, q, nullptr, out, RQ, CDIM, HID, ACT_NONE, 0);
}

// round 14
// speedup vs baseline: 3.7488x; 1.0841x over previous
#include <cuda_runtime.h>
#include <cuda_fp16.h>
#include <cstdint>
#include <math.h>

// ---------------- problem constants (fixed shapes) ----------------
#define BATCH 2
#define NQ    8192
#define RQ    (BATCH*NQ)     // 16384 query rows
#define CDIM  256
#define HEADS 8
#define DH    32
#define LEV   3
#define PTS   4
#define NV    6300           // 4800+1200+300
#define RV    (BATCH*NV)     // 12600 value rows
#define HID   1024           // MLP*C
#define NOFF  (HEADS*LEV*PTS*2)  // 192
#define NAW   (HEADS*LEV*PTS)    // 96
#define NOL   (NOFF+NAW)         // 288

// ---------------- scratch (static device memory; no allocs allowed) ----------------
__device__ float  g_qn   [RQ*CDIM];
__device__ __half g_qa_h [RQ*CDIM];
__device__ float  g_ol   [RQ*NOL];
__device__ __half g_val_h[RV*CDIM];
__device__ __half g_v    [RV*CDIM];
__device__ __half g_attn_h[RQ*CDIM];
__device__ float  g_q    [RQ*CDIM];
__device__ __half g_q2_h [RQ*CDIM];
__device__ __half g_h_h  [RQ*HID];
__device__ __half g_wcatT[NOL*CDIM];
__device__ __half g_wvT  [CDIM*CDIM];
__device__ __half g_wpT  [CDIM*CDIM];
__device__ __half g_wf1T [HID*CDIM];
__device__ __half g_wf2T [CDIM*HID];
__device__ float  g_bcat [NOL];

// ---------------- combined prep: all 6 weight transposes (+bias concat), 1 launch ----------------
__global__ void prep_kernel(const float* __restrict__ Wo, const float* __restrict__ Wa,
                            const float* __restrict__ Wv, const float* __restrict__ Wp,
                            const float* __restrict__ Wf1, const float* __restrict__ Wf2,
                            const float* __restrict__ bo, const float* __restrict__ ba)
{
    int bid = blockIdx.x;
    int tx = threadIdx.x, ty = threadIdx.y;     // 32 x 8
    int tid = ty * 32 + tx;

    int flat = bid * 256 + tid;
    if (flat < NOL) g_bcat[flat] = (flat < NOFF) ? bo[flat] : ba[flat - NOFF];

    const float* src; __half* dst; int K, N, t0;
    if (bid < 48)       { src = Wo;  dst = g_wcatT;               K = CDIM; N = NOFF; t0 = 0;   }
    else if (bid < 72)  { src = Wa;  dst = g_wcatT + NOFF*CDIM;   K = CDIM; N = NAW;  t0 = 48;  }
    else if (bid < 136) { src = Wv;  dst = g_wvT;                 K = CDIM; N = CDIM; t0 = 72;  }
    else if (bid < 200) { src = Wp;  dst = g_wpT;                 K = CDIM; N = CDIM; t0 = 136; }
    else if (bid < 456) { src = Wf1; dst = g_wf1T;                K = CDIM; N = HID;  t0 = 200; }
    else                { src = Wf2; dst = g_wf2T;                K = HID;  N = CDIM; t0 = 456; }

    int t  = bid - t0;
    int nx = N / 32;
    int n0 = (t % nx) * 32, k0 = (t / nx) * 32;

    __shared__ float tile[32][33];
    #pragma unroll
    for (int i = ty; i < 32; i += 8)
        tile[i][tx] = src[(k0 + i) * N + n0 + tx];
    __syncthreads();
    #pragma unroll
    for (int i = ty; i < 32; i += 8)
        dst[(n0 + i) * K + k0 + tx] = __float2half_rn(tile[tx][i]);
}

__global__ void f2h_kernel(const float* __restrict__ src, __half* __restrict__ dst, int n)
{
    int i = (blockIdx.x * 256 + threadIdx.x) * 4;
    if (i < n) {
        float4 v = *reinterpret_cast<const float4*>(src + i);
        *reinterpret_cast<__half2*>(dst + i)     = __floats2half2_rn(v.x, v.y);
        *reinterpret_cast<__half2*>(dst + i + 2) = __floats2half2_rn(v.z, v.w);
    }
}

// ---------------- LayerNorm over C=256 (one block per row, 256 threads) ----------------
__global__ void ln_kernel(const float* __restrict__ x,
                          const float* __restrict__ g, const float* __restrict__ b,
                          const float* __restrict__ pos,
                          float* __restrict__ outn, __half* __restrict__ outh)
{
    int row = blockIdx.x;
    int t = threadIdx.x;
    float v = x[row*CDIM + t];

    __shared__ float sred[8];
    __shared__ float s_mean, s_var;

    float s = v;
    #pragma unroll
    for (int o = 16; o > 0; o >>= 1) s += __shfl_xor_sync(0xffffffffu, s, o);
    if ((t & 31) == 0) sred[t >> 5] = s;
    __syncthreads();
    if (t == 0) {
        float tot = 0.f;
        #pragma unroll
        for (int i = 0; i < 8; i++) tot += sred[i];
        s_mean = tot * (1.0f / CDIM);
    }
    __syncthreads();
    float mean = s_mean;

    float d = v - mean;
    float s2 = d * d;
    #pragma unroll
    for (int o = 16; o > 0; o >>= 1) s2 += __shfl_xor_sync(0xffffffffu, s2, o);
    __syncthreads();
    if ((t & 31) == 0) sred[t >> 5] = s2;
    __syncthreads();
    if (t == 0) {
        float tot = 0.f;
        #pragma unroll
        for (int i = 0; i < 8; i++) tot += sred[i];
        s_var = tot * (1.0f / CDIM);
    }
    __syncthreads();

    float y = d * rsqrtf(s_var + 1e-5f) * g[t] + b[t];
    if (outn) outn[row*CDIM + t] = y;
    float ya = pos ? (y + pos[row*CDIM + t]) : y;
    outh[row*CDIM + t] = __float2half_rn(ya);
}

// ---------------- fp16 tensor-core GEMM, BM=128 BN=64 BK=64, 2-stage, ldmatrix ----------------
// 256 threads = 8 warps (4m x 2n); warp tile 32x32 = 2x4 mma m16n8k16; target 3 CTAs/SM.
#define ACT_NONE 0
#define ACT_GELU 1
#define PH 72    // smem row pitch in halves (144B); ldmatrix phases conflict-free

#define A_BYTES (128*PH*2)           // 18432
#define B_BYTES (64*PH*2)            // 9216
#define STAGE_BYTES (A_BYTES + B_BYTES)   // 27648
#define SMEM_TOT (2*STAGE_BYTES)          // 55296

__device__ __forceinline__ uint32_t smem_u32(const void* p) {
    uint32_t a;
    asm("{ .reg .u64 t; cvta.to.shared.u64 t, %1; cvt.u32.u64 %0, t; }" : "=r"(a) : "l"(p));
    return a;
}
__device__ __forceinline__ void cp_async16(uint32_t dst, const void* src) {
    asm volatile("cp.async.cg.shared.global [%0], [%1], 16;" :: "r"(dst), "l"(src));
}
__device__ __forceinline__ void cp_commit() {
    asm volatile("cp.async.commit_group;" ::: "memory");
}
template<int N>
__device__ __forceinline__ void cp_wait() {
    asm volatile("cp.async.wait_group %0;" :: "n"(N) : "memory");
}
__device__ __forceinline__ void ldsm_x4(uint32_t& r0, uint32_t& r1, uint32_t& r2, uint32_t& r3,
                                        uint32_t addr) {
    asm volatile("ldmatrix.sync.aligned.m8n8.x4.shared.b16 {%0,%1,%2,%3}, [%4];"
                 : "=r"(r0), "=r"(r1), "=r"(r2), "=r"(r3) : "r"(addr));
}
__device__ __forceinline__ void ldsm_x2(uint32_t& r0, uint32_t& r1, uint32_t addr) {
    asm volatile("ldmatrix.sync.aligned.m8n8.x2.shared.b16 {%0,%1}, [%2];"
                 : "=r"(r0), "=r"(r1) : "r"(addr));
}
__device__ __forceinline__ void mma_f16(float4& d,
                                        uint32_t a0, uint32_t a1, uint32_t a2, uint32_t a3,
                                        uint32_t b0, uint32_t b1) {
    asm volatile(
        "mma.sync.aligned.m16n8k16.row.col.f32.f16.f16.f32 "
        "{%0,%1,%2,%3}, {%4,%5,%6,%7}, {%8,%9}, {%0,%1,%2,%3};\n"
        : "+f"(d.x), "+f"(d.y), "+f"(d.z), "+f"(d.w)
        : "r"(a0), "r"(a1), "r"(a2), "r"(a3), "r"(b0), "r"(b1));
}

__global__ __launch_bounds__(256, 3)
void gemm_f16_kernel(const __half* __restrict__ A, const __half* __restrict__ WT,
                     const float* __restrict__ bias,
                     const float* __restrict__ res1, const float* __restrict__ res2,
                     void* __restrict__ Cout,
                     int M, int N, int K, int act, int out_half)
{
    extern __shared__ char smem[];
    uint32_t smem_base = smem_u32(smem);

    int tid  = threadIdx.x;
    int lane = tid & 31;
    int warp = tid >> 5;
    int g = lane >> 2;      // 0..7
    int t = lane & 3;       // 0..3
    int wm = warp >> 1;     // 0..3  (m groups of 32)
    int wn = warp & 1;      // 0..1  (n groups of 32)
    int m0w = wm * 32;
    int n0w = wn * 32;
    int bm0 = blockIdx.y * 128;
    int bn0 = blockIdx.x * 64;

    // ldmatrix per-lane byte offsets
    uint32_t a_off = (uint32_t)((m0w + (lane & 15)) * (PH * 2) + (lane >> 4) * 16);
    uint32_t b_off = (uint32_t)((n0w + (lane & 7)) * (PH * 2) + ((lane >> 3) & 1) * 16);

    float4 acc[2][4];
    #pragma unroll
    for (int i = 0; i < 2; i++)
        #pragma unroll
        for (int j = 0; j < 4; j++)
            acc[i][j] = make_float4(0.f, 0.f, 0.f, 0.f);

    const int nchunks = K >> 6;     // BK=64

    // ---- stage loader: A 128x64h (4 cp/thread) + B 64x64h (2 cp/thread), one group ----
    auto load_chunk = [&](int c, int s) {
        int k0 = c << 6;
        uint32_t as = smem_base + (uint32_t)(s * STAGE_BYTES);
        uint32_t bs = as + A_BYTES;
        #pragma unroll
        for (int p = 0; p < 4; p++) {
            int idx = p * 256 + tid;
            int row = idx >> 3;
            int c8  = (idx & 7) * 8;
            int grow = bm0 + row; if (grow > M - 1) grow = M - 1;
            cp_async16(as + (uint32_t)(row * PH + c8) * 2u, A + grow * K + k0 + c8);
        }
        #pragma unroll
        for (int p = 0; p < 2; p++) {
            int idx = p * 256 + tid;
            int row = idx >> 3;
            int c8  = (idx & 7) * 8;
            int gn  = bn0 + row; if (gn > N - 1) gn = N - 1;
            cp_async16(bs + (uint32_t)(row * PH + c8) * 2u, WT + gn * K + k0 + c8);
        }
        cp_commit();
    };

    load_chunk(0, 0);

    int s = 0;
    for (int c = 0; c < nchunks; c++) {
        cp_wait<0>();          // drains everything pending -> chunk c definitely landed
        __syncthreads();
        if (c + 1 < nchunks) load_chunk(c + 1, s ^ 1);   // overlaps with compute of c

        uint32_t as = smem_base + (uint32_t)(s * STAGE_BYTES);
        uint32_t bs = as + A_BYTES;

        #pragma unroll
        for (int ks = 0; ks < 4; ks++) {
            uint32_t kofs = (uint32_t)(ks * 32);   // 16 halves per k-step
            uint32_t a[2][4];
            #pragma unroll
            for (int im = 0; im < 2; im++)
                ldsm_x4(a[im][0], a[im][1], a[im][2], a[im][3],
                        as + a_off + (uint32_t)(im * 16 * PH * 2) + kofs);
            uint32_t b[4][2];
            #pragma unroll
            for (int in = 0; in < 4; in++)
                ldsm_x2(b[in][0], b[in][1], bs + b_off + (uint32_t)(in * 8 * PH * 2) + kofs);
            #pragma unroll
            for (int in = 0; in < 4; in++) {
                mma_f16(acc[0][in], a[0][0], a[0][1], a[0][2], a[0][3], b[in][0], b[in][1]);
                mma_f16(acc[1][in], a[1][0], a[1][1], a[1][2], a[1][3], b[in][0], b[in][1]);
            }
        }
        __syncthreads();       // compute done before stage s overwritten next iteration
        s ^= 1;
    }

    // ---- epilogue ----
    #pragma unroll
    for (int im = 0; im < 2; im++) {
        int r0 = bm0 + m0w + im * 16 + g;
        int r1 = r0 + 8;
        #pragma unroll
        for (int in = 0; in < 4; in++) {
            int c = bn0 + n0w + in * 8 + 2 * t;
            if (c >= N) continue;   // N even -> c+1 < N too
            float bx = bias[c], by = bias[c + 1];

            float v0 = acc[im][in].x + bx;
            float v1 = acc[im][in].y + by;
            float v2 = acc[im][in].z + bx;
            float v3 = acc[im][in].w + by;
            if (act == ACT_GELU) {
                v0 = 0.5f * v0 * (1.0f + erff(v0 * 0.70710678118654752f));
                v1 = 0.5f * v1 * (1.0f + erff(v1 * 0.70710678118654752f));
                v2 = 0.5f * v2 * (1.0f + erff(v2 * 0.70710678118654752f));
                v3 = 0.5f * v3 * (1.0f + erff(v3 * 0.70710678118654752f));
            }
            if (r0 < M) {
                int oi = r0 * N + c;
                if (res1) { v0 += res1[oi]; v1 += res1[oi + 1]; }
                if (res2) { v0 += res2[oi]; v1 += res2[oi + 1]; }
                if (out_half)
                    *reinterpret_cast<__half2*>((__half*)Cout + oi) = __floats2half2_rn(v0, v1);
                else
                    *reinterpret_cast<float2*>((float*)Cout + oi) = make_float2(v0, v1);
            }
            if (r1 < M) {
                int oi = r1 * N + c;
                if (res1) { v2 += res1[oi]; v3 += res1[oi + 1]; }
                if (res2) { v2 += res2[oi]; v3 += res2[oi + 1]; }
                if (out_half)
                    *reinterpret_cast<__half2*>((__half*)Cout + oi) = __floats2half2_rn(v2, v3);
                else
                    *reinterpret_cast<float2*>((float*)Cout + oi) = make_float2(v2, v3);
            }
        }
    }
}

// ---------------- deformable sampling + fused softmax (fp16 values, fp16 out) ----------------
__global__ void sample_kernel(const float* __restrict__ refp)
{
    int row0 = blockIdx.x * 2;
    int t    = threadIdx.x;

    __shared__ float s_off[2][NOFF];
    __shared__ float s_aw [2][NAW];
    __shared__ float s_ref[2][LEV * 2];

    #pragma unroll
    for (int r = 0; r < 2; r++) {
        int row = row0 + r;
        if (t < NOFF)   s_off[r][t] = g_ol[row * NOL + t];
        if (t < NAW)    s_aw [r][t] = g_ol[row * NOL + NOFF + t];
        if (t < LEV*2)  s_ref[r][t] = refp[row * LEV * 2 + t];
    }
    __syncthreads();

    if (t < 16) {
        int r = t >> 3, h = t & 7;
        float* v = &s_aw[r][h * (LEV * PTS)];
        float mx = -1e30f;
        float e[LEV * PTS];
        #pragma unroll
        for (int i = 0; i < LEV * PTS; i++) mx = fmaxf(mx, v[i]);
        float sum = 0.f;
        #pragma unroll
        for (int i = 0; i < LEV * PTS; i++) { e[i] = __expf(v[i] - mx); sum += e[i]; }
        float inv = 1.0f / sum;
        #pragma unroll
        for (int i = 0; i < LEV * PTS; i++) v[i] = e[i] * inv;
    }
    __syncthreads();

    int r = t >> 7;
    int h = (t >> 4) & 7;
    int d = (t & 15) * 2;
    int row = row0 + r;
    int b   = row / NQ;

    const int Hl_[LEV] = {60, 30, 15};
    const int Wl_[LEV] = {80, 40, 20};
    const int St_[LEV] = {0, 4800, 6000};

    float2 acc = make_float2(0.f, 0.f);
    #pragma unroll
    for (int l = 0; l < LEV; l++) {
        int Hl = Hl_[l], Wl = Wl_[l];
        const __half* vbase = g_v + (b * NV + St_[l]) * CDIM + h * DH + d;
        float rx = s_ref[r][l * 2 + 0];
        float ry = s_ref[r][l * 2 + 1];
        #pragma unroll
        for (int p = 0; p < PTS; p++) {
            int oi = ((h * LEV + l) * PTS + p) * 2;
            float gx = rx * (float)Wl + s_off[r][oi + 0] - 0.5f;
            float gy = ry * (float)Hl + s_off[r][oi + 1] - 0.5f;
            float w  = s_aw[r][(h * LEV + l) * PTS + p];

            float x0f = floorf(gx), y0f = floorf(gy);
            int x0 = (int)x0f, y0 = (int)y0f;
            float wx = gx - x0f, wy = gy - y0f;

            float2 sv = make_float2(0.f, 0.f);
            #pragma unroll
            for (int dy = 0; dy < 2; dy++) {
                int yi = y0 + dy;
                if (yi < 0 || yi >= Hl) continue;
                float wyv = dy ? wy : (1.f - wy);
                #pragma unroll
                for (int dx = 0; dx < 2; dx++) {
                    int xi = x0 + dx;
                    if (xi < 0 || xi >= Wl) continue;
                    float wxv = dx ? wx : (1.f - wx);
                    __half2 hv = *reinterpret_cast<const __half2*>(vbase + (yi * Wl + xi) * CDIM);
                    float2 vv = __half22float2(hv);
                    float cw = wyv * wxv;
                    sv.x = fmaf(cw, vv.x, sv.x);
                    sv.y = fmaf(cw, vv.y, sv.y);
                }
            }
            acc.x = fmaf(w, sv.x, acc.x);
            acc.y = fmaf(w, sv.y, acc.y);
        }
    }
    *reinterpret_cast<__half2*>(&g_attn_h[row * CDIM + h * DH + d]) = __floats2half2_rn(acc.x, acc.y);
}

// ---------------- launch ----------------
extern "C" void kernel_launch(void* const* d_in, const int* in_sizes, int n_in,
                              void* d_out, int out_size)
{
    const float* query = (const float*)d_in[0];
    const float* value = (const float*)d_in[1];
    const float* qpos  = (const float*)d_in[2];
    const float* refp  = (const float*)d_in[3];
    const float* g1  = (const float*)d_in[6];
    const float* b1  = (const float*)d_in[7];
    const float* Wo  = (const float*)d_in[8];
    const float* bo  = (const float*)d_in[9];
    const float* Wa  = (const float*)d_in[10];
    const float* ba  = (const float*)d_in[11];
    const float* Wv  = (const float*)d_in[12];
    const float* bv  = (const float*)d_in[13];
    const float* Wp  = (const float*)d_in[14];
    const float* bp  = (const float*)d_in[15];
    const float* g2  = (const float*)d_in[16];
    const float* b2  = (const float*)d_in[17];
    const float* Wf1 = (const float*)d_in[18];
    const float* bf1 = (const float*)d_in[19];
    const float* Wf2 = (const float*)d_in[20];
    const float* bf2 = (const float*)d_in[21];
    float* out = (float*)d_out;

    float *qn, *olbuf, *q, *bcat;
    __half *qa_h, *val_h, *vproj, *attn_h, *q2_h, *h_h;
    __half *wcatT, *wvT, *wpT, *wf1T, *wf2T;
    cudaGetSymbolAddress((void**)&qn,     g_qn);
    cudaGetSymbolAddress((void**)&qa_h,   g_qa_h);
    cudaGetSymbolAddress((void**)&olbuf,  g_ol);
    cudaGetSymbolAddress((void**)&val_h,  g_val_h);
    cudaGetSymbolAddress((void**)&vproj,  g_v);
    cudaGetSymbolAddress((void**)&attn_h, g_attn_h);
    cudaGetSymbolAddress((void**)&q,      g_q);
    cudaGetSymbolAddress((void**)&q2_h,   g_q2_h);
    cudaGetSymbolAddress((void**)&h_h,    g_h_h);
    cudaGetSymbolAddress((void**)&wcatT,  g_wcatT);
    cudaGetSymbolAddress((void**)&wvT,    g_wvT);
    cudaGetSymbolAddress((void**)&wpT,    g_wpT);
    cudaGetSymbolAddress((void**)&wf1T,   g_wf1T);
    cudaGetSymbolAddress((void**)&wf2T,   g_wf2T);
    cudaGetSymbolAddress((void**)&bcat,   g_bcat);

    cudaFuncSetAttribute(gemm_f16_kernel, cudaFuncAttributeMaxDynamicSharedMemorySize, SMEM_TOT);

    // 0) prep
    prep_kernel<<<712, dim3(32, 8)>>>(Wo, Wa, Wv, Wp, Wf1, Wf2, bo, ba);
    f2h_kernel<<<(RV*CDIM/4 + 255)/256, 256>>>(value, val_h, RV*CDIM);

    // 1) LN1
    ln_kernel<<<RQ, 256>>>(query, g1, b1, qpos, qn, qa_h);

    // 2) fused offsets+logits [RQ x 288]
    gemm_f16_kernel<<<dim3((NOL + 63)/64, RQ/128), 256, SMEM_TOT>>>(
        qa_h, wcatT, bcat, nullptr, nullptr, olbuf, RQ, NOL, CDIM, ACT_NONE, 0);

    // 3) value projection -> fp16 [RV x 256]
    gemm_f16_kernel<<<dim3(4, (RV + 127)/128), 256, SMEM_TOT>>>(
        val_h, wvT, bv, nullptr, nullptr, vproj, RV, CDIM, CDIM, ACT_NONE, 1);

    // 4) fused softmax + sampling -> attn_h
    sample_kernel<<<RQ/2, 256>>>(refp);

    // 5) output proj + residuals (fp32)
    gemm_f16_kernel<<<dim3(4, RQ/128), 256, SMEM_TOT>>>(
        attn_h, wpT, bp, qn, query, q, RQ, CDIM, CDIM, ACT_NONE, 0);

    // 6) LN2 -> fp16
    ln_kernel<<<RQ, 256>>>(q, g2, b2, nullptr, nullptr, q2_h);

    // 7) FFN up + GELU -> fp16 [RQ x 1024]
    gemm_f16_kernel<<<dim3(16, RQ/128), 256, SMEM_TOT>>>(
        q2_h, wf1T, bf1, nullptr, nullptr, h_h, RQ, HID, CDIM, ACT_GELU, 1);

    // 8) FFN down + residual (fp32)
    gemm_f16_kernel<<<dim3(4, RQ/128), 256, SMEM_TOT>>>(
        h_h, wf2T, bf2, q, nullptr, out, RQ, CDIM, HID, ACT_NONE, 0);
}

// round 16
// speedup vs baseline: 3.8513x; 1.0273x over previous
#include <cuda_runtime.h>
#include <cuda_fp16.h>
#include <cstdint>
#include <math.h>

// ---------------- problem constants (fixed shapes) ----------------
#define BATCH 2
#define NQ    8192
#define RQ    (BATCH*NQ)     // 16384 query rows
#define CDIM  256
#define HEADS 8
#define DH    32
#define LEV   3
#define PTS   4
#define NV    6300           // 4800+1200+300
#define RV    (BATCH*NV)     // 12600 value rows
#define HID   1024           // MLP*C
#define NOFF  (HEADS*LEV*PTS*2)  // 192
#define NAW   (HEADS*LEV*PTS)    // 96
#define NOL   (NOFF+NAW)         // 288

// ---------------- scratch (static device memory; no allocs allowed) ----------------
__device__ float  g_qn   [RQ*CDIM];
__device__ __half g_qa_h [RQ*CDIM];
__device__ float  g_ol   [RQ*NOL];
__device__ __half g_val_h[RV*CDIM];
__device__ __half g_v    [RV*CDIM];
__device__ __half g_attn_h[RQ*CDIM];
__device__ float  g_q    [RQ*CDIM];
__device__ __half g_q2_h [RQ*CDIM];
__device__ __half g_h_h  [RQ*HID];
__device__ __half g_wcatT[NOL*CDIM];
__device__ __half g_wvT  [CDIM*CDIM];
__device__ __half g_wpT  [CDIM*CDIM];
__device__ __half g_wf1T [HID*CDIM];
__device__ __half g_wf2T [CDIM*HID];
__device__ float  g_bcat [NOL];

// ---------------- combined prep: all 6 weight transposes (+bias concat), 1 launch ----------------
__global__ void prep_kernel(const float* __restrict__ Wo, const float* __restrict__ Wa,
                            const float* __restrict__ Wv, const float* __restrict__ Wp,
                            const float* __restrict__ Wf1, const float* __restrict__ Wf2,
                            const float* __restrict__ bo, const float* __restrict__ ba)
{
    int bid = blockIdx.x;
    int tx = threadIdx.x, ty = threadIdx.y;     // 32 x 8
    int tid = ty * 32 + tx;

    int flat = bid * 256 + tid;
    if (flat < NOL) g_bcat[flat] = (flat < NOFF) ? bo[flat] : ba[flat - NOFF];

    const float* src; __half* dst; int K, N, t0;
    if (bid < 48)       { src = Wo;  dst = g_wcatT;               K = CDIM; N = NOFF; t0 = 0;   }
    else if (bid < 72)  { src = Wa;  dst = g_wcatT + NOFF*CDIM;   K = CDIM; N = NAW;  t0 = 48;  }
    else if (bid < 136) { src = Wv;  dst = g_wvT;                 K = CDIM; N = CDIM; t0 = 72;  }
    else if (bid < 200) { src = Wp;  dst = g_wpT;                 K = CDIM; N = CDIM; t0 = 136; }
    else if (bid < 456) { src = Wf1; dst = g_wf1T;                K = CDIM; N = HID;  t0 = 200; }
    else                { src = Wf2; dst = g_wf2T;                K = HID;  N = CDIM; t0 = 456; }

    int t  = bid - t0;
    int nx = N / 32;
    int n0 = (t % nx) * 32, k0 = (t / nx) * 32;

    __shared__ float tile[32][33];
    #pragma unroll
    for (int i = ty; i < 32; i += 8)
        tile[i][tx] = src[(k0 + i) * N + n0 + tx];
    __syncthreads();
    #pragma unroll
    for (int i = ty; i < 32; i += 8)
        dst[(n0 + i) * K + k0 + tx] = __float2half_rn(tile[tx][i]);
}

__global__ void f2h_kernel(const float* __restrict__ src, __half* __restrict__ dst, int n)
{
    int i = (blockIdx.x * 256 + threadIdx.x) * 4;
    if (i < n) {
        float4 v = *reinterpret_cast<const float4*>(src + i);
        *reinterpret_cast<__half2*>(dst + i)     = __floats2half2_rn(v.x, v.y);
        *reinterpret_cast<__half2*>(dst + i + 2) = __floats2half2_rn(v.z, v.w);
    }
}

// ---------------- LayerNorm: warp-per-row, 8 rows/block, shuffle-only ----------------
__global__ void ln_kernel(const float* __restrict__ x,
                          const float* __restrict__ g, const float* __restrict__ b,
                          const float* __restrict__ pos,
                          float* __restrict__ outn, __half* __restrict__ outh)
{
    int warp = threadIdx.x >> 5;
    int lane = threadIdx.x & 31;
    int row  = blockIdx.x * 8 + warp;

    const float* xr = x + row * CDIM;
    int c0 = lane * 4;            // first float4
    int c1 = 128 + lane * 4;      // second float4
    float4 v0 = *reinterpret_cast<const float4*>(xr + c0);
    float4 v1 = *reinterpret_cast<const float4*>(xr + c1);

    float s = v0.x + v0.y + v0.z + v0.w + v1.x + v1.y + v1.z + v1.w;
    #pragma unroll
    for (int o = 16; o > 0; o >>= 1) s += __shfl_xor_sync(0xffffffffu, s, o);
    float mean = s * (1.0f / CDIM);

    float d0x = v0.x - mean, d0y = v0.y - mean, d0z = v0.z - mean, d0w = v0.w - mean;
    float d1x = v1.x - mean, d1y = v1.y - mean, d1z = v1.z - mean, d1w = v1.w - mean;
    float s2 = d0x*d0x + d0y*d0y + d0z*d0z + d0w*d0w + d1x*d1x + d1y*d1y + d1z*d1z + d1w*d1w;
    #pragma unroll
    for (int o = 16; o > 0; o >>= 1) s2 += __shfl_xor_sync(0xffffffffu, s2, o);
    float inv = rsqrtf(s2 * (1.0f / CDIM) + 1e-5f);

    float4 g0 = *reinterpret_cast<const float4*>(g + c0);
    float4 g1 = *reinterpret_cast<const float4*>(g + c1);
    float4 b0 = *reinterpret_cast<const float4*>(b + c0);
    float4 b1 = *reinterpret_cast<const float4*>(b + c1);

    float y0x = d0x * inv * g0.x + b0.x, y0y = d0y * inv * g0.y + b0.y;
    float y0z = d0z * inv * g0.z + b0.z, y0w = d0w * inv * g0.w + b0.w;
    float y1x = d1x * inv * g1.x + b1.x, y1y = d1y * inv * g1.y + b1.y;
    float y1z = d1z * inv * g1.z + b1.z, y1w = d1w * inv * g1.w + b1.w;

    if (outn) {
        *reinterpret_cast<float4*>(outn + row * CDIM + c0) = make_float4(y0x, y0y, y0z, y0w);
        *reinterpret_cast<float4*>(outn + row * CDIM + c1) = make_float4(y1x, y1y, y1z, y1w);
    }
    float a0x = y0x, a0y = y0y, a0z = y0z, a0w = y0w;
    float a1x = y1x, a1y = y1y, a1z = y1z, a1w = y1w;
    if (pos) {
        const float* pr = pos + row * CDIM;
        float4 p0 = *reinterpret_cast<const float4*>(pr + c0);
        float4 p1 = *reinterpret_cast<const float4*>(pr + c1);
        a0x += p0.x; a0y += p0.y; a0z += p0.z; a0w += p0.w;
        a1x += p1.x; a1y += p1.y; a1z += p1.z; a1w += p1.w;
    }
    __half2 h0 = __floats2half2_rn(a0x, a0y);
    __half2 h1 = __floats2half2_rn(a0z, a0w);
    __half2 h2 = __floats2half2_rn(a1x, a1y);
    __half2 h3 = __floats2half2_rn(a1z, a1w);
    *reinterpret_cast<__half2*>(outh + row * CDIM + c0)     = h0;
    *reinterpret_cast<__half2*>(outh + row * CDIM + c0 + 2) = h1;
    *reinterpret_cast<__half2*>(outh + row * CDIM + c1)     = h2;
    *reinterpret_cast<__half2*>(outh + row * CDIM + c1 + 2) = h3;
}

// ---------------- fp16 tensor-core GEMM, BM=128 BN=64 BK=32, 4-stage, ldmatrix ----------------
// 256 threads = 8 warps (4m x 2n); warp tile 32x32; 3 CTAs/SM; prefetch depth 3.
#define ACT_NONE 0
#define ACT_GELU 1
#define PH 40    // smem row pitch in halves (80B = 16*5; gcd(5,8)=1 -> ldmatrix phases conflict-free)

#define A_BYTES (128*PH*2)           // 10240
#define B_BYTES (64*PH*2)            // 5120
#define STAGE_BYTES (A_BYTES + B_BYTES)   // 15360
#define SMEM_TOT (4*STAGE_BYTES)          // 61440

__device__ __forceinline__ uint32_t smem_u32(const void* p) {
    uint32_t a;
    asm("{ .reg .u64 t; cvta.to.shared.u64 t, %1; cvt.u32.u64 %0, t; }" : "=r"(a) : "l"(p));
    return a;
}
__device__ __forceinline__ void cp_async16(uint32_t dst, const void* src) {
    asm volatile("cp.async.cg.shared.global [%0], [%1], 16;" :: "r"(dst), "l"(src));
}
__device__ __forceinline__ void cp_commit() {
    asm volatile("cp.async.commit_group;" ::: "memory");
}
template<int N>
__device__ __forceinline__ void cp_wait() {
    asm volatile("cp.async.wait_group %0;" :: "n"(N) : "memory");
}
__device__ __forceinline__ void ldsm_x4(uint32_t& r0, uint32_t& r1, uint32_t& r2, uint32_t& r3,
                                        uint32_t addr) {
    asm volatile("ldmatrix.sync.aligned.m8n8.x4.shared.b16 {%0,%1,%2,%3}, [%4];"
                 : "=r"(r0), "=r"(r1), "=r"(r2), "=r"(r3) : "r"(addr));
}
__device__ __forceinline__ void ldsm_x2(uint32_t& r0, uint32_t& r1, uint32_t addr) {
    asm volatile("ldmatrix.sync.aligned.m8n8.x2.shared.b16 {%0,%1}, [%2];"
                 : "=r"(r0), "=r"(r1) : "r"(addr));
}
__device__ __forceinline__ void mma_f16(float4& d,
                                        uint32_t a0, uint32_t a1, uint32_t a2, uint32_t a3,
                                        uint32_t b0, uint32_t b1) {
    asm volatile(
        "mma.sync.aligned.m16n8k16.row.col.f32.f16.f16.f32 "
        "{%0,%1,%2,%3}, {%4,%5,%6,%7}, {%8,%9}, {%0,%1,%2,%3};\n"
        : "+f"(d.x), "+f"(d.y), "+f"(d.z), "+f"(d.w)
        : "r"(a0), "r"(a1), "r"(a2), "r"(a3), "r"(b0), "r"(b1));
}

__global__ __launch_bounds__(256, 3)
void gemm_f16_kernel(const __half* __restrict__ A, const __half* __restrict__ WT,
                     const float* __restrict__ bias,
                     const float* __restrict__ res1, const float* __restrict__ res2,
                     void* __restrict__ Cout,
                     int M, int N, int K, int act, int out_half)
{
    extern __shared__ char smem[];
    uint32_t smem_base = smem_u32(smem);

    int tid  = threadIdx.x;
    int lane = tid & 31;
    int warp = tid >> 5;
    int g = lane >> 2;      // 0..7
    int t = lane & 3;       // 0..3
    int wm = warp >> 1;     // 0..3  (m groups of 32)
    int wn = warp & 1;      // 0..1  (n groups of 32)
    int m0w = wm * 32;
    int n0w = wn * 32;
    int bm0 = blockIdx.y * 128;
    int bn0 = blockIdx.x * 64;

    // ldmatrix per-lane byte offsets (pitch = PH*2 = 80B)
    uint32_t a_off = (uint32_t)((m0w + (lane & 15)) * (PH * 2) + (lane >> 4) * 16);
    uint32_t b_off = (uint32_t)((n0w + (lane & 7)) * (PH * 2) + ((lane >> 3) & 1) * 16);

    float4 acc[2][4];
    #pragma unroll
    for (int i = 0; i < 2; i++)
        #pragma unroll
        for (int j = 0; j < 4; j++)
            acc[i][j] = make_float4(0.f, 0.f, 0.f, 0.f);

    const int nchunks = K >> 5;     // BK=32

    // ---- stage loader: A 128x32h (2 cp/thread) + B 64x32h (1 cp/thread), one group ----
    auto load_chunk = [&](int c, int s) {
        int k0 = c << 5;
        uint32_t as = smem_base + (uint32_t)(s * STAGE_BYTES);
        uint32_t bs = as + A_BYTES;
        #pragma unroll
        for (int p = 0; p < 2; p++) {
            int idx = p * 256 + tid;
            int row = idx >> 2;          // 4 chunks of 16B per 64B row
            int c8  = (idx & 3) * 8;     // halves
            int grow = bm0 + row; if (grow > M - 1) grow = M - 1;
            cp_async16(as + (uint32_t)(row * PH + c8) * 2u, A + grow * K + k0 + c8);
        }
        {
            int row = tid >> 2;
            int c8  = (tid & 3) * 8;
            int gn  = bn0 + row; if (gn > N - 1) gn = N - 1;
            cp_async16(bs + (uint32_t)(row * PH + c8) * 2u, WT + gn * K + k0 + c8);
        }
        cp_commit();
    };

    // prologue: 3 chunks in flight (4 stages)
    #pragma unroll
    for (int c0 = 0; c0 < 3; c0++)
        if (c0 < nchunks) load_chunk(c0, c0);

    int s = 0;
    for (int c = 0; c < nchunks; c++) {
        cp_wait<2>();          // exactly 3 pending each iteration -> chunk c landed
        __syncthreads();       // also orders prev compute before next overwrite
        if (c + 3 < nchunks) {
            int s3 = s + 3; if (s3 >= 4) s3 -= 4;
            load_chunk(c + 3, s3);
        } else {
            cp_commit();       // empty group keeps pending-count invariant (R9 fix)
        }

        uint32_t as = smem_base + (uint32_t)(s * STAGE_BYTES);
        uint32_t bs = as + A_BYTES;

        #pragma unroll
        for (int ks = 0; ks < 2; ks++) {
            uint32_t kofs = (uint32_t)(ks * 32);   // 16 halves = 32B per k-step
            uint32_t a[2][4];
            #pragma unroll
            for (int im = 0; im < 2; im++)
                ldsm_x4(a[im][0], a[im][1], a[im][2], a[im][3],
                        as + a_off + (uint32_t)(im * 16 * PH * 2) + kofs);
            uint32_t b[4][2];
            #pragma unroll
            for (int in = 0; in < 4; in++)
                ldsm_x2(b[in][0], b[in][1], bs + b_off + (uint32_t)(in * 8 * PH * 2) + kofs);
            #pragma unroll
            for (int in = 0; in < 4; in++) {
                mma_f16(acc[0][in], a[0][0], a[0][1], a[0][2], a[0][3], b[in][0], b[in][1]);
                mma_f16(acc[1][in], a[1][0], a[1][1], a[1][2], a[1][3], b[in][0], b[in][1]);
            }
        }
        if (++s >= 4) s = 0;
    }

    // ---- epilogue ----
    #pragma unroll
    for (int im = 0; im < 2; im++) {
        int r0 = bm0 + m0w + im * 16 + g;
        int r1 = r0 + 8;
        #pragma unroll
        for (int in = 0; in < 4; in++) {
            int c = bn0 + n0w + in * 8 + 2 * t;
            if (c >= N) continue;   // N even -> c+1 < N too
            float bx = bias[c], by = bias[c + 1];

            float v0 = acc[im][in].x + bx;
            float v1 = acc[im][in].y + by;
            float v2 = acc[im][in].z + bx;
            float v3 = acc[im][in].w + by;
            if (act == ACT_GELU) {
                v0 = 0.5f * v0 * (1.0f + erff(v0 * 0.70710678118654752f));
                v1 = 0.5f * v1 * (1.0f + erff(v1 * 0.70710678118654752f));
                v2 = 0.5f * v2 * (1.0f + erff(v2 * 0.70710678118654752f));
                v3 = 0.5f * v3 * (1.0f + erff(v3 * 0.70710678118654752f));
            }
            if (r0 < M) {
                int oi = r0 * N + c;
                if (res1) { v0 += res1[oi]; v1 += res1[oi + 1]; }
                if (res2) { v0 += res2[oi]; v1 += res2[oi + 1]; }
                if (out_half)
                    *reinterpret_cast<__half2*>((__half*)Cout + oi) = __floats2half2_rn(v0, v1);
                else
                    *reinterpret_cast<float2*>((float*)Cout + oi) = make_float2(v0, v1);
            }
            if (r1 < M) {
                int oi = r1 * N + c;
                if (res1) { v2 += res1[oi]; v3 += res1[oi + 1]; }
                if (res2) { v2 += res2[oi]; v3 += res2[oi + 1]; }
                if (out_half)
                    *reinterpret_cast<__half2*>((__half*)Cout + oi) = __floats2half2_rn(v2, v3);
                else
                    *reinterpret_cast<float2*>((float*)Cout + oi) = make_float2(v2, v3);
            }
        }
    }
}

// ---------------- deformable sampling + fused softmax (fp16 values, fp16 out) ----------------
__global__ void sample_kernel(const float* __restrict__ refp)
{
    int row0 = blockIdx.x * 2;
    int t    = threadIdx.x;

    __shared__ float s_off[2][NOFF];
    __shared__ float s_aw [2][NAW];
    __shared__ float s_ref[2][LEV * 2];

    #pragma unroll
    for (int r = 0; r < 2; r++) {
        int row = row0 + r;
        if (t < NOFF)   s_off[r][t] = g_ol[row * NOL + t];
        if (t < NAW)    s_aw [r][t] = g_ol[row * NOL + NOFF + t];
        if (t < LEV*2)  s_ref[r][t] = refp[row * LEV * 2 + t];
    }
    __syncthreads();

    if (t < 16) {
        int r = t >> 3, h = t & 7;
        float* v = &s_aw[r][h * (LEV * PTS)];
        float mx = -1e30f;
        float e[LEV * PTS];
        #pragma unroll
        for (int i = 0; i < LEV * PTS; i++) mx = fmaxf(mx, v[i]);
        float sum = 0.f;
        #pragma unroll
        for (int i = 0; i < LEV * PTS; i++) { e[i] = __expf(v[i] - mx); sum += e[i]; }
        float inv = 1.0f / sum;
        #pragma unroll
        for (int i = 0; i < LEV * PTS; i++) v[i] = e[i] * inv;
    }
    __syncthreads();

    int r = t >> 7;
    int h = (t >> 4) & 7;
    int d = (t & 15) * 2;
    int row = row0 + r;
    int b   = row / NQ;

    const int Hl_[LEV] = {60, 30, 15};
    const int Wl_[LEV] = {80, 40, 20};
    const int St_[LEV] = {0, 4800, 6000};

    float2 acc = make_float2(0.f, 0.f);
    #pragma unroll
    for (int l = 0; l < LEV; l++) {
        int Hl = Hl_[l], Wl = Wl_[l];
        const __half* vbase = g_v + (b * NV + St_[l]) * CDIM + h * DH + d;
        float rx = s_ref[r][l * 2 + 0];
        float ry = s_ref[r][l * 2 + 1];
        #pragma unroll
        for (int p = 0; p < PTS; p++) {
            int oi = ((h * LEV + l) * PTS + p) * 2;
            float gx = rx * (float)Wl + s_off[r][oi + 0] - 0.5f;
            float gy = ry * (float)Hl + s_off[r][oi + 1] - 0.5f;
            float w  = s_aw[r][(h * LEV + l) * PTS + p];

            float x0f = floorf(gx), y0f = floorf(gy);
            int x0 = (int)x0f, y0 = (int)y0f;
            float wx = gx - x0f, wy = gy - y0f;

            float2 sv = make_float2(0.f, 0.f);
            #pragma unroll
            for (int dy = 0; dy < 2; dy++) {
                int yi = y0 + dy;
                if (yi < 0 || yi >= Hl) continue;
                float wyv = dy ? wy : (1.f - wy);
                #pragma unroll
                for (int dx = 0; dx < 2; dx++) {
                    int xi = x0 + dx;
                    if (xi < 0 || xi >= Wl) continue;
                    float wxv = dx ? wx : (1.f - wx);
                    __half2 hv = *reinterpret_cast<const __half2*>(vbase + (yi * Wl + xi) * CDIM);
                    float2 vv = __half22float2(hv);
                    float cw = wyv * wxv;
                    sv.x = fmaf(cw, vv.x, sv.x);
                    sv.y = fmaf(cw, vv.y, sv.y);
                }
            }
            acc.x = fmaf(w, sv.x, acc.x);
            acc.y = fmaf(w, sv.y, acc.y);
        }
    }
    *reinterpret_cast<__half2*>(&g_attn_h[row * CDIM + h * DH + d]) = __floats2half2_rn(acc.x, acc.y);
}

// ---------------- launch ----------------
extern "C" void kernel_launch(void* const* d_in, const int* in_sizes, int n_in,
                              void* d_out, int out_size)
{
    const float* query = (const float*)d_in[0];
    const float* value = (const float*)d_in[1];
    const float* qpos  = (const float*)d_in[2];
    const float* refp  = (const float*)d_in[3];
    const float* g1  = (const float*)d_in[6];
    const float* b1  = (const float*)d_in[7];
    const float* Wo  = (const float*)d_in[8];
    const float* bo  = (const float*)d_in[9];
    const float* Wa  = (const float*)d_in[10];
    const float* ba  = (const float*)d_in[11];
    const float* Wv  = (const float*)d_in[12];
    const float* bv  = (const float*)d_in[13];
    const float* Wp  = (const float*)d_in[14];
    const float* bp  = (const float*)d_in[15];
    const float* g2  = (const float*)d_in[16];
    const float* b2  = (const float*)d_in[17];
    const float* Wf1 = (const float*)d_in[18];
    const float* bf1 = (const float*)d_in[19];
    const float* Wf2 = (const float*)d_in[20];
    const float* bf2 = (const float*)d_in[21];
    float* out = (float*)d_out;

    float *qn, *olbuf, *q, *bcat;
    __half *qa_h, *val_h, *vproj, *attn_h, *q2_h, *h_h;
    __half *wcatT, *wvT, *wpT, *wf1T, *wf2T;
    cudaGetSymbolAddress((void**)&qn,     g_qn);
    cudaGetSymbolAddress((void**)&qa_h,   g_qa_h);
    cudaGetSymbolAddress((void**)&olbuf,  g_ol);
    cudaGetSymbolAddress((void**)&val_h,  g_val_h);
    cudaGetSymbolAddress((void**)&vproj,  g_v);
    cudaGetSymbolAddress((void**)&attn_h, g_attn_h);
    cudaGetSymbolAddress((void**)&q,      g_q);
    cudaGetSymbolAddress((void**)&q2_h,   g_q2_h);
    cudaGetSymbolAddress((void**)&h_h,    g_h_h);
    cudaGetSymbolAddress((void**)&wcatT,  g_wcatT);
    cudaGetSymbolAddress((void**)&wvT,    g_wvT);
    cudaGetSymbolAddress((void**)&wpT,    g_wpT);
    cudaGetSymbolAddress((void**)&wf1T,   g_wf1T);
    cudaGetSymbolAddress((void**)&wf2T,   g_wf2T);
    cudaGetSymbolAddress((void**)&bcat,   g_bcat);

    cudaFuncSetAttribute(gemm_f16_kernel, cudaFuncAttributeMaxDynamicSharedMemorySize, SMEM_TOT);

    // 0) prep
    prep_kernel<<<712, dim3(32, 8)>>>(Wo, Wa, Wv, Wp, Wf1, Wf2, bo, ba);
    f2h_kernel<<<(RV*CDIM/4 + 255)/256, 256>>>(value, val_h, RV*CDIM);

    // 1) LN1 (warp-per-row)
    ln_kernel<<<RQ/8, 256>>>(query, g1, b1, qpos, qn, qa_h);

    // 2) fused offsets+logits [RQ x 288]
    gemm_f16_kernel<<<dim3((NOL + 63)/64, RQ/128), 256, SMEM_TOT>>>(
        qa_h, wcatT, bcat, nullptr, nullptr, olbuf, RQ, NOL, CDIM, ACT_NONE, 0);

    // 3) value projection -> fp16 [RV x 256]
    gemm_f16_kernel<<<dim3(4, (RV + 127)/128), 256, SMEM_TOT>>>(
        val_h, wvT, bv, nullptr, nullptr, vproj, RV, CDIM, CDIM, ACT_NONE, 1);

    // 4) fused softmax + sampling -> attn_h
    sample_kernel<<<RQ/2, 256>>>(refp);

    // 5) output proj + residuals (fp32)
    gemm_f16_kernel<<<dim3(4, RQ/128), 256, SMEM_TOT>>>(
        attn_h, wpT, bp, qn, query, q, RQ, CDIM, CDIM, ACT_NONE, 0);

    // 6) LN2 -> fp16 (warp-per-row)
    ln_kernel<<<RQ/8, 256>>>(q, g2, b2, nullptr, nullptr, q2_h);

    // 7) FFN up + GELU -> fp16 [RQ x 1024]
    gemm_f16_kernel<<<dim3(16, RQ/128), 256, SMEM_TOT>>>(
        q2_h, wf1T, bf1, nullptr, nullptr, h_h, RQ, HID, CDIM, ACT_GELU, 1);

    // 8) FFN down + residual (fp32)
    gemm_f16_kernel<<<dim3(4, RQ/128), 256, SMEM_TOT>>>(
        h_h, wf2T, bf2, q, nullptr, out, RQ, CDIM, HID, ACT_NONE, 0);
}

// round 17
// speedup vs baseline: 4.1222x; 1.0704x over previous
#include <cuda_runtime.h>
#include <cuda_fp16.h>
#include <cstdint>
#include <math.h>

// ---------------- problem constants (fixed shapes) ----------------
#define BATCH 2
#define NQ    8192
#define RQ    (BATCH*NQ)     // 16384 query rows
#define CDIM  256
#define HEADS 8
#define DH    32
#define LEV   3
#define PTS   4
#define NV    6300           // 4800+1200+300
#define RV    (BATCH*NV)     // 12600 value rows
#define HID   1024           // MLP*C
#define NOFF  (HEADS*LEV*PTS*2)  // 192
#define NAW   (HEADS*LEV*PTS)    // 96
#define NOL   (NOFF+NAW)         // 288

// ---------------- scratch (static device memory; no allocs allowed) ----------------
__device__ float  g_qn   [RQ*CDIM];
__device__ __half g_qa_h [RQ*CDIM];
__device__ float  g_ol   [RQ*NOL];
__device__ __half g_val_h[RV*CDIM];
__device__ __half g_v    [RV*CDIM];
__device__ __half g_attn_h[RQ*CDIM];
__device__ float  g_q    [RQ*CDIM];
__device__ __half g_q2_h [RQ*CDIM];
__device__ __half g_h_h  [RQ*HID];
__device__ __half g_wcatT[NOL*CDIM];
__device__ __half g_wvT  [CDIM*CDIM];
__device__ __half g_wpT  [CDIM*CDIM];
__device__ __half g_wf1T [HID*CDIM];
__device__ __half g_wf2T [CDIM*HID];
__device__ float  g_bcat [NOL];

// ---------------- combined prep: 6 weight transposes + bias concat + value f2h, 1 launch ----------------
// blocks 0..711: 32x32 transpose tiles. blocks 712..: value f2h (1024 floats per block).
#define PREP_TBLKS 712
#define F2H_BLKS   ((RV*CDIM + 1023) / 1024)    // 3150
__global__ void prep_kernel(const float* __restrict__ Wo, const float* __restrict__ Wa,
                            const float* __restrict__ Wv, const float* __restrict__ Wp,
                            const float* __restrict__ Wf1, const float* __restrict__ Wf2,
                            const float* __restrict__ bo, const float* __restrict__ ba,
                            const float* __restrict__ value)
{
    int bid = blockIdx.x;
    int tx = threadIdx.x, ty = threadIdx.y;     // 32 x 8
    int tid = ty * 32 + tx;

    if (bid >= PREP_TBLKS) {
        // f2h of value: 4 floats per thread
        int i = ((bid - PREP_TBLKS) * 256 + tid) * 4;
        if (i < RV * CDIM) {
            float4 v = *reinterpret_cast<const float4*>(value + i);
            *reinterpret_cast<__half2*>(g_val_h + i)     = __floats2half2_rn(v.x, v.y);
            *reinterpret_cast<__half2*>(g_val_h + i + 2) = __floats2half2_rn(v.z, v.w);
        }
        return;
    }

    int flat = bid * 256 + tid;
    if (flat < NOL) g_bcat[flat] = (flat < NOFF) ? bo[flat] : ba[flat - NOFF];

    const float* src; __half* dst; int K, N, t0;
    if (bid < 48)       { src = Wo;  dst = g_wcatT;               K = CDIM; N = NOFF; t0 = 0;   }
    else if (bid < 72)  { src = Wa;  dst = g_wcatT + NOFF*CDIM;   K = CDIM; N = NAW;  t0 = 48;  }
    else if (bid < 136) { src = Wv;  dst = g_wvT;                 K = CDIM; N = CDIM; t0 = 72;  }
    else if (bid < 200) { src = Wp;  dst = g_wpT;                 K = CDIM; N = CDIM; t0 = 136; }
    else if (bid < 456) { src = Wf1; dst = g_wf1T;                K = CDIM; N = HID;  t0 = 200; }
    else                { src = Wf2; dst = g_wf2T;                K = HID;  N = CDIM; t0 = 456; }

    int t  = bid - t0;
    int nx = N / 32;
    int n0 = (t % nx) * 32, k0 = (t / nx) * 32;

    __shared__ float tile[32][33];
    #pragma unroll
    for (int i = ty; i < 32; i += 8)
        tile[i][tx] = src[(k0 + i) * N + n0 + tx];
    __syncthreads();
    #pragma unroll
    for (int i = ty; i < 32; i += 8)
        dst[(n0 + i) * K + k0 + tx] = __float2half_rn(tile[tx][i]);
}

// ---------------- LayerNorm: warp-per-row, 8 rows/block, shuffle-only ----------------
__global__ void ln_kernel(const float* __restrict__ x,
                          const float* __restrict__ g, const float* __restrict__ b,
                          const float* __restrict__ pos,
                          float* __restrict__ outn, __half* __restrict__ outh)
{
    int warp = threadIdx.x >> 5;
    int lane = threadIdx.x & 31;
    int row  = blockIdx.x * 8 + warp;

    const float* xr = x + row * CDIM;
    int c0 = lane * 4;            // first float4
    int c1 = 128 + lane * 4;      // second float4
    float4 v0 = *reinterpret_cast<const float4*>(xr + c0);
    float4 v1 = *reinterpret_cast<const float4*>(xr + c1);

    float s = v0.x + v0.y + v0.z + v0.w + v1.x + v1.y + v1.z + v1.w;
    #pragma unroll
    for (int o = 16; o > 0; o >>= 1) s += __shfl_xor_sync(0xffffffffu, s, o);
    float mean = s * (1.0f / CDIM);

    float d0x = v0.x - mean, d0y = v0.y - mean, d0z = v0.z - mean, d0w = v0.w - mean;
    float d1x = v1.x - mean, d1y = v1.y - mean, d1z = v1.z - mean, d1w = v1.w - mean;
    float s2 = d0x*d0x + d0y*d0y + d0z*d0z + d0w*d0w + d1x*d1x + d1y*d1y + d1z*d1z + d1w*d1w;
    #pragma unroll
    for (int o = 16; o > 0; o >>= 1) s2 += __shfl_xor_sync(0xffffffffu, s2, o);
    float inv = rsqrtf(s2 * (1.0f / CDIM) + 1e-5f);

    float4 g0 = *reinterpret_cast<const float4*>(g + c0);
    float4 g1 = *reinterpret_cast<const float4*>(g + c1);
    float4 b0 = *reinterpret_cast<const float4*>(b + c0);
    float4 b1 = *reinterpret_cast<const float4*>(b + c1);

    float y0x = d0x * inv * g0.x + b0.x, y0y = d0y * inv * g0.y + b0.y;
    float y0z = d0z * inv * g0.z + b0.z, y0w = d0w * inv * g0.w + b0.w;
    float y1x = d1x * inv * g1.x + b1.x, y1y = d1y * inv * g1.y + b1.y;
    float y1z = d1z * inv * g1.z + b1.z, y1w = d1w * inv * g1.w + b1.w;

    if (outn) {
        *reinterpret_cast<float4*>(outn + row * CDIM + c0) = make_float4(y0x, y0y, y0z, y0w);
        *reinterpret_cast<float4*>(outn + row * CDIM + c1) = make_float4(y1x, y1y, y1z, y1w);
    }
    float a0x = y0x, a0y = y0y, a0z = y0z, a0w = y0w;
    float a1x = y1x, a1y = y1y, a1z = y1z, a1w = y1w;
    if (pos) {
        const float* pr = pos + row * CDIM;
        float4 p0 = *reinterpret_cast<const float4*>(pr + c0);
        float4 p1 = *reinterpret_cast<const float4*>(pr + c1);
        a0x += p0.x; a0y += p0.y; a0z += p0.z; a0w += p0.w;
        a1x += p1.x; a1y += p1.y; a1z += p1.z; a1w += p1.w;
    }
    *reinterpret_cast<__half2*>(outh + row * CDIM + c0)     = __floats2half2_rn(a0x, a0y);
    *reinterpret_cast<__half2*>(outh + row * CDIM + c0 + 2) = __floats2half2_rn(a0z, a0w);
    *reinterpret_cast<__half2*>(outh + row * CDIM + c1)     = __floats2half2_rn(a1x, a1y);
    *reinterpret_cast<__half2*>(outh + row * CDIM + c1 + 2) = __floats2half2_rn(a1z, a1w);
}

// ---------------- fp16 tensor-core GEMM, BM=128 BN=64 BK=64, 2-stage, ldmatrix (R14 config) ----------------
// 256 threads = 8 warps (4m x 2n); warp tile 32x32; 3 CTAs/SM.
#define ACT_NONE 0
#define ACT_GELU 1
#define PH 72    // smem row pitch in halves (144B); ldmatrix phases conflict-free

#define A_BYTES (128*PH*2)           // 18432
#define B_BYTES (64*PH*2)            // 9216
#define STAGE_BYTES (A_BYTES + B_BYTES)   // 27648
#define SMEM_TOT (2*STAGE_BYTES)          // 55296

__device__ __forceinline__ uint32_t smem_u32(const void* p) {
    uint32_t a;
    asm("{ .reg .u64 t; cvta.to.shared.u64 t, %1; cvt.u32.u64 %0, t; }" : "=r"(a) : "l"(p));
    return a;
}
__device__ __forceinline__ void cp_async16(uint32_t dst, const void* src) {
    asm volatile("cp.async.cg.shared.global [%0], [%1], 16;" :: "r"(dst), "l"(src));
}
__device__ __forceinline__ void cp_commit() {
    asm volatile("cp.async.commit_group;" ::: "memory");
}
template<int N>
__device__ __forceinline__ void cp_wait() {
    asm volatile("cp.async.wait_group %0;" :: "n"(N) : "memory");
}
__device__ __forceinline__ void ldsm_x4(uint32_t& r0, uint32_t& r1, uint32_t& r2, uint32_t& r3,
                                        uint32_t addr) {
    asm volatile("ldmatrix.sync.aligned.m8n8.x4.shared.b16 {%0,%1,%2,%3}, [%4];"
                 : "=r"(r0), "=r"(r1), "=r"(r2), "=r"(r3) : "r"(addr));
}
__device__ __forceinline__ void ldsm_x2(uint32_t& r0, uint32_t& r1, uint32_t addr) {
    asm volatile("ldmatrix.sync.aligned.m8n8.x2.shared.b16 {%0,%1}, [%2];"
                 : "=r"(r0), "=r"(r1) : "r"(addr));
}
__device__ __forceinline__ void mma_f16(float4& d,
                                        uint32_t a0, uint32_t a1, uint32_t a2, uint32_t a3,
                                        uint32_t b0, uint32_t b1) {
    asm volatile(
        "mma.sync.aligned.m16n8k16.row.col.f32.f16.f16.f32 "
        "{%0,%1,%2,%3}, {%4,%5,%6,%7}, {%8,%9}, {%0,%1,%2,%3};\n"
        : "+f"(d.x), "+f"(d.y), "+f"(d.z), "+f"(d.w)
        : "r"(a0), "r"(a1), "r"(a2), "r"(a3), "r"(b0), "r"(b1));
}

__global__ __launch_bounds__(256, 3)
void gemm_f16_kernel(const __half* __restrict__ A, const __half* __restrict__ WT,
                     const float* __restrict__ bias,
                     const float* __restrict__ res1, const float* __restrict__ res2,
                     void* __restrict__ Cout,
                     int M, int N, int K, int act, int out_half)
{
    extern __shared__ char smem[];
    uint32_t smem_base = smem_u32(smem);

    int tid  = threadIdx.x;
    int lane = tid & 31;
    int warp = tid >> 5;
    int g = lane >> 2;      // 0..7
    int t = lane & 3;       // 0..3
    int wm = warp >> 1;     // 0..3  (m groups of 32)
    int wn = warp & 1;      // 0..1  (n groups of 32)
    int m0w = wm * 32;
    int n0w = wn * 32;
    int bm0 = blockIdx.y * 128;
    int bn0 = blockIdx.x * 64;

    // ldmatrix per-lane byte offsets
    uint32_t a_off = (uint32_t)((m0w + (lane & 15)) * (PH * 2) + (lane >> 4) * 16);
    uint32_t b_off = (uint32_t)((n0w + (lane & 7)) * (PH * 2) + ((lane >> 3) & 1) * 16);

    float4 acc[2][4];
    #pragma unroll
    for (int i = 0; i < 2; i++)
        #pragma unroll
        for (int j = 0; j < 4; j++)
            acc[i][j] = make_float4(0.f, 0.f, 0.f, 0.f);

    const int nchunks = K >> 6;     // BK=64

    // ---- stage loader: A 128x64h (4 cp/thread) + B 64x64h (2 cp/thread), one group ----
    auto load_chunk = [&](int c, int s) {
        int k0 = c << 6;
        uint32_t as = smem_base + (uint32_t)(s * STAGE_BYTES);
        uint32_t bs = as + A_BYTES;
        #pragma unroll
        for (int p = 0; p < 4; p++) {
            int idx = p * 256 + tid;
            int row = idx >> 3;
            int c8  = (idx & 7) * 8;
            int grow = bm0 + row; if (grow > M - 1) grow = M - 1;
            cp_async16(as + (uint32_t)(row * PH + c8) * 2u, A + grow * K + k0 + c8);
        }
        #pragma unroll
        for (int p = 0; p < 2; p++) {
            int idx = p * 256 + tid;
            int row = idx >> 3;
            int c8  = (idx & 7) * 8;
            int gn  = bn0 + row; if (gn > N - 1) gn = N - 1;
            cp_async16(bs + (uint32_t)(row * PH + c8) * 2u, WT + gn * K + k0 + c8);
        }
        cp_commit();
    };

    load_chunk(0, 0);

    int s = 0;
    for (int c = 0; c < nchunks; c++) {
        cp_wait<0>();          // drains everything pending -> chunk c definitely landed
        __syncthreads();
        if (c + 1 < nchunks) load_chunk(c + 1, s ^ 1);   // overlaps with compute of c

        uint32_t as = smem_base + (uint32_t)(s * STAGE_BYTES);
        uint32_t bs = as + A_BYTES;

        #pragma unroll
        for (int ks = 0; ks < 4; ks++) {
            uint32_t kofs = (uint32_t)(ks * 32);   // 16 halves per k-step
            uint32_t a[2][4];
            #pragma unroll
            for (int im = 0; im < 2; im++)
                ldsm_x4(a[im][0], a[im][1], a[im][2], a[im][3],
                        as + a_off + (uint32_t)(im * 16 * PH * 2) + kofs);
            uint32_t b[4][2];
            #pragma unroll
            for (int in = 0; in < 4; in++)
                ldsm_x2(b[in][0], b[in][1], bs + b_off + (uint32_t)(in * 8 * PH * 2) + kofs);
            #pragma unroll
            for (int in = 0; in < 4; in++) {
                mma_f16(acc[0][in], a[0][0], a[0][1], a[0][2], a[0][3], b[in][0], b[in][1]);
                mma_f16(acc[1][in], a[1][0], a[1][1], a[1][2], a[1][3], b[in][0], b[in][1]);
            }
        }
        __syncthreads();       // compute done before stage s overwritten next iteration
        s ^= 1;
    }

    // ---- epilogue ----
    #pragma unroll
    for (int im = 0; im < 2; im++) {
        int r0 = bm0 + m0w + im * 16 + g;
        int r1 = r0 + 8;
        #pragma unroll
        for (int in = 0; in < 4; in++) {
            int c = bn0 + n0w + in * 8 + 2 * t;
            if (c >= N) continue;   // N even -> c+1 < N too
            float bx = bias[c], by = bias[c + 1];

            float v0 = acc[im][in].x + bx;
            float v1 = acc[im][in].y + by;
            float v2 = acc[im][in].z + bx;
            float v3 = acc[im][in].w + by;
            if (act == ACT_GELU) {
                v0 = 0.5f * v0 * (1.0f + erff(v0 * 0.70710678118654752f));
                v1 = 0.5f * v1 * (1.0f + erff(v1 * 0.70710678118654752f));
                v2 = 0.5f * v2 * (1.0f + erff(v2 * 0.70710678118654752f));
                v3 = 0.5f * v3 * (1.0f + erff(v3 * 0.70710678118654752f));
            }
            if (r0 < M) {
                int oi = r0 * N + c;
                if (res1) { v0 += res1[oi]; v1 += res1[oi + 1]; }
                if (res2) { v0 += res2[oi]; v1 += res2[oi + 1]; }
                if (out_half)
                    *reinterpret_cast<__half2*>((__half*)Cout + oi) = __floats2half2_rn(v0, v1);
                else
                    *reinterpret_cast<float2*>((float*)Cout + oi) = make_float2(v0, v1);
            }
            if (r1 < M) {
                int oi = r1 * N + c;
                if (res1) { v2 += res1[oi]; v3 += res1[oi + 1]; }
                if (res2) { v2 += res2[oi]; v3 += res2[oi + 1]; }
                if (out_half)
                    *reinterpret_cast<__half2*>((__half*)Cout + oi) = __floats2half2_rn(v2, v3);
                else
                    *reinterpret_cast<float2*>((float*)Cout + oi) = make_float2(v2, v3);
            }
        }
    }
}

// ---------------- deformable sampling + fused softmax (fp16 values, fp16 out) ----------------
__global__ void sample_kernel(const float* __restrict__ refp)
{
    int row0 = blockIdx.x * 2;
    int t    = threadIdx.x;

    __shared__ float s_off[2][NOFF];
    __shared__ float s_aw [2][NAW];
    __shared__ float s_ref[2][LEV * 2];

    #pragma unroll
    for (int r = 0; r < 2; r++) {
        int row = row0 + r;
        if (t < NOFF)   s_off[r][t] = g_ol[row * NOL + t];
        if (t < NAW)    s_aw [r][t] = g_ol[row * NOL + NOFF + t];
        if (t < LEV*2)  s_ref[r][t] = refp[row * LEV * 2 + t];
    }
    __syncthreads();

    if (t < 16) {
        int r = t >> 3, h = t & 7;
        float* v = &s_aw[r][h * (LEV * PTS)];
        float mx = -1e30f;
        float e[LEV * PTS];
        #pragma unroll
        for (int i = 0; i < LEV * PTS; i++) mx = fmaxf(mx, v[i]);
        float sum = 0.f;
        #pragma unroll
        for (int i = 0; i < LEV * PTS; i++) { e[i] = __expf(v[i] - mx); sum += e[i]; }
        float inv = 1.0f / sum;
        #pragma unroll
        for (int i = 0; i < LEV * PTS; i++) v[i] = e[i] * inv;
    }
    __syncthreads();

    int r = t >> 7;
    int h = (t >> 4) & 7;
    int d = (t & 15) * 2;
    int row = row0 + r;
    int b   = row / NQ;

    const int Hl_[LEV] = {60, 30, 15};
    const int Wl_[LEV] = {80, 40, 20};
    const int St_[LEV] = {0, 4800, 6000};

    float2 acc = make_float2(0.f, 0.f);
    #pragma unroll
    for (int l = 0; l < LEV; l++) {
        int Hl = Hl_[l], Wl = Wl_[l];
        const __half* vbase = g_v + (b * NV + St_[l]) * CDIM + h * DH + d;
        float rx = s_ref[r][l * 2 + 0];
        float ry = s_ref[r][l * 2 + 1];
        #pragma unroll
        for (int p = 0; p < PTS; p++) {
            int oi = ((h * LEV + l) * PTS + p) * 2;
            float gx = rx * (float)Wl + s_off[r][oi + 0] - 0.5f;
            float gy = ry * (float)Hl + s_off[r][oi + 1] - 0.5f;
            float w  = s_aw[r][(h * LEV + l) * PTS + p];

            float x0f = floorf(gx), y0f = floorf(gy);
            int x0 = (int)x0f, y0 = (int)y0f;
            float wx = gx - x0f, wy = gy - y0f;

            float2 sv = make_float2(0.f, 0.f);
            #pragma unroll
            for (int dy = 0; dy < 2; dy++) {
                int yi = y0 + dy;
                if (yi < 0 || yi >= Hl) continue;
                float wyv = dy ? wy : (1.f - wy);
                #pragma unroll
                for (int dx = 0; dx < 2; dx++) {
                    int xi = x0 + dx;
                    if (xi < 0 || xi >= Wl) continue;
                    float wxv = dx ? wx : (1.f - wx);
                    __half2 hv = *reinterpret_cast<const __half2*>(vbase + (yi * Wl + xi) * CDIM);
                    float2 vv = __half22float2(hv);
                    float cw = wyv * wxv;
                    sv.x = fmaf(cw, vv.x, sv.x);
                    sv.y = fmaf(cw, vv.y, sv.y);
                }
            }
            acc.x = fmaf(w, sv.x, acc.x);
            acc.y = fmaf(w, sv.y, acc.y);
        }
    }
    *reinterpret_cast<__half2*>(&g_attn_h[row * CDIM + h * DH + d]) = __floats2half2_rn(acc.x, acc.y);
}

// ---------------- launch ----------------
extern "C" void kernel_launch(void* const* d_in, const int* in_sizes, int n_in,
                              void* d_out, int out_size)
{
    const float* query = (const float*)d_in[0];
    const float* value = (const float*)d_in[1];
    const float* qpos  = (const float*)d_in[2];
    const float* refp  = (const float*)d_in[3];
    const float* g1  = (const float*)d_in[6];
    const float* b1  = (const float*)d_in[7];
    const float* Wo  = (const float*)d_in[8];
    const float* bo  = (const float*)d_in[9];
    const float* Wa  = (const float*)d_in[10];
    const float* ba  = (const float*)d_in[11];
    const float* Wv  = (const float*)d_in[12];
    const float* bv  = (const float*)d_in[13];
    const float* Wp  = (const float*)d_in[14];
    const float* bp  = (const float*)d_in[15];
    const float* g2  = (const float*)d_in[16];
    const float* b2  = (const float*)d_in[17];
    const float* Wf1 = (const float*)d_in[18];
    const float* bf1 = (const float*)d_in[19];
    const float* Wf2 = (const float*)d_in[20];
    const float* bf2 = (const float*)d_in[21];
    float* out = (float*)d_out;

    float *qn, *olbuf, *q, *bcat;
    __half *qa_h, *vproj, *attn_h, *q2_h, *h_h;
    __half *wcatT, *wvT, *wpT, *wf1T, *wf2T, *val_h;
    cudaGetSymbolAddress((void**)&qn,     g_qn);
    cudaGetSymbolAddress((void**)&qa_h,   g_qa_h);
    cudaGetSymbolAddress((void**)&olbuf,  g_ol);
    cudaGetSymbolAddress((void**)&val_h,  g_val_h);
    cudaGetSymbolAddress((void**)&vproj,  g_v);
    cudaGetSymbolAddress((void**)&attn_h, g_attn_h);
    cudaGetSymbolAddress((void**)&q,      g_q);
    cudaGetSymbolAddress((void**)&q2_h,   g_q2_h);
    cudaGetSymbolAddress((void**)&h_h,    g_h_h);
    cudaGetSymbolAddress((void**)&wcatT,  g_wcatT);
    cudaGetSymbolAddress((void**)&wvT,    g_wvT);
    cudaGetSymbolAddress((void**)&wpT,    g_wpT);
    cudaGetSymbolAddress((void**)&wf1T,   g_wf1T);
    cudaGetSymbolAddress((void**)&wf2T,   g_wf2T);
    cudaGetSymbolAddress((void**)&bcat,   g_bcat);

    cudaFuncSetAttribute(gemm_f16_kernel, cudaFuncAttributeMaxDynamicSharedMemorySize, SMEM_TOT);

    // 0) prep: weight transposes + bias concat + value f2h in ONE launch
    prep_kernel<<<PREP_TBLKS + F2H_BLKS, dim3(32, 8)>>>(Wo, Wa, Wv, Wp, Wf1, Wf2, bo, ba, value);

    // 1) LN1 (warp-per-row)
    ln_kernel<<<RQ/8, 256>>>(query, g1, b1, qpos, qn, qa_h);

    // 2) fused offsets+logits [RQ x 288]
    gemm_f16_kernel<<<dim3((NOL + 63)/64, RQ/128), 256, SMEM_TOT>>>(
        qa_h, wcatT, bcat, nullptr, nullptr, olbuf, RQ, NOL, CDIM, ACT_NONE, 0);

    // 3) value projection -> fp16 [RV x 256]
    gemm_f16_kernel<<<dim3(4, (RV + 127)/128), 256, SMEM_TOT>>>(
        val_h, wvT, bv, nullptr, nullptr, vproj, RV, CDIM, CDIM, ACT_NONE, 1);

    // 4) fused softmax + sampling -> attn_h
    sample_kernel<<<RQ/2, 256>>>(refp);

    // 5) output proj + residuals (fp32)
    gemm_f16_kernel<<<dim3(4, RQ/128), 256, SMEM_TOT>>>(
        attn_h, wpT, bp, qn, query, q, RQ, CDIM, CDIM, ACT_NONE, 0);

    // 6) LN2 -> fp16 (warp-per-row)
    ln_kernel<<<RQ/8, 256>>>(q, g2, b2, nullptr, nullptr, q2_h);

    // 7) FFN up + GELU -> fp16 [RQ x 1024]
    gemm_f16_kernel<<<dim3(16, RQ/128), 256, SMEM_TOT>>>(
        q2_h, wf1T, bf1, nullptr, nullptr, h_h, RQ, HID, CDIM, ACT_GELU, 1);

    // 8) FFN down + residual (fp32)
    gemm_f16_kernel<<<dim3(4, RQ/128), 256, SMEM_TOT>>>(
        h_h, wf2T, bf2, q, nullptr, out, RQ, CDIM, HID, ACT_NONE, 0);
}